// round 11
// baseline (speedup 1.0000x reference)
#include <cuda_runtime.h>
#include <cuda_bf16.h>
#include <cuda_fp8.h>
#include <cstdint>
#include <math.h>

// ---------------------------------------------------------------------------
// Problem constants
// ---------------------------------------------------------------------------
static constexpr int S_ = 2048, B_ = 8, D_ = 1024, M_ = S_ * B_;
static constexpr float SCALE_ = 0.03125f;      // 1/sqrt(1024)
static constexpr float UPS_   = 128.0f;        // 2^7 operand scale
static constexpr float DNS_   = 0.0078125f;    // 2^-7

// ---------------------------------------------------------------------------
// Static scratch. Split layout per row of K elements (4 bytes/elem):
//   bytes [0, 2K)   : hi bf16   (A-role: unscaled; B-role: x 2^7)
//   bytes [2K, 3K)  : hi8 e4m3  (unscaled, both roles)
//   bytes [3K, 4K)  : lo8 e4m3  (lo x 2^7, both roles)
// ---------------------------------------------------------------------------
__device__ __nv_bfloat16 g_Qc [(size_t)M_ * 2 * D_];   // A-role
__device__ __nv_bfloat16 g_Kc [(size_t)M_ * 2 * D_];   // B-role
__device__ __nv_bfloat16 g_Vc [(size_t)M_ * 2 * D_];   // A-role
__device__ __nv_bfloat16 g_WkT[(size_t)D_ * 2 * D_];   // A-role
__device__ __nv_bfloat16 g_WqT[(size_t)D_ * 2 * D_];   // B-role
__device__ __nv_bfloat16 g_WvT[(size_t)D_ * 2 * D_];   // B-role
__device__ __nv_bfloat16 g_Wos[(size_t)D_ * 2 * D_];   // A-role
__device__ __nv_bfloat16 g_H  [(size_t)D_ * 2 * D_];   // B-role (GEMM out)
__device__ __nv_bfloat16 g_WvoB[(size_t)D_ * 2 * D_];  // B-role (GEMM out)
__device__ __nv_bfloat16 g_T  [(size_t)M_ * 2 * D_];   // A-role (GEMM out)
__device__ float         g_Zf [(size_t)M_ * D_];
__device__ __nv_bfloat16 g_Zt [(size_t)B_ * D_ * 2 * S_]; // B-role
__device__ float         g_P  [(size_t)B_ * S_ * S_];
__device__ __nv_bfloat16 g_Pbf[(size_t)B_ * S_ * 2 * S_]; // A-role
__device__ float         g_w2 [D_];
__device__ float         g_cb [D_];
__device__ float         g_vb [(size_t)B_ * S_];       // pre-scaled by SCALE_

// ---------------------------------------------------------------------------
// Portable PTX helpers
// ---------------------------------------------------------------------------
__device__ __forceinline__ uint32_t smem_u32(const void* p) {
    uint32_t a;
    asm("{ .reg .u64 t; cvta.to.shared.u64 t, %1; cvt.u32.u64 %0, t; }" : "=r"(a) : "l"(p));
    return a;
}

__device__ __forceinline__ void ldsm4(uint32_t* r, uint32_t a) {
    asm volatile("ldmatrix.sync.aligned.m8n8.x4.shared.b16 {%0,%1,%2,%3}, [%4];"
                 : "=r"(r[0]), "=r"(r[1]), "=r"(r[2]), "=r"(r[3]) : "r"(a));
}

__device__ __forceinline__ void mma16816(float* d, const uint32_t* a, const uint32_t* b) {
    asm volatile(
        "mma.sync.aligned.m16n8k16.row.col.f32.bf16.bf16.f32 "
        "{%0,%1,%2,%3}, {%4,%5,%6,%7}, {%8,%9}, {%0,%1,%2,%3};"
        : "+f"(d[0]), "+f"(d[1]), "+f"(d[2]), "+f"(d[3])
        : "r"(a[0]), "r"(a[1]), "r"(a[2]), "r"(a[3]), "r"(b[0]), "r"(b[1]));
}

__device__ __forceinline__ void mma16832q(float* d, const uint32_t* a, const uint32_t* b) {
    asm volatile(
        "mma.sync.aligned.m16n8k32.row.col.f32.e4m3.e4m3.f32 "
        "{%0,%1,%2,%3}, {%4,%5,%6,%7}, {%8,%9}, {%0,%1,%2,%3};"
        : "+f"(d[0]), "+f"(d[1]), "+f"(d[2]), "+f"(d[3])
        : "r"(a[0]), "r"(a[1]), "r"(a[2]), "r"(a[3]), "r"(b[0]), "r"(b[1]));
}

__device__ __forceinline__ void cp16(uint32_t saddr, const void* gaddr) {
    asm volatile("cp.async.cg.shared.global [%0], [%1], 16;" :: "r"(saddr), "l"(gaddr));
}
__device__ __forceinline__ void cp_commit() {
    asm volatile("cp.async.commit_group;" ::: "memory");
}
template<int N>
__device__ __forceinline__ void cp_wait() {
    asm volatile("cp.async.wait_group %0;" :: "n"(N) : "memory");
}

__device__ __forceinline__ float neg_inf_f() { return __int_as_float(0xff800000); }

__device__ __forceinline__ uint32_t pack_bf2(float a, float b) {
    __nv_bfloat162 h = __floats2bfloat162_rn(a, b);
    return *reinterpret_cast<uint32_t*>(&h);
}

__device__ __forceinline__ uint32_t e4m3(float x) {
    return (uint32_t)__nv_cvt_float_to_fp8(x, __NV_SATFINITE, __NV_E4M3);
}
__device__ __forceinline__ uint32_t e4m3x4(float a, float b, float c, float d) {
    return e4m3(a) | (e4m3(b) << 8) | (e4m3(c) << 16) | (e4m3(d) << 24);
}

// swizzles
__device__ __forceinline__ uint32_t swz(int row, int cc) {     // 128B rows
    return (uint32_t)(row << 7) + (uint32_t)((cc ^ (row & 7)) << 4);
}
__device__ __forceinline__ uint32_t so8(int row, int b) {      // fp8 64B rows packed 2/line
    return (uint32_t)((row >> 1) << 7) + (uint32_t)((row & 1) << 6)
         + (uint32_t)(((b ^ ((row >> 1) & 3))) << 4);
}

// ---------------------------------------------------------------------------
// Split GEMM: acc = 2^7*(Ahi*Bhi) via bf16 + 2^7*(Alo*Bhi + Ahi*Blo) via fp8.
// CTA tile 256x128, warp tile 64x64 (8 warps), k-chunk 64, 2-stage cp.async.
// EPI: 0 = fp32 (+bias), 1 = A-role split out, 2 = B-role split out,
//      4 = scores: v = acc*scale + cbias[bz*S+n] (mask), fp32
// ---------------------------------------------------------------------------
struct GArgs {
    const char* A; const char* B;
    long ldaB, ldbB, bsAB, bsBB;   // byte strides (row, batch)
    long aH8, aL8, bH8, bL8;       // in-row byte offsets of fp8 sections
    int  Kpart;
    float scale;                   // final multiplier (includes 2^-7)
    const float* bias;
    const float* cbias;
    float* outF; long ldo, bsO;    // element strides (EPI 0/4)
    char* outH;  long ldoB, bsOB;  // byte strides (EPI 1/2)
    long oH8, oL8;                 // out-row fp8 byte offsets (EPI 1/2)
};

static constexpr int STAGE = 98304;                 // 96 KB
static constexpr int GEMM_SMEM = 1024 + 2 * STAGE;  // 197632 B
// stage-internal offsets
static constexpr int O_AHI = 0,      O_AH8 = 32768, O_AL8 = 49152;
static constexpr int O_BHI = 65536,  O_BH8 = 81920, O_BL8 = 90112;

template<int EPI, bool CAUSALK, bool TRIL>
__device__ __forceinline__ void gemm_body(const GArgs& g, int nt, int mt, int bz)
{
    if (TRIL && nt * 128 > mt * 256 + 255) return;
    const int mBase = mt * 256, nBase = nt * 128;

    extern __shared__ char smem_raw[];
    const uint32_t sbase = smem_u32(smem_raw);
    const uint32_t abase = (sbase + 1023) & ~1023u;

    const int tid  = threadIdx.x;
    const int lane = tid & 31;
    const int warp = tid >> 5;
    const int wm   = warp >> 1;
    const int wn   = warp & 1;

    const char* Ab = g.A + (long)bz * g.bsAB;
    const char* Bb = g.B + (long)bz * g.bsBB;

    const int kEff = CAUSALK ? (mBase + 256) : g.Kpart;
    const int nch  = kEff >> 6;

    auto issue_chunk = [&](int c) {
        const long kc = (long)(c << 6);   // element offset of chunk
        const uint32_t base = abase + (c & 1) * STAGE;
#pragma unroll
        for (int i = 0; i < 8; i++) {     // A hi bf16: 256 rows x 128B
            const int id = tid + i * 256;
            const int row = id >> 3, cc = id & 7;
            cp16(base + O_AHI + swz(row, cc),
                 Ab + (long)(mBase + row) * g.ldaB + 2 * kc + cc * 16);
        }
#pragma unroll
        for (int i = 0; i < 4; i++) {     // A hi8 + lo8: 256 rows x 64B each
            const int id = tid + i * 256;
            const int row = id >> 2, b = id & 3;
            const uint32_t so = so8(row, b);
            const char* src = Ab + (long)(mBase + row) * g.ldaB + kc + b * 16;
            cp16(base + O_AH8 + so, src + g.aH8);
            cp16(base + O_AL8 + so, src + g.aL8);
        }
#pragma unroll
        for (int i = 0; i < 4; i++) {     // B hi bf16: 128 rows x 128B
            const int id = tid + i * 256;
            const int row = id >> 3, cc = id & 7;
            cp16(base + O_BHI + swz(row, cc),
                 Bb + (long)(nBase + row) * g.ldbB + 2 * kc + cc * 16);
        }
#pragma unroll
        for (int i = 0; i < 2; i++) {     // B hi8 + lo8: 128 rows x 64B each
            const int id = tid + i * 256;
            const int row = id >> 2, b = id & 3;
            const uint32_t so = so8(row, b);
            const char* src = Bb + (long)(nBase + row) * g.ldbB + kc + b * 16;
            cp16(base + O_BH8 + so, src + g.bH8);
            cp16(base + O_BL8 + so, src + g.bL8);
        }
        cp_commit();
    };

    float acc[4][8][4];
#pragma unroll
    for (int i = 0; i < 4; i++)
#pragma unroll
        for (int j = 0; j < 8; j++)
#pragma unroll
            for (int d = 0; d < 4; d++) acc[i][j][d] = 0.0f;

    issue_chunk(0);

    const int arow = (lane & 7) + ((lane >> 3) & 1) * 8;
    const int acol = lane >> 4;
    const int brow = (lane & 7) + ((lane >> 4) & 1) * 8;
    const int bcol = (lane >> 3) & 1;

    for (int c = 0; c < nch; c++) {
        if (c + 1 < nch) issue_chunk(c + 1);
        if (c + 1 < nch) cp_wait<1>(); else cp_wait<0>();
        __syncthreads();

        const uint32_t base = abase + (c & 1) * STAGE;
        const uint32_t sAhi = base + O_AHI, sAh8 = base + O_AH8, sAl8 = base + O_AL8;
        const uint32_t sBhi = base + O_BHI, sBh8 = base + O_BH8, sBl8 = base + O_BL8;

        // ---- bf16 hi*hi : 4 x k16 ----
#pragma unroll
        for (int ks = 0; ks < 4; ks++) {
            uint32_t af[4][4], bf[4][4];
#pragma unroll
            for (int mi = 0; mi < 4; mi++) {
                const int row = wm * 64 + mi * 16 + arow;
                ldsm4(af[mi], sAhi + swz(row, ks * 2 + acol));
            }
#pragma unroll
            for (int nj = 0; nj < 4; nj++) {
                const int row = wn * 64 + nj * 16 + brow;
                ldsm4(bf[nj], sBhi + swz(row, ks * 2 + bcol));
            }
#pragma unroll
            for (int mi = 0; mi < 4; mi++)
#pragma unroll
                for (int nj = 0; nj < 4; nj++) {
                    mma16816(acc[mi][2 * nj],     af[mi], &bf[nj][0]);
                    mma16816(acc[mi][2 * nj + 1], af[mi], &bf[nj][2]);
                }
        }

        // ---- fp8 cross terms : 2 x k32, two passes each ----
#pragma unroll
        for (int k2 = 0; k2 < 2; k2++) {
            uint32_t a8[4][4], b8[4][4];
            // pass A: Alo8 * Bhi8
#pragma unroll
            for (int mi = 0; mi < 4; mi++) {
                const int row = wm * 64 + mi * 16 + arow;
                ldsm4(a8[mi], sAl8 + so8(row, k2 * 2 + acol));
            }
#pragma unroll
            for (int nj = 0; nj < 4; nj++) {
                const int row = wn * 64 + nj * 16 + brow;
                ldsm4(b8[nj], sBh8 + so8(row, k2 * 2 + bcol));
            }
#pragma unroll
            for (int mi = 0; mi < 4; mi++)
#pragma unroll
                for (int nj = 0; nj < 4; nj++) {
                    mma16832q(acc[mi][2 * nj],     a8[mi], &b8[nj][0]);
                    mma16832q(acc[mi][2 * nj + 1], a8[mi], &b8[nj][2]);
                }
            // pass B: Ahi8 * Blo8
#pragma unroll
            for (int mi = 0; mi < 4; mi++) {
                const int row = wm * 64 + mi * 16 + arow;
                ldsm4(a8[mi], sAh8 + so8(row, k2 * 2 + acol));
            }
#pragma unroll
            for (int nj = 0; nj < 4; nj++) {
                const int row = wn * 64 + nj * 16 + brow;
                ldsm4(b8[nj], sBl8 + so8(row, k2 * 2 + bcol));
            }
#pragma unroll
            for (int mi = 0; mi < 4; mi++)
#pragma unroll
                for (int nj = 0; nj < 4; nj++) {
                    mma16832q(acc[mi][2 * nj],     a8[mi], &b8[nj][0]);
                    mma16832q(acc[mi][2 * nj + 1], a8[mi], &b8[nj][2]);
                }
        }
        __syncthreads();   // bound warp skew: prefetch of c+2 can't race readers of c
    }

    // ------------------------- epilogue -------------------------
    const int gq = lane >> 2, tg = lane & 3;
#pragma unroll
    for (int mi = 0; mi < 4; mi++) {
#pragma unroll
        for (int half = 0; half < 2; half++) {
            const int gm = mBase + wm * 64 + mi * 16 + gq + half * 8;
#pragma unroll
            for (int ni = 0; ni < 8; ni++) {
                const int gn = nBase + wn * 64 + ni * 8 + 2 * tg;
                const float r0 = acc[mi][ni][half * 2 + 0];
                const float r1 = acc[mi][ni][half * 2 + 1];

                if (EPI == 0) {
                    float2 v;
                    v.x = r0 * g.scale; v.y = r1 * g.scale;
                    if (g.bias) { v.x += g.bias[gn + 0]; v.y += g.bias[gn + 1]; }
                    *reinterpret_cast<float2*>(
                        g.outF + (long)bz * g.bsO + (long)gm * g.ldo + gn) = v;
                } else if (EPI == 1 || EPI == 2) {
                    const float v0 = r0 * g.scale, v1 = r1 * g.scale;
                    const __nv_bfloat16 h0 = __float2bfloat16(v0);
                    const __nv_bfloat16 h1 = __float2bfloat16(v1);
                    const float f0 = __bfloat162float(h0), f1 = __bfloat162float(h1);
                    const float l0 = v0 - f0, l1 = v1 - f1;
                    char* rowp = g.outH + (long)bz * g.bsOB + (long)gm * g.ldoB;
                    const float hm = (EPI == 2) ? UPS_ : 1.0f;
                    *reinterpret_cast<uint32_t*>(rowp + 2 * gn) = pack_bf2(f0 * hm, f1 * hm);
                    *reinterpret_cast<uint16_t*>(rowp + g.oH8 + gn) =
                        (uint16_t)(e4m3(f0) | (e4m3(f1) << 8));
                    *reinterpret_cast<uint16_t*>(rowp + g.oL8 + gn) =
                        (uint16_t)(e4m3(l0 * UPS_) | (e4m3(l1 * UPS_) << 8));
                } else {  // EPI == 4 : scores
                    const float cb0 = g.cbias[(long)bz * S_ + gn + 0];
                    const float cb1 = g.cbias[(long)bz * S_ + gn + 1];
                    float2 v;
                    v.x = (gn + 0 > gm) ? neg_inf_f() : r0 * g.scale + cb0;
                    v.y = (gn + 1 > gm) ? neg_inf_f() : r1 * g.scale + cb1;
                    *reinterpret_cast<float2*>(
                        g.outF + (long)bz * g.bsO + (long)gm * g.ldo + gn) = v;
                }
            }
        }
    }
}

template<int EPI, bool CAUSALK, bool TRIL>
__global__ void __launch_bounds__(256, 1) gemm_one(GArgs g)
{
    gemm_body<EPI, CAUSALK, TRIL>(g, blockIdx.x, gridDim.y - 1 - blockIdx.y, blockIdx.z);
}

template<int E0, int E1>
__global__ void __launch_bounds__(256, 1) gemm_dual(GArgs g0, GArgs g1)
{
    if (blockIdx.z == 0)
        gemm_body<E0, false, false>(g0, blockIdx.x, blockIdx.y, 0);
    else
        gemm_body<E1, false, false>(g1, blockIdx.x, blockIdx.y, 0);
}

// ---------------------------------------------------------------------------
// Merged q/k/v conversion. z: 0=Qc(A), 1=Kc(B), 2=Vc(A). K=1024 rows (4096B).
// ---------------------------------------------------------------------------
__global__ void conv_split_in(const float* __restrict__ q, const float* __restrict__ k,
                              const float* __restrict__ v,
                              char* __restrict__ Qc, char* __restrict__ Kc,
                              char* __restrict__ Vc)
{
    const float* in = (blockIdx.z == 0) ? q : (blockIdx.z == 1) ? k : v;
    char* out = (blockIdx.z == 0) ? Qc : (blockIdx.z == 1) ? Kc : Vc;
    const float hm = (blockIdx.z == 1) ? UPS_ : 1.0f;
    const long base = (long)blockIdx.x * 1024 + threadIdx.x;

    float4 v4[4];
#pragma unroll
    for (int j = 0; j < 4; j++)
        v4[j] = reinterpret_cast<const float4*>(in)[base + j * 256];

#pragma unroll
    for (int j = 0; j < 4; j++) {
        const long idx = (base + j * 256) * 4;
        const long m = idx >> 10;
        const int  kk = (int)(idx & 1023);
        const float x0 = v4[j].x, x1 = v4[j].y, x2 = v4[j].z, x3 = v4[j].w;
        const float f0 = __bfloat162float(__float2bfloat16(x0));
        const float f1 = __bfloat162float(__float2bfloat16(x1));
        const float f2 = __bfloat162float(__float2bfloat16(x2));
        const float f3 = __bfloat162float(__float2bfloat16(x3));
        char* rowp = out + m * 4096;
        uint2 hp;
        hp.x = pack_bf2(f0 * hm, f1 * hm);
        hp.y = pack_bf2(f2 * hm, f3 * hm);
        *reinterpret_cast<uint2*>(rowp + 2 * kk) = hp;
        *reinterpret_cast<uint32_t*>(rowp + 2048 + kk) = e4m3x4(f0, f1, f2, f3);
        *reinterpret_cast<uint32_t*>(rowp + 3072 + kk) =
            e4m3x4((x0 - f0) * UPS_, (x1 - f1) * UPS_, (x2 - f2) * UPS_, (x3 - f3) * UPS_);
    }
}

// ---------------------------------------------------------------------------
// Wos conversion (A-role, row-major, K=1024)
// ---------------------------------------------------------------------------
__global__ void conv_split_k1024(const float* __restrict__ in, char* __restrict__ out,
                                 long n4)
{
    const long i = (long)blockIdx.x * 256 + threadIdx.x;
    if (i >= n4) return;
    const float4 x = reinterpret_cast<const float4*>(in)[i];
    const long idx = i * 4;
    const long m = idx >> 10;
    const int  kk = (int)(idx & 1023);
    const float f0 = __bfloat162float(__float2bfloat16(x.x));
    const float f1 = __bfloat162float(__float2bfloat16(x.y));
    const float f2 = __bfloat162float(__float2bfloat16(x.z));
    const float f3 = __bfloat162float(__float2bfloat16(x.w));
    char* rowp = out + m * 4096;
    uint2 hp; hp.x = pack_bf2(f0, f1); hp.y = pack_bf2(f2, f3);
    *reinterpret_cast<uint2*>(rowp + 2 * kk) = hp;
    *reinterpret_cast<uint32_t*>(rowp + 2048 + kk) = e4m3x4(f0, f1, f2, f3);
    *reinterpret_cast<uint32_t*>(rowp + 3072 + kk) =
        e4m3x4((x.x - f0) * UPS_, (x.y - f1) * UPS_, (x.z - f2) * UPS_, (x.w - f3) * UPS_);
}

// ---------------------------------------------------------------------------
// Weight transpose + split: out row a gets W[.,a]. hiMul = 1 (A-role) or 128 (B)
// ---------------------------------------------------------------------------
__global__ void transpose_split_w(const float* __restrict__ W, char* __restrict__ out,
                                  float hiMul)
{
    __shared__ float t[32][33];
    const int a0 = blockIdx.x * 32, e0 = blockIdx.y * 32;
    const int tx = threadIdx.x, ty = threadIdx.y;
#pragma unroll
    for (int r = 0; r < 32; r += 8)
        t[r + ty][tx] = W[(long)(e0 + r + ty) * D_ + a0 + tx];
    __syncthreads();
#pragma unroll
    for (int r = 0; r < 32; r += 8) {
        const int a = a0 + r + ty, e = e0 + tx;
        const float v = t[tx][r + ty];
        const float f = __bfloat162float(__float2bfloat16(v));
        char* rowp = out + (long)a * 4096;
        *reinterpret_cast<__nv_bfloat16*>(rowp + 2 * e) = __float2bfloat16(f * hiMul);
        *reinterpret_cast<uint8_t*>(rowp + 2048 + e) = (uint8_t)e4m3(f);
        *reinterpret_cast<uint8_t*>(rowp + 3072 + e) = (uint8_t)e4m3((v - f) * UPS_);
    }
}

// ---------------------------------------------------------------------------
// Z fp32 [s*B+b][d] -> Zt (B-role) rows [b][d] of K=S (8192B rows)
// ---------------------------------------------------------------------------
__global__ void transpose_split_v(const float* __restrict__ Vf, char* __restrict__ Vt)
{
    __shared__ float t[64][33];
    const int d0 = blockIdx.x * 32, s0 = blockIdx.y * 64, b = blockIdx.z;
    const int tx = threadIdx.x, ty = threadIdx.y;
#pragma unroll
    for (int j = 0; j < 8; j++) {
        const int sl = j * 8 + ty;
        t[sl][tx] = Vf[((size_t)(s0 + sl) * B_ + b) * D_ + d0 + tx];
    }
    __syncthreads();
#pragma unroll
    for (int jj = 0; jj < 4; jj++) {
        const int dl = jj * 8 + ty;
        const int s = s0 + 2 * tx;
        const float va = t[2 * tx][dl], vb = t[2 * tx + 1][dl];
        const float fa = __bfloat162float(__float2bfloat16(va));
        const float fb = __bfloat162float(__float2bfloat16(vb));
        char* rowp = Vt + ((size_t)b * D_ + d0 + dl) * 8192;
        *reinterpret_cast<uint32_t*>(rowp + 2 * s) = pack_bf2(fa * UPS_, fb * UPS_);
        *reinterpret_cast<uint16_t*>(rowp + 4096 + s) =
            (uint16_t)(e4m3(fa) | (e4m3(fb) << 8));
        *reinterpret_cast<uint16_t*>(rowp + 6144 + s) =
            (uint16_t)(e4m3((va - fa) * UPS_) | (e4m3((vb - fb) * UPS_) << 8));
    }
}

// ---------------------------------------------------------------------------
// Small exact-bias kernels
// ---------------------------------------------------------------------------
__global__ void w2_kernel(const float* __restrict__ Wk, const float* __restrict__ bq,
                          float* __restrict__ w2)
{
    const int a = blockIdx.x * 256 + threadIdx.x;
    float s = 0.0f;
    for (int d = 0; d < D_; d++) s += bq[d] * Wk[(long)d * D_ + a];
    w2[a] = s;
}

__global__ void cb_kernel(const float* __restrict__ Wo, const float* __restrict__ bv,
                          const float* __restrict__ bo, float* __restrict__ cb)
{
    const int o = blockIdx.x * 8 + (threadIdx.x >> 5);
    const int lane = threadIdx.x & 31;
    float s = 0.0f;
    for (int e = lane * 4; e < D_; e += 128) {
        const float4 w = *reinterpret_cast<const float4*>(Wo + (long)o * D_ + e);
        const float4 b = *reinterpret_cast<const float4*>(bv + e);
        s += w.x * b.x + w.y * b.y + w.z * b.z + w.w * b.w;
    }
#pragma unroll
    for (int off = 16; off > 0; off >>= 1) s += __shfl_xor_sync(0xffffffffu, s, off);
    if (lane == 0) cb[o] = bo[o] + s;
}

__global__ void vb_kernel(const float* __restrict__ key, const float* __restrict__ w2,
                          float* __restrict__ vb)
{
    const int m = blockIdx.x * 8 + (threadIdx.x >> 5);
    const int lane = threadIdx.x & 31;
    const float* row = key + (long)m * D_;
    float s = 0.0f;
    for (int a = lane * 4; a < D_; a += 128) {
        const float4 k = *reinterpret_cast<const float4*>(row + a);
        const float4 w = *reinterpret_cast<const float4*>(w2 + a);
        s += k.x * w.x + k.y * w.y + k.z * w.z + k.w * w.w;
    }
#pragma unroll
    for (int off = 16; off > 0; off >>= 1) s += __shfl_xor_sync(0xffffffffu, s, off);
    if (lane == 0) {
        const int b = m & (B_ - 1);
        const int j = m >> 3;
        vb[(long)b * S_ + j] = s * SCALE_;   // pre-scaled for EPI4
    }
}

// ---------------------------------------------------------------------------
// Fused row softmax + A-role split emit. Pbf rows: K=S (8192B).
// ---------------------------------------------------------------------------
__global__ void __launch_bounds__(256) softmax_split(const float* __restrict__ P,
                                                     char* __restrict__ Pb)
{
    const int i = blockIdx.x, b = blockIdx.y;
    const float* p = P + ((size_t)b * S_ + i) * S_;
    char* rowp = Pb + ((size_t)b * S_ + i) * 8192;
    const int jEnd = ((i >> 7) + 1) << 7;
    const int tid = threadIdx.x;
    __shared__ float sm[8];

    float m = neg_inf_f();
    for (int j = tid * 4; j < jEnd; j += 1024) {
        const float4 v = *reinterpret_cast<const float4*>(p + j);
        m = fmaxf(m, fmaxf(fmaxf(v.x, v.y), fmaxf(v.z, v.w)));
    }
#pragma unroll
    for (int off = 16; off > 0; off >>= 1) m = fmaxf(m, __shfl_xor_sync(0xffffffffu, m, off));
    if ((tid & 31) == 0) sm[tid >> 5] = m;
    __syncthreads();
    const float rowmax = fmaxf(fmaxf(fmaxf(sm[0], sm[1]), fmaxf(sm[2], sm[3])),
                               fmaxf(fmaxf(sm[4], sm[5]), fmaxf(sm[6], sm[7])));
    __syncthreads();

    float s = 0.0f;
    for (int j = tid * 4; j < jEnd; j += 1024) {
        const float4 v = *reinterpret_cast<const float4*>(p + j);
        s += __expf(v.x - rowmax) + __expf(v.y - rowmax)
           + __expf(v.z - rowmax) + __expf(v.w - rowmax);
    }
#pragma unroll
    for (int off = 16; off > 0; off >>= 1) s += __shfl_xor_sync(0xffffffffu, s, off);
    if ((tid & 31) == 0) sm[tid >> 5] = s;
    __syncthreads();
    const float inv = 1.0f / ((sm[0] + sm[1]) + (sm[2] + sm[3]) + (sm[4] + sm[5]) + (sm[6] + sm[7]));

    for (int j = tid * 4; j < jEnd; j += 1024) {
        const float4 v = *reinterpret_cast<const float4*>(p + j);
        const float e0 = __expf(v.x - rowmax) * inv;
        const float e1 = __expf(v.y - rowmax) * inv;
        const float e2 = __expf(v.z - rowmax) * inv;
        const float e3 = __expf(v.w - rowmax) * inv;
        const float f0 = __bfloat162float(__float2bfloat16(e0));
        const float f1 = __bfloat162float(__float2bfloat16(e1));
        const float f2 = __bfloat162float(__float2bfloat16(e2));
        const float f3 = __bfloat162float(__float2bfloat16(e3));
        uint2 hp; hp.x = pack_bf2(f0, f1); hp.y = pack_bf2(f2, f3);
        *reinterpret_cast<uint2*>(rowp + 2 * j) = hp;
        *reinterpret_cast<uint32_t*>(rowp + 4096 + j) = e4m3x4(f0, f1, f2, f3);
        *reinterpret_cast<uint32_t*>(rowp + 6144 + j) =
            e4m3x4((e0 - f0) * UPS_, (e1 - f1) * UPS_, (e2 - f2) * UPS_, (e3 - f3) * UPS_);
    }
}

// ---------------------------------------------------------------------------
extern "C" void kernel_launch(void* const* d_in, const int* in_sizes, int n_in,
                              void* d_out, int out_size)
{
    const float* query = (const float*)d_in[0];
    const float* key   = (const float*)d_in[1];
    const float* value = (const float*)d_in[2];
    const float* Wq = (const float*)d_in[4];
    const float* bq = (const float*)d_in[5];
    const float* Wk = (const float*)d_in[6];
    // d_in[7] = bk : softmax-invariant, dropped exactly
    const float* Wv = (const float*)d_in[8];
    const float* bv = (const float*)d_in[9];
    const float* Wo = (const float*)d_in[10];
    const float* bo = (const float*)d_in[11];
    float* out = (float*)d_out;

    char *Qc, *Kc, *Vc, *WkT, *WqT, *WvT, *Wos, *H, *WvoB, *T, *Zt, *Pbf;
    float *Zf, *P, *w2, *cb, *vb;
    cudaGetSymbolAddress((void**)&Qc,  g_Qc);
    cudaGetSymbolAddress((void**)&Kc,  g_Kc);
    cudaGetSymbolAddress((void**)&Vc,  g_Vc);
    cudaGetSymbolAddress((void**)&WkT, g_WkT);
    cudaGetSymbolAddress((void**)&WqT, g_WqT);
    cudaGetSymbolAddress((void**)&WvT, g_WvT);
    cudaGetSymbolAddress((void**)&Wos, g_Wos);
    cudaGetSymbolAddress((void**)&H,   g_H);
    cudaGetSymbolAddress((void**)&WvoB,g_WvoB);
    cudaGetSymbolAddress((void**)&T,   g_T);
    cudaGetSymbolAddress((void**)&Zf,  g_Zf);
    cudaGetSymbolAddress((void**)&Zt,  g_Zt);
    cudaGetSymbolAddress((void**)&P,   g_P);
    cudaGetSymbolAddress((void**)&Pbf, g_Pbf);
    cudaGetSymbolAddress((void**)&w2,  g_w2);
    cudaGetSymbolAddress((void**)&cb,  g_cb);
    cudaGetSymbolAddress((void**)&vb,  g_vb);

    cudaFuncSetAttribute(gemm_dual<2, 2>,
                         cudaFuncAttributeMaxDynamicSharedMemorySize, GEMM_SMEM);
    cudaFuncSetAttribute(gemm_dual<1, 0>,
                         cudaFuncAttributeMaxDynamicSharedMemorySize, GEMM_SMEM);
    cudaFuncSetAttribute(gemm_one<4, false, true>,
                         cudaFuncAttributeMaxDynamicSharedMemorySize, GEMM_SMEM);
    cudaFuncSetAttribute(gemm_one<0, true, false>,
                         cudaFuncAttributeMaxDynamicSharedMemorySize, GEMM_SMEM);

    const long n4w = (long)D_ * D_ / 4;
    const long n4i = (long)M_ * D_ / 4;

    // ---- conversions ----
    conv_split_in<<<dim3((unsigned)(n4i / 1024), 1, 3), 256>>>(query, key, value, Qc, Kc, Vc);
    conv_split_k1024<<<(unsigned)((n4w + 255) / 256), 256>>>(Wo, Wos, n4w);
    transpose_split_w<<<dim3(D_ / 32, D_ / 32), dim3(32, 8)>>>(Wk, WkT, 1.0f);
    transpose_split_w<<<dim3(D_ / 32, D_ / 32), dim3(32, 8)>>>(Wq, WqT, UPS_);
    transpose_split_w<<<dim3(D_ / 32, D_ / 32), dim3(32, 8)>>>(Wv, WvT, UPS_);

    // ---- exact bias terms ----
    w2_kernel<<<D_ / 256, 256>>>(Wk, bq, w2);
    cb_kernel<<<D_ / 8, 256>>>(Wo, bv, bo, cb);
    vb_kernel<<<M_ / 8, 256>>>(key, w2, vb);

    // ---- H = Wk^T Wq (B-role out)  and  WvoB = Wo Wv (B-role out) ----
    GArgs hA{};
    hA.A = WkT; hA.ldaB = 4096; hA.bsAB = 0; hA.aH8 = 2048; hA.aL8 = 3072;
    hA.B = WqT; hA.ldbB = 4096; hA.bsBB = 0; hA.bH8 = 2048; hA.bL8 = 3072;
    hA.Kpart = D_; hA.scale = DNS_;
    hA.outH = H; hA.ldoB = 4096; hA.bsOB = 0; hA.oH8 = 2048; hA.oL8 = 3072;
    GArgs hB = hA;
    hB.A = Wos; hB.B = WvT; hB.outH = WvoB;
    gemm_dual<2, 2><<<dim3(D_ / 128, D_ / 256, 2), 256, GEMM_SMEM>>>(hA, hB);

    // ---- T = query*G (A-role out)  and  Z = value*Wvo^T (fp32), dual ----
    GArgs tA{};
    tA.A = Qc; tA.ldaB = 4096; tA.bsAB = 0; tA.aH8 = 2048; tA.aL8 = 3072;
    tA.B = H;  tA.ldbB = 4096; tA.bsBB = 0; tA.bH8 = 2048; tA.bL8 = 3072;
    tA.Kpart = D_; tA.scale = DNS_;
    tA.outH = T; tA.ldoB = 4096; tA.bsOB = 0; tA.oH8 = 2048; tA.oL8 = 3072;
    GArgs tB{};
    tB.A = Vc; tB.ldaB = 4096; tB.bsAB = 0; tB.aH8 = 2048; tB.aL8 = 3072;
    tB.B = WvoB; tB.ldbB = 4096; tB.bsBB = 0; tB.bH8 = 2048; tB.bL8 = 3072;
    tB.Kpart = D_; tB.scale = DNS_;
    tB.outF = Zf; tB.ldo = D_; tB.bsO = 0;
    gemm_dual<1, 0><<<dim3(D_ / 128, M_ / 256, 2), 256, GEMM_SMEM>>>(tA, tB);

    // ---- Z^T (B-role) for the PV GEMM ----
    transpose_split_v<<<dim3(D_ / 32, S_ / 64, B_), dim3(32, 8)>>>(Zf, Zt);

    // ---- Scores: P = SCALE*(T.key^T) + vbS, tril tiles, causal mask ----
    GArgs sc{};
    sc.A = T;  sc.ldaB = (long)B_ * 4096; sc.bsAB = 4096; sc.aH8 = 2048; sc.aL8 = 3072;
    sc.B = Kc; sc.ldbB = (long)B_ * 4096; sc.bsBB = 4096; sc.bH8 = 2048; sc.bL8 = 3072;
    sc.Kpart = D_; sc.scale = SCALE_ * DNS_; sc.cbias = vb;
    sc.outF = P; sc.ldo = S_; sc.bsO = (long)S_ * S_;
    gemm_one<4, false, true><<<dim3(S_ / 128, S_ / 256, B_), 256, GEMM_SMEM>>>(sc);

    // ---- fused softmax + A-role split ----
    softmax_split<<<dim3(S_, B_), 256>>>(P, Pbf);

    // ---- out = P @ Z + cb (causal K bound), fp32 to d_out ----
    GArgs pv{};
    pv.A = Pbf; pv.ldaB = 8192; pv.bsAB = (long)S_ * 8192; pv.aH8 = 4096; pv.aL8 = 6144;
    pv.B = Zt;  pv.ldbB = 8192; pv.bsBB = (long)D_ * 8192; pv.bH8 = 4096; pv.bL8 = 6144;
    pv.Kpart = S_; pv.scale = DNS_; pv.bias = cb;
    pv.outF = out; pv.ldo = (long)B_ * D_; pv.bsO = D_;
    gemm_one<0, true, false><<<dim3(D_ / 128, S_ / 256, B_), 256, GEMM_SMEM>>>(pv);
}

// round 12
// speedup vs baseline: 1.3040x; 1.3040x over previous
#include <cuda_runtime.h>
#include <cuda_bf16.h>
#include <cstdint>
#include <math.h>

// ---------------------------------------------------------------------------
// Problem constants
// ---------------------------------------------------------------------------
static constexpr int S_ = 2048, B_ = 8, D_ = 1024, M_ = S_ * B_;
static constexpr float SCALE_ = 0.03125f;  // 1/sqrt(1024)

// ---------------------------------------------------------------------------
// Static scratch. Split-bf16 layout: row-major [rows][2*K]: hi at [k], lo at [K+k].
// ---------------------------------------------------------------------------
__device__ __nv_bfloat16 g_Qc [(size_t)M_ * 2 * D_];
__device__ __nv_bfloat16 g_Kc [(size_t)M_ * 2 * D_];
__device__ __nv_bfloat16 g_Vc [(size_t)M_ * 2 * D_];
__device__ __nv_bfloat16 g_WkT[(size_t)D_ * 2 * D_];
__device__ __nv_bfloat16 g_WqT[(size_t)D_ * 2 * D_];
__device__ __nv_bfloat16 g_WvT[(size_t)D_ * 2 * D_];
__device__ __nv_bfloat16 g_Wos[(size_t)D_ * 2 * D_];
__device__ __nv_bfloat16 g_H  [(size_t)D_ * 2 * D_];   // (Wk^T Wq) split
__device__ __nv_bfloat16 g_WvoB[(size_t)D_ * 2 * D_];  // (Wo Wv)[o][a] split
__device__ __nv_bfloat16 g_T  [(size_t)M_ * 2 * D_];   // T = query * G
__device__ float         g_Zf [(size_t)M_ * D_];       // Z = value * Wvo^T
__device__ __nv_bfloat16 g_Zt [(size_t)B_ * D_ * 2 * S_]; // Z^T split
__device__ float         g_P  [(size_t)B_ * S_ * S_];
__device__ __nv_bfloat16 g_Pbf[(size_t)B_ * S_ * 2 * S_];
__device__ float         g_w2 [D_];
__device__ float         g_cb [D_];
__device__ float         g_vb [(size_t)B_ * S_];

// ---------------------------------------------------------------------------
// Portable PTX helpers
// ---------------------------------------------------------------------------
__device__ __forceinline__ uint32_t smem_u32(const void* p) {
    uint32_t a;
    asm("{ .reg .u64 t; cvta.to.shared.u64 t, %1; cvt.u32.u64 %0, t; }" : "=r"(a) : "l"(p));
    return a;
}

__device__ __forceinline__ void ldsm4(uint32_t* r, uint32_t a) {
    asm volatile("ldmatrix.sync.aligned.m8n8.x4.shared.b16 {%0,%1,%2,%3}, [%4];"
                 : "=r"(r[0]), "=r"(r[1]), "=r"(r[2]), "=r"(r[3]) : "r"(a));
}

__device__ __forceinline__ void mma16816(float* d, const uint32_t* a, const uint32_t* b) {
    asm volatile(
        "mma.sync.aligned.m16n8k16.row.col.f32.bf16.bf16.f32 "
        "{%0,%1,%2,%3}, {%4,%5,%6,%7}, {%8,%9}, {%0,%1,%2,%3};"
        : "+f"(d[0]), "+f"(d[1]), "+f"(d[2]), "+f"(d[3])
        : "r"(a[0]), "r"(a[1]), "r"(a[2]), "r"(a[3]), "r"(b[0]), "r"(b[1]));
}

__device__ __forceinline__ void cp16(uint32_t saddr, const void* gaddr) {
    asm volatile("cp.async.cg.shared.global [%0], [%1], 16;" :: "r"(saddr), "l"(gaddr));
}
__device__ __forceinline__ void cp_commit() {
    asm volatile("cp.async.commit_group;" ::: "memory");
}
template<int N>
__device__ __forceinline__ void cp_wait() {
    asm volatile("cp.async.wait_group %0;" :: "n"(N) : "memory");
}

__device__ __forceinline__ float neg_inf_f() { return __int_as_float(0xff800000); }

__device__ __forceinline__ uint32_t pack_bf2(float a, float b) {
    __nv_bfloat162 h = __floats2bfloat162_rn(a, b);
    return *reinterpret_cast<uint32_t*>(&h);
}

// ---------------------------------------------------------------------------
// Fused split GEMM. CTA tile 256x128, 512 threads = 16 warps, warp tile 32x64
// (wm = warp>>1 in 0..7, wn = warp&1). k-chunk 64, 2-stage cp.async pipeline.
// acc = 2-level split: Alo*Bhi + Ahi*Bhi + Ahi*Blo.
// EPI: 0 = fp32 out (+bias), 1 = split-bf16 out, 4 = scores (cbias+mask+scale)
// ---------------------------------------------------------------------------
struct GArgs {
    const __nv_bfloat16* A; const __nv_bfloat16* B;
    long lda, ldb, bsA, bsB;
    long oAlo, oBlo;
    int  Kpart;
    float scale;
    const float* bias;
    const float* cbias;
    float* outF;
    __nv_bfloat16* outH;
    long ldo, bsO, loOff;
};

static constexpr int A_TILE = 32768;
static constexpr int B_TILE = 16384;
static constexpr int STAGE  = 2 * A_TILE + 2 * B_TILE;  // 96 KB
static constexpr int GEMM_SMEM = 1024 + 2 * STAGE;      // 193 KB
static constexpr int NT = 512;

template<int EPI, bool CAUSALK, bool TRIL>
__device__ __forceinline__ void gemm_body(const GArgs& g, int nt, int mt, int bz)
{
    if (TRIL && nt * 128 > mt * 256 + 255) return;
    const int mBase = mt * 256, nBase = nt * 128;

    extern __shared__ char smem_raw[];
    const uint32_t sbase = smem_u32(smem_raw);
    const uint32_t abase = (sbase + 1023) & ~1023u;

    const int tid  = threadIdx.x;
    const int lane = tid & 31;
    const int warp = tid >> 5;
    const int wm   = warp >> 1;        // 0..7 -> m offset wm*32
    const int wn   = warp & 1;         // 0..1 -> n offset wn*64

    const __nv_bfloat16* Ab = g.A + (long)bz * g.bsA;
    const __nv_bfloat16* Bb = g.B + (long)bz * g.bsB;

    const int kEff = CAUSALK ? (mBase + 256) : g.Kpart;
    const int nch  = kEff >> 6;

    auto issue_chunk = [&](int c) {
        const long kc = (long)(c << 6);
        const int st = c & 1;
        const uint32_t sAhi = abase + st * STAGE;
        const uint32_t sAlo = sAhi + A_TILE;
        const uint32_t sBhi = sAhi + 2 * A_TILE;
        const uint32_t sBlo = sBhi + B_TILE;
#pragma unroll
        for (int i = 0; i < 4; i++) {     // A: 256 rows x 8 blocks
            const int id = tid + i * NT;
            const int row = id >> 3, cc = id & 7;
            const uint32_t so = (uint32_t)(row << 7) + (uint32_t)((cc ^ (row & 7)) << 4);
            const __nv_bfloat16* src = Ab + (long)(mBase + row) * g.lda + kc + cc * 8;
            cp16(sAhi + so, src);
            cp16(sAlo + so, src + g.oAlo);
        }
#pragma unroll
        for (int i = 0; i < 2; i++) {     // B: 128 rows x 8 blocks
            const int id = tid + i * NT;
            const int row = id >> 3, cc = id & 7;
            const uint32_t so = (uint32_t)(row << 7) + (uint32_t)((cc ^ (row & 7)) << 4);
            const __nv_bfloat16* src = Bb + (long)(nBase + row) * g.ldb + kc + cc * 8;
            cp16(sBhi + so, src);
            cp16(sBlo + so, src + g.oBlo);
        }
        cp_commit();
    };

    float acc[2][8][4];
#pragma unroll
    for (int i = 0; i < 2; i++)
#pragma unroll
        for (int j = 0; j < 8; j++)
#pragma unroll
            for (int d = 0; d < 4; d++) acc[i][j][d] = 0.0f;

    issue_chunk(0);

    const int arow = (lane & 7) + ((lane >> 3) & 1) * 8;
    const int acol = lane >> 4;
    const int brow = (lane & 7) + ((lane >> 4) & 1) * 8;
    const int bcol = (lane >> 3) & 1;

    for (int c = 0; c < nch; c++) {
        if (c + 1 < nch) issue_chunk(c + 1);
        if (c + 1 < nch) cp_wait<1>(); else cp_wait<0>();
        __syncthreads();

        const int st = c & 1;
        const uint32_t sAhi = abase + st * STAGE;
        const uint32_t sAlo = sAhi + A_TILE;
        const uint32_t sBhi = sAhi + 2 * A_TILE;
        const uint32_t sBlo = sBhi + B_TILE;

#pragma unroll
        for (int ks = 0; ks < 4; ks++) {
            uint32_t af[2][4], bf[4][4];
            // pass 1: Alo x Bhi
#pragma unroll
            for (int mi = 0; mi < 2; mi++) {
                const int row = wm * 32 + mi * 16 + arow;
                const int cc  = ks * 2 + acol;
                ldsm4(af[mi], sAlo + (row << 7) + ((cc ^ (row & 7)) << 4));
            }
#pragma unroll
            for (int nj = 0; nj < 4; nj++) {
                const int row = wn * 64 + nj * 16 + brow;
                const int cc  = ks * 2 + bcol;
                ldsm4(bf[nj], sBhi + (row << 7) + ((cc ^ (row & 7)) << 4));
            }
#pragma unroll
            for (int mi = 0; mi < 2; mi++)
#pragma unroll
                for (int nj = 0; nj < 4; nj++) {
                    mma16816(acc[mi][2 * nj],     af[mi], &bf[nj][0]);
                    mma16816(acc[mi][2 * nj + 1], af[mi], &bf[nj][2]);
                }
            // pass 2: Ahi x Bhi (swap A only)
#pragma unroll
            for (int mi = 0; mi < 2; mi++) {
                const int row = wm * 32 + mi * 16 + arow;
                const int cc  = ks * 2 + acol;
                ldsm4(af[mi], sAhi + (row << 7) + ((cc ^ (row & 7)) << 4));
            }
#pragma unroll
            for (int mi = 0; mi < 2; mi++)
#pragma unroll
                for (int nj = 0; nj < 4; nj++) {
                    mma16816(acc[mi][2 * nj],     af[mi], &bf[nj][0]);
                    mma16816(acc[mi][2 * nj + 1], af[mi], &bf[nj][2]);
                }
            // pass 3: Ahi x Blo (swap B only)
#pragma unroll
            for (int nj = 0; nj < 4; nj++) {
                const int row = wn * 64 + nj * 16 + brow;
                const int cc  = ks * 2 + bcol;
                ldsm4(bf[nj], sBlo + (row << 7) + ((cc ^ (row & 7)) << 4));
            }
#pragma unroll
            for (int mi = 0; mi < 2; mi++)
#pragma unroll
                for (int nj = 0; nj < 4; nj++) {
                    mma16816(acc[mi][2 * nj],     af[mi], &bf[nj][0]);
                    mma16816(acc[mi][2 * nj + 1], af[mi], &bf[nj][2]);
                }
        }
        __syncthreads();
    }

    // ------------------------- epilogue (compile-time EPI) -------------------
    const int gq = lane >> 2, tg = lane & 3;
#pragma unroll
    for (int mi = 0; mi < 2; mi++) {
#pragma unroll
        for (int half = 0; half < 2; half++) {
            const int gm = mBase + wm * 32 + mi * 16 + gq + half * 8;
#pragma unroll
            for (int ni = 0; ni < 8; ni++) {
                const int gn = nBase + wn * 64 + ni * 8 + 2 * tg;
                const float v0 = acc[mi][ni][half * 2 + 0];
                const float v1 = acc[mi][ni][half * 2 + 1];

                if (EPI == 0) {
                    float2 v;
                    v.x = v0; v.y = v1;
                    if (g.bias) { v.x += g.bias[gn + 0]; v.y += g.bias[gn + 1]; }
                    *reinterpret_cast<float2*>(
                        g.outF + (long)bz * g.bsO + (long)gm * g.ldo + gn) = v;
                } else if (EPI == 1) {
                    const __nv_bfloat16 h0 = __float2bfloat16(v0);
                    const __nv_bfloat16 h1 = __float2bfloat16(v1);
                    const __nv_bfloat16 l0 = __float2bfloat16(v0 - __bfloat162float(h0));
                    const __nv_bfloat16 l1 = __float2bfloat16(v1 - __bfloat162float(h1));
                    __nv_bfloat16* o = g.outH + (long)bz * g.bsO + (long)gm * g.ldo + gn;
                    *reinterpret_cast<__nv_bfloat162*>(o) = __nv_bfloat162(h0, h1);
                    *reinterpret_cast<__nv_bfloat162*>(o + g.loOff) = __nv_bfloat162(l0, l1);
                } else {  // EPI == 4 : scores
                    const float cb0 = g.cbias[(long)bz * S_ + gn + 0];
                    const float cb1 = g.cbias[(long)bz * S_ + gn + 1];
                    float2 v;
                    v.x = (gn + 0 > gm) ? neg_inf_f() : (v0 + cb0) * g.scale;
                    v.y = (gn + 1 > gm) ? neg_inf_f() : (v1 + cb1) * g.scale;
                    *reinterpret_cast<float2*>(
                        g.outF + (long)bz * g.bsO + (long)gm * g.ldo + gn) = v;
                }
            }
        }
    }
}

template<int EPI, bool CAUSALK, bool TRIL>
__global__ void __launch_bounds__(NT, 1) gemm_one(GArgs g)
{
    gemm_body<EPI, CAUSALK, TRIL>(g, blockIdx.x, gridDim.y - 1 - blockIdx.y, blockIdx.z);
}

template<int E0, int E1>
__global__ void __launch_bounds__(NT, 1) gemm_dual(GArgs g0, GArgs g1)
{
    if (blockIdx.z == 0)
        gemm_body<E0, false, false>(g0, blockIdx.x, blockIdx.y, 0);
    else
        gemm_body<E1, false, false>(g1, blockIdx.x, blockIdx.y, 0);
}

// ---------------------------------------------------------------------------
// Merged q/k/v fp32 -> split bf16 [m][2*1024]; 4 float4s per thread (MLP=4)
// ---------------------------------------------------------------------------
__global__ void conv_split_in(const float* __restrict__ q, const float* __restrict__ k,
                              const float* __restrict__ v,
                              __nv_bfloat16* __restrict__ Qc, __nv_bfloat16* __restrict__ Kc,
                              __nv_bfloat16* __restrict__ Vc)
{
    const float* in = (blockIdx.z == 0) ? q : (blockIdx.z == 1) ? k : v;
    __nv_bfloat16* out = (blockIdx.z == 0) ? Qc : (blockIdx.z == 1) ? Kc : Vc;
    const long base = (long)blockIdx.x * 1024 + threadIdx.x;

    float4 v4[4];
#pragma unroll
    for (int j = 0; j < 4; j++)
        v4[j] = reinterpret_cast<const float4*>(in)[base + j * 256];

#pragma unroll
    for (int j = 0; j < 4; j++) {
        const long idx = (base + j * 256) * 4;
        const long m = idx >> 10;
        const int  kk = (int)(idx & 1023);
        const __nv_bfloat16 h0 = __float2bfloat16(v4[j].x);
        const __nv_bfloat16 h1 = __float2bfloat16(v4[j].y);
        const __nv_bfloat16 h2 = __float2bfloat16(v4[j].z);
        const __nv_bfloat16 h3 = __float2bfloat16(v4[j].w);
        uint2 hp, lp;
        hp.x = pack_bf2(v4[j].x, v4[j].y);
        hp.y = pack_bf2(v4[j].z, v4[j].w);
        lp.x = pack_bf2(v4[j].x - __bfloat162float(h0), v4[j].y - __bfloat162float(h1));
        lp.y = pack_bf2(v4[j].z - __bfloat162float(h2), v4[j].w - __bfloat162float(h3));
        __nv_bfloat16* o = out + m * 2048 + kk;
        *reinterpret_cast<uint2*>(o)        = hp;
        *reinterpret_cast<uint2*>(o + 1024) = lp;
    }
}

// ---------------------------------------------------------------------------
// Weight fp32 -> split bf16 (row-major)
// ---------------------------------------------------------------------------
__global__ void conv_split_k1024(const float* __restrict__ in,
                                 __nv_bfloat16* __restrict__ out, long n4)
{
    const long i = (long)blockIdx.x * 256 + threadIdx.x;
    if (i >= n4) return;
    const float4 v = reinterpret_cast<const float4*>(in)[i];
    const long idx = i * 4;
    const long m = idx >> 10;
    const int  k = (int)(idx & 1023);
    const __nv_bfloat16 h0 = __float2bfloat16(v.x);
    const __nv_bfloat16 h1 = __float2bfloat16(v.y);
    const __nv_bfloat16 h2 = __float2bfloat16(v.z);
    const __nv_bfloat16 h3 = __float2bfloat16(v.w);
    uint2 hp, lp;
    hp.x = pack_bf2(v.x, v.y);
    hp.y = pack_bf2(v.z, v.w);
    lp.x = pack_bf2(v.x - __bfloat162float(h0), v.y - __bfloat162float(h1));
    lp.y = pack_bf2(v.z - __bfloat162float(h2), v.w - __bfloat162float(h3));
    __nv_bfloat16* o = out + m * 2048 + k;
    *reinterpret_cast<uint2*>(o)        = hp;
    *reinterpret_cast<uint2*>(o + 1024) = lp;
}

// ---------------------------------------------------------------------------
// 3 weight transposes merged: z picks (Wk->WkT, Wq->WqT, Wv->WvT)
// ---------------------------------------------------------------------------
__global__ void transpose_split_w3(const float* __restrict__ Wk, const float* __restrict__ Wq,
                                   const float* __restrict__ Wv,
                                   __nv_bfloat16* __restrict__ WkT, __nv_bfloat16* __restrict__ WqT,
                                   __nv_bfloat16* __restrict__ WvT)
{
    const float* W = (blockIdx.z == 0) ? Wk : (blockIdx.z == 1) ? Wq : Wv;
    __nv_bfloat16* out = (blockIdx.z == 0) ? WkT : (blockIdx.z == 1) ? WqT : WvT;

    __shared__ float t[32][33];
    const int a0 = blockIdx.x * 32, e0 = blockIdx.y * 32;
    const int tx = threadIdx.x, ty = threadIdx.y;
#pragma unroll
    for (int r = 0; r < 32; r += 8)
        t[r + ty][tx] = W[(long)(e0 + r + ty) * D_ + a0 + tx];
    __syncthreads();
#pragma unroll
    for (int r = 0; r < 32; r += 8) {
        const int a = a0 + r + ty, e = e0 + tx;
        const float v = t[tx][r + ty];
        const __nv_bfloat16 h = __float2bfloat16(v);
        __nv_bfloat16* o = out + (long)a * 2 * D_ + e;
        o[0]  = h;
        o[D_] = __float2bfloat16(v - __bfloat162float(h));
    }
}

// ---------------------------------------------------------------------------
// Z fp32 [s*B+b][d] -> Zt split [b][d][hi(S)|lo(S)], packed uint32 stores.
// ---------------------------------------------------------------------------
__global__ void transpose_split_v(const float* __restrict__ Vf,
                                  __nv_bfloat16* __restrict__ Vt)
{
    __shared__ float t[64][33];
    const int d0 = blockIdx.x * 32, s0 = blockIdx.y * 64, b = blockIdx.z;
    const int tx = threadIdx.x, ty = threadIdx.y;
#pragma unroll
    for (int j = 0; j < 8; j++) {
        const int sl = j * 8 + ty;
        t[sl][tx] = Vf[((size_t)(s0 + sl) * B_ + b) * D_ + d0 + tx];
    }
    __syncthreads();
#pragma unroll
    for (int jj = 0; jj < 4; jj++) {
        const int dl = jj * 8 + ty;
        const float va = t[2 * tx][dl];
        const float vb = t[2 * tx + 1][dl];
        const __nv_bfloat16 ha = __float2bfloat16(va);
        const __nv_bfloat16 hb = __float2bfloat16(vb);
        __nv_bfloat16* o = Vt + ((size_t)b * D_ + d0 + dl) * (2 * S_) + s0 + 2 * tx;
        *reinterpret_cast<uint32_t*>(o) = pack_bf2(va, vb);
        *reinterpret_cast<uint32_t*>(o + S_) =
            pack_bf2(va - __bfloat162float(ha), vb - __bfloat162float(hb));
    }
}

// ---------------------------------------------------------------------------
// Small exact-bias kernels
// ---------------------------------------------------------------------------
__global__ void w2_kernel(const float* __restrict__ Wk, const float* __restrict__ bq,
                          float* __restrict__ w2)
{
    const int a = blockIdx.x * 256 + threadIdx.x;
    float s = 0.0f;
    for (int d = 0; d < D_; d++) s += bq[d] * Wk[(long)d * D_ + a];
    w2[a] = s;
}

__global__ void cb_kernel(const float* __restrict__ Wo, const float* __restrict__ bv,
                          const float* __restrict__ bo, float* __restrict__ cb)
{
    const int o = blockIdx.x * 8 + (threadIdx.x >> 5);
    const int lane = threadIdx.x & 31;
    float s = 0.0f;
    for (int e = lane * 4; e < D_; e += 128) {
        const float4 w = *reinterpret_cast<const float4*>(Wo + (long)o * D_ + e);
        const float4 b = *reinterpret_cast<const float4*>(bv + e);
        s += w.x * b.x + w.y * b.y + w.z * b.z + w.w * b.w;
    }
#pragma unroll
    for (int off = 16; off > 0; off >>= 1) s += __shfl_xor_sync(0xffffffffu, s, off);
    if (lane == 0) cb[o] = bo[o] + s;
}

__global__ void vb_kernel(const float* __restrict__ key, const float* __restrict__ w2,
                          float* __restrict__ vb)
{
    const int m = blockIdx.x * 8 + (threadIdx.x >> 5);
    const int lane = threadIdx.x & 31;
    const float* row = key + (long)m * D_;
    float s = 0.0f;
    for (int a = lane * 4; a < D_; a += 128) {
        const float4 k = *reinterpret_cast<const float4*>(row + a);
        const float4 w = *reinterpret_cast<const float4*>(w2 + a);
        s += k.x * w.x + k.y * w.y + k.z * w.z + k.w * w.w;
    }
#pragma unroll
    for (int off = 16; off > 0; off >>= 1) s += __shfl_xor_sync(0xffffffffu, s, off);
    if (lane == 0) {
        const int b = m & (B_ - 1);
        const int j = m >> 3;
        vb[(long)b * S_ + j] = s;
    }
}

// ---------------------------------------------------------------------------
// Fused row softmax + split-bf16 emit (fast exp, float4 strides)
// ---------------------------------------------------------------------------
__global__ void __launch_bounds__(256) softmax_split(const float* __restrict__ P,
                                                     __nv_bfloat16* __restrict__ Pb)
{
    const int i = blockIdx.x, b = blockIdx.y;
    const float* p = P + ((size_t)b * S_ + i) * S_;
    __nv_bfloat16* o = Pb + ((size_t)b * S_ + i) * (2 * S_);
    const int jEnd = ((i >> 7) + 1) << 7;
    const int tid = threadIdx.x;
    __shared__ float sm[8];

    float m = neg_inf_f();
    for (int j = tid * 4; j < jEnd; j += 1024) {
        const float4 v = *reinterpret_cast<const float4*>(p + j);
        m = fmaxf(m, fmaxf(fmaxf(v.x, v.y), fmaxf(v.z, v.w)));
    }
#pragma unroll
    for (int off = 16; off > 0; off >>= 1) m = fmaxf(m, __shfl_xor_sync(0xffffffffu, m, off));
    if ((tid & 31) == 0) sm[tid >> 5] = m;
    __syncthreads();
    const float rowmax = fmaxf(fmaxf(fmaxf(sm[0], sm[1]), fmaxf(sm[2], sm[3])),
                               fmaxf(fmaxf(sm[4], sm[5]), fmaxf(sm[6], sm[7])));
    __syncthreads();

    float s = 0.0f;
    for (int j = tid * 4; j < jEnd; j += 1024) {
        const float4 v = *reinterpret_cast<const float4*>(p + j);
        s += __expf(v.x - rowmax) + __expf(v.y - rowmax)
           + __expf(v.z - rowmax) + __expf(v.w - rowmax);
    }
#pragma unroll
    for (int off = 16; off > 0; off >>= 1) s += __shfl_xor_sync(0xffffffffu, s, off);
    if ((tid & 31) == 0) sm[tid >> 5] = s;
    __syncthreads();
    const float inv = 1.0f / ((sm[0] + sm[1]) + (sm[2] + sm[3]) + (sm[4] + sm[5]) + (sm[6] + sm[7]));

    for (int j = tid * 4; j < jEnd; j += 1024) {
        const float4 v = *reinterpret_cast<const float4*>(p + j);
        const float e0 = __expf(v.x - rowmax) * inv;
        const float e1 = __expf(v.y - rowmax) * inv;
        const float e2 = __expf(v.z - rowmax) * inv;
        const float e3 = __expf(v.w - rowmax) * inv;
        const __nv_bfloat16 h0 = __float2bfloat16(e0);
        const __nv_bfloat16 h1 = __float2bfloat16(e1);
        const __nv_bfloat16 h2 = __float2bfloat16(e2);
        const __nv_bfloat16 h3 = __float2bfloat16(e3);
        uint2 hp, lp;
        hp.x = pack_bf2(e0, e1); hp.y = pack_bf2(e2, e3);
        lp.x = pack_bf2(e0 - __bfloat162float(h0), e1 - __bfloat162float(h1));
        lp.y = pack_bf2(e2 - __bfloat162float(h2), e3 - __bfloat162float(h3));
        *reinterpret_cast<uint2*>(o + j)      = hp;
        *reinterpret_cast<uint2*>(o + S_ + j) = lp;
    }
}

// ---------------------------------------------------------------------------
extern "C" void kernel_launch(void* const* d_in, const int* in_sizes, int n_in,
                              void* d_out, int out_size)
{
    const float* query = (const float*)d_in[0];
    const float* key   = (const float*)d_in[1];
    const float* value = (const float*)d_in[2];
    const float* Wq = (const float*)d_in[4];
    const float* bq = (const float*)d_in[5];
    const float* Wk = (const float*)d_in[6];
    // d_in[7] = bk : softmax-invariant, dropped exactly
    const float* Wv = (const float*)d_in[8];
    const float* bv = (const float*)d_in[9];
    const float* Wo = (const float*)d_in[10];
    const float* bo = (const float*)d_in[11];
    float* out = (float*)d_out;

    __nv_bfloat16 *Qc, *Kc, *Vc, *WkT, *WqT, *WvT, *Wos, *H, *WvoB, *T, *Zt, *Pbf;
    float *Zf, *P, *w2, *cb, *vb;
    cudaGetSymbolAddress((void**)&Qc,  g_Qc);
    cudaGetSymbolAddress((void**)&Kc,  g_Kc);
    cudaGetSymbolAddress((void**)&Vc,  g_Vc);
    cudaGetSymbolAddress((void**)&WkT, g_WkT);
    cudaGetSymbolAddress((void**)&WqT, g_WqT);
    cudaGetSymbolAddress((void**)&WvT, g_WvT);
    cudaGetSymbolAddress((void**)&Wos, g_Wos);
    cudaGetSymbolAddress((void**)&H,   g_H);
    cudaGetSymbolAddress((void**)&WvoB,g_WvoB);
    cudaGetSymbolAddress((void**)&T,   g_T);
    cudaGetSymbolAddress((void**)&Zf,  g_Zf);
    cudaGetSymbolAddress((void**)&Zt,  g_Zt);
    cudaGetSymbolAddress((void**)&P,   g_P);
    cudaGetSymbolAddress((void**)&Pbf, g_Pbf);
    cudaGetSymbolAddress((void**)&w2,  g_w2);
    cudaGetSymbolAddress((void**)&cb,  g_cb);
    cudaGetSymbolAddress((void**)&vb,  g_vb);

    cudaFuncSetAttribute(gemm_dual<1, 1>,
                         cudaFuncAttributeMaxDynamicSharedMemorySize, GEMM_SMEM);
    cudaFuncSetAttribute(gemm_dual<1, 0>,
                         cudaFuncAttributeMaxDynamicSharedMemorySize, GEMM_SMEM);
    cudaFuncSetAttribute(gemm_one<4, false, true>,
                         cudaFuncAttributeMaxDynamicSharedMemorySize, GEMM_SMEM);
    cudaFuncSetAttribute(gemm_one<0, true, false>,
                         cudaFuncAttributeMaxDynamicSharedMemorySize, GEMM_SMEM);

    const long n4w = (long)D_ * D_ / 4;
    const long n4i = (long)M_ * D_ / 4;

    // ---- conversions ----
    conv_split_in<<<dim3((unsigned)(n4i / 1024), 1, 3), 256>>>(query, key, value, Qc, Kc, Vc);
    conv_split_k1024<<<(unsigned)((n4w + 255) / 256), 256>>>(Wo, Wos, n4w);
    transpose_split_w3<<<dim3(D_ / 32, D_ / 32, 3), dim3(32, 8)>>>(Wk, Wq, Wv, WkT, WqT, WvT);

    // ---- exact bias terms ----
    w2_kernel<<<D_ / 256, 256>>>(Wk, bq, w2);
    cb_kernel<<<D_ / 8, 256>>>(Wo, bv, bo, cb);
    vb_kernel<<<M_ / 8, 256>>>(key, w2, vb);

    // ---- H = Wk^T Wq  and  WvoB = (Wo Wv)[o][a], one dual launch ----
    GArgs hA{};
    hA.A = WkT; hA.lda = 2 * D_; hA.bsA = 0; hA.oAlo = D_;
    hA.B = WqT; hA.ldb = 2 * D_; hA.bsB = 0; hA.oBlo = D_;
    hA.Kpart = D_; hA.scale = 1.0f; hA.bias = nullptr; hA.cbias = nullptr;
    hA.outH = H; hA.ldo = 2 * D_; hA.bsO = 0; hA.loOff = D_;
    GArgs hB = hA;
    hB.A = Wos; hB.B = WvT; hB.outH = WvoB;
    gemm_dual<1, 1><<<dim3(D_ / 128, D_ / 256, 2), NT, GEMM_SMEM>>>(hA, hB);

    // ---- T = query * G (split out)  and  Z = value * Wvo^T (fp32 out), dual ----
    GArgs tA{};
    tA.A = Qc; tA.lda = 2 * D_; tA.bsA = 0; tA.oAlo = D_;
    tA.B = H;  tA.ldb = 2 * D_; tA.bsB = 0; tA.oBlo = D_;
    tA.Kpart = D_; tA.scale = 1.0f; tA.bias = nullptr; tA.cbias = nullptr;
    tA.outH = T; tA.ldo = 2 * D_; tA.bsO = 0; tA.loOff = D_;
    GArgs tB{};
    tB.A = Vc; tB.lda = 2 * D_; tB.bsA = 0; tB.oAlo = D_;
    tB.B = WvoB; tB.ldb = 2 * D_; tB.bsB = 0; tB.oBlo = D_;
    tB.Kpart = D_; tB.scale = 1.0f; tB.bias = nullptr; tB.cbias = nullptr;
    tB.outF = Zf; tB.ldo = D_; tB.bsO = 0;
    gemm_dual<1, 0><<<dim3(D_ / 128, M_ / 256, 2), NT, GEMM_SMEM>>>(tA, tB);

    // ---- Z^T split for the PV GEMM ----
    transpose_split_v<<<dim3(D_ / 32, S_ / 64, B_), dim3(32, 8)>>>(Zf, Zt);

    // ---- Scores: P = SCALE * (T . key^T + vb), tril tiles, causal mask ----
    GArgs sc{};
    sc.A = T;  sc.lda = (long)B_ * 2 * D_; sc.bsA = 2 * D_; sc.oAlo = D_;
    sc.B = Kc; sc.ldb = (long)B_ * 2 * D_; sc.bsB = 2 * D_; sc.oBlo = D_;
    sc.Kpart = D_; sc.scale = SCALE_; sc.bias = nullptr; sc.cbias = vb;
    sc.outF = P; sc.ldo = S_; sc.bsO = (long)S_ * S_;
    gemm_one<4, false, true><<<dim3(S_ / 128, S_ / 256, B_), NT, GEMM_SMEM>>>(sc);

    // ---- fused softmax + P split ----
    softmax_split<<<dim3(S_, B_), 256>>>(P, Pbf);

    // ---- out = P @ Z + cb (causal K bound), fp32 straight to d_out ----
    GArgs pv{};
    pv.A = Pbf; pv.lda = 2 * S_; pv.bsA = (long)S_ * 2 * S_; pv.oAlo = S_;
    pv.B = Zt;  pv.ldb = 2 * S_; pv.bsB = (long)D_ * 2 * S_; pv.oBlo = S_;
    pv.Kpart = S_; pv.scale = 1.0f; pv.bias = cb; pv.cbias = nullptr;
    pv.outF = out; pv.ldo = (long)B_ * D_; pv.bsO = D_;
    gemm_one<0, true, false><<<dim3(D_ / 128, S_ / 256, B_), NT, GEMM_SMEM>>>(pv);
}

// round 13
// speedup vs baseline: 1.3513x; 1.0363x over previous
#include <cuda_runtime.h>
#include <cuda_bf16.h>
#include <cstdint>
#include <math.h>

// ---------------------------------------------------------------------------
// Problem constants
// ---------------------------------------------------------------------------
static constexpr int S_ = 2048, B_ = 8, D_ = 1024, M_ = S_ * B_;
static constexpr float SCALE_ = 0.03125f;  // 1/sqrt(1024)

// ---------------------------------------------------------------------------
// Static scratch. Split-bf16 layout: row-major [rows][2*K]: hi at [k], lo at [K+k].
// ---------------------------------------------------------------------------
__device__ __nv_bfloat16 g_Qc [(size_t)M_ * 2 * D_];
__device__ __nv_bfloat16 g_Kc [(size_t)M_ * 2 * D_];
__device__ __nv_bfloat16 g_Vc [(size_t)M_ * 2 * D_];
__device__ __nv_bfloat16 g_WkT[(size_t)D_ * 2 * D_];
__device__ __nv_bfloat16 g_WqT[(size_t)D_ * 2 * D_];
__device__ __nv_bfloat16 g_WvT[(size_t)D_ * 2 * D_];
__device__ __nv_bfloat16 g_Wos[(size_t)D_ * 2 * D_];
__device__ __nv_bfloat16 g_H  [(size_t)D_ * 2 * D_];   // (Wk^T Wq) split
__device__ __nv_bfloat16 g_WvoB[(size_t)D_ * 2 * D_];  // (Wo Wv)[o][a] split
__device__ __nv_bfloat16 g_T  [(size_t)M_ * 2 * D_];   // T = query * G
__device__ float         g_Zf [(size_t)M_ * D_];       // Z = value * Wvo^T
__device__ __nv_bfloat16 g_Zt [(size_t)B_ * D_ * 2 * S_]; // Z^T split
__device__ float         g_P  [(size_t)B_ * S_ * S_];
__device__ __nv_bfloat16 g_Pbf[(size_t)B_ * S_ * 2 * S_];
__device__ float         g_w2p[16][D_];                // w2 partials
__device__ float         g_w2 [D_];
__device__ float         g_cb [D_];
__device__ float         g_vb [(size_t)B_ * S_];

// ---------------------------------------------------------------------------
// Portable PTX helpers
// ---------------------------------------------------------------------------
__device__ __forceinline__ uint32_t smem_u32(const void* p) {
    uint32_t a;
    asm("{ .reg .u64 t; cvta.to.shared.u64 t, %1; cvt.u32.u64 %0, t; }" : "=r"(a) : "l"(p));
    return a;
}

__device__ __forceinline__ void ldsm4(uint32_t* r, uint32_t a) {
    asm volatile("ldmatrix.sync.aligned.m8n8.x4.shared.b16 {%0,%1,%2,%3}, [%4];"
                 : "=r"(r[0]), "=r"(r[1]), "=r"(r[2]), "=r"(r[3]) : "r"(a));
}

__device__ __forceinline__ void mma16816(float* d, const uint32_t* a, const uint32_t* b) {
    asm volatile(
        "mma.sync.aligned.m16n8k16.row.col.f32.bf16.bf16.f32 "
        "{%0,%1,%2,%3}, {%4,%5,%6,%7}, {%8,%9}, {%0,%1,%2,%3};"
        : "+f"(d[0]), "+f"(d[1]), "+f"(d[2]), "+f"(d[3])
        : "r"(a[0]), "r"(a[1]), "r"(a[2]), "r"(a[3]), "r"(b[0]), "r"(b[1]));
}

__device__ __forceinline__ void cp16(uint32_t saddr, const void* gaddr) {
    asm volatile("cp.async.cg.shared.global [%0], [%1], 16;" :: "r"(saddr), "l"(gaddr));
}
__device__ __forceinline__ void cp_commit() {
    asm volatile("cp.async.commit_group;" ::: "memory");
}
template<int N>
__device__ __forceinline__ void cp_wait() {
    asm volatile("cp.async.wait_group %0;" :: "n"(N) : "memory");
}

__device__ __forceinline__ float neg_inf_f() { return __int_as_float(0xff800000); }

__device__ __forceinline__ uint32_t pack_bf2(float a, float b) {
    __nv_bfloat162 h = __floats2bfloat162_rn(a, b);
    return *reinterpret_cast<uint32_t*>(&h);
}

// ---------------------------------------------------------------------------
// Fused split GEMM (R10 engine). CTA 256x128, 256 threads, warp tile 64x64.
// acc = Alo*Bhi + Ahi*Bhi + Ahi*Blo. k-chunk 64, 2-stage cp.async.
// EPI: 0 = fp32 out (+bias), 1 = split-bf16 out, 4 = scores (cbias+mask+scale)
// ---------------------------------------------------------------------------
struct GArgs {
    const __nv_bfloat16* A; const __nv_bfloat16* B;
    long lda, ldb, bsA, bsB;
    long oAlo, oBlo;
    int  Kpart;
    float scale;
    const float* bias;
    const float* cbias;
    float* outF;
    __nv_bfloat16* outH;
    long ldo, bsO, loOff;
};

static constexpr int A_TILE = 32768;
static constexpr int B_TILE = 16384;
static constexpr int STAGE  = 2 * A_TILE + 2 * B_TILE;  // 96 KB
static constexpr int GEMM_SMEM = 1024 + 2 * STAGE;      // 193 KB

template<int EPI, bool CAUSALK, bool TRIL>
__device__ __forceinline__ void gemm_body(const GArgs& g, int nt, int mt, int bz)
{
    if (TRIL && nt * 128 > mt * 256 + 255) return;
    const int mBase = mt * 256, nBase = nt * 128;

    extern __shared__ char smem_raw[];
    const uint32_t sbase = smem_u32(smem_raw);
    const uint32_t abase = (sbase + 1023) & ~1023u;

    const int tid  = threadIdx.x;
    const int lane = tid & 31;
    const int warp = tid >> 5;
    const int wm   = warp >> 1;
    const int wn   = warp & 1;

    const __nv_bfloat16* Ab = g.A + (long)bz * g.bsA;
    const __nv_bfloat16* Bb = g.B + (long)bz * g.bsB;

    const int kEff = CAUSALK ? (mBase + 256) : g.Kpart;
    const int nch  = kEff >> 6;

    auto issue_chunk = [&](int c) {
        const long kc = (long)(c << 6);
        const int st = c & 1;
        const uint32_t sAhi = abase + st * STAGE;
        const uint32_t sAlo = sAhi + A_TILE;
        const uint32_t sBhi = sAhi + 2 * A_TILE;
        const uint32_t sBlo = sBhi + B_TILE;
#pragma unroll
        for (int i = 0; i < 8; i++) {
            const int id = tid + i * 256;
            const int row = id >> 3, cc = id & 7;
            const uint32_t so = (uint32_t)(row << 7) + (uint32_t)((cc ^ (row & 7)) << 4);
            const __nv_bfloat16* src = Ab + (long)(mBase + row) * g.lda + kc + cc * 8;
            cp16(sAhi + so, src);
            cp16(sAlo + so, src + g.oAlo);
        }
#pragma unroll
        for (int i = 0; i < 4; i++) {
            const int id = tid + i * 256;
            const int row = id >> 3, cc = id & 7;
            const uint32_t so = (uint32_t)(row << 7) + (uint32_t)((cc ^ (row & 7)) << 4);
            const __nv_bfloat16* src = Bb + (long)(nBase + row) * g.ldb + kc + cc * 8;
            cp16(sBhi + so, src);
            cp16(sBlo + so, src + g.oBlo);
        }
        cp_commit();
    };

    float acc[4][8][4];
#pragma unroll
    for (int i = 0; i < 4; i++)
#pragma unroll
        for (int j = 0; j < 8; j++)
#pragma unroll
            for (int d = 0; d < 4; d++) acc[i][j][d] = 0.0f;

    issue_chunk(0);

    const int arow = (lane & 7) + ((lane >> 3) & 1) * 8;
    const int acol = lane >> 4;
    const int brow = (lane & 7) + ((lane >> 4) & 1) * 8;
    const int bcol = (lane >> 3) & 1;

    for (int c = 0; c < nch; c++) {
        if (c + 1 < nch) issue_chunk(c + 1);
        if (c + 1 < nch) cp_wait<1>(); else cp_wait<0>();
        __syncthreads();

        const int st = c & 1;
        const uint32_t sAhi = abase + st * STAGE;
        const uint32_t sAlo = sAhi + A_TILE;
        const uint32_t sBhi = sAhi + 2 * A_TILE;
        const uint32_t sBlo = sBhi + B_TILE;

#pragma unroll
        for (int ks = 0; ks < 4; ks++) {
            uint32_t af[4][4], bf[4][4];
            // pass 1: Alo x Bhi
#pragma unroll
            for (int mi = 0; mi < 4; mi++) {
                const int row = wm * 64 + mi * 16 + arow;
                const int cc  = ks * 2 + acol;
                ldsm4(af[mi], sAlo + (row << 7) + ((cc ^ (row & 7)) << 4));
            }
#pragma unroll
            for (int nj = 0; nj < 4; nj++) {
                const int row = wn * 64 + nj * 16 + brow;
                const int cc  = ks * 2 + bcol;
                ldsm4(bf[nj], sBhi + (row << 7) + ((cc ^ (row & 7)) << 4));
            }
#pragma unroll
            for (int mi = 0; mi < 4; mi++)
#pragma unroll
                for (int nj = 0; nj < 4; nj++) {
                    mma16816(acc[mi][2 * nj],     af[mi], &bf[nj][0]);
                    mma16816(acc[mi][2 * nj + 1], af[mi], &bf[nj][2]);
                }
            // pass 2: Ahi x Bhi
#pragma unroll
            for (int mi = 0; mi < 4; mi++) {
                const int row = wm * 64 + mi * 16 + arow;
                const int cc  = ks * 2 + acol;
                ldsm4(af[mi], sAhi + (row << 7) + ((cc ^ (row & 7)) << 4));
            }
#pragma unroll
            for (int mi = 0; mi < 4; mi++)
#pragma unroll
                for (int nj = 0; nj < 4; nj++) {
                    mma16816(acc[mi][2 * nj],     af[mi], &bf[nj][0]);
                    mma16816(acc[mi][2 * nj + 1], af[mi], &bf[nj][2]);
                }
            // pass 3: Ahi x Blo
#pragma unroll
            for (int nj = 0; nj < 4; nj++) {
                const int row = wn * 64 + nj * 16 + brow;
                const int cc  = ks * 2 + bcol;
                ldsm4(bf[nj], sBlo + (row << 7) + ((cc ^ (row & 7)) << 4));
            }
#pragma unroll
            for (int mi = 0; mi < 4; mi++)
#pragma unroll
                for (int nj = 0; nj < 4; nj++) {
                    mma16816(acc[mi][2 * nj],     af[mi], &bf[nj][0]);
                    mma16816(acc[mi][2 * nj + 1], af[mi], &bf[nj][2]);
                }
        }
        __syncthreads();
    }

    // ------------------------- epilogue (compile-time EPI) -------------------
    const int gq = lane >> 2, tg = lane & 3;
#pragma unroll
    for (int mi = 0; mi < 4; mi++) {
#pragma unroll
        for (int half = 0; half < 2; half++) {
            const int gm = mBase + wm * 64 + mi * 16 + gq + half * 8;
#pragma unroll
            for (int ni = 0; ni < 8; ni++) {
                const int gn = nBase + wn * 64 + ni * 8 + 2 * tg;
                const float v0 = acc[mi][ni][half * 2 + 0];
                const float v1 = acc[mi][ni][half * 2 + 1];

                if (EPI == 0) {
                    float2 v;
                    v.x = v0; v.y = v1;
                    if (g.bias) { v.x += g.bias[gn + 0]; v.y += g.bias[gn + 1]; }
                    *reinterpret_cast<float2*>(
                        g.outF + (long)bz * g.bsO + (long)gm * g.ldo + gn) = v;
                } else if (EPI == 1) {
                    const __nv_bfloat16 h0 = __float2bfloat16(v0);
                    const __nv_bfloat16 h1 = __float2bfloat16(v1);
                    const __nv_bfloat16 l0 = __float2bfloat16(v0 - __bfloat162float(h0));
                    const __nv_bfloat16 l1 = __float2bfloat16(v1 - __bfloat162float(h1));
                    __nv_bfloat16* o = g.outH + (long)bz * g.bsO + (long)gm * g.ldo + gn;
                    *reinterpret_cast<__nv_bfloat162*>(o) = __nv_bfloat162(h0, h1);
                    *reinterpret_cast<__nv_bfloat162*>(o + g.loOff) = __nv_bfloat162(l0, l1);
                } else {  // EPI == 4 : scores
                    const float cb0 = g.cbias[(long)bz * S_ + gn + 0];
                    const float cb1 = g.cbias[(long)bz * S_ + gn + 1];
                    float2 v;
                    v.x = (gn + 0 > gm) ? neg_inf_f() : (v0 + cb0) * g.scale;
                    v.y = (gn + 1 > gm) ? neg_inf_f() : (v1 + cb1) * g.scale;
                    *reinterpret_cast<float2*>(
                        g.outF + (long)bz * g.bsO + (long)gm * g.ldo + gn) = v;
                }
            }
        }
    }
}

template<int EPI, bool CAUSALK, bool TRIL>
__global__ void __launch_bounds__(256, 1) gemm_one(GArgs g)
{
    gemm_body<EPI, CAUSALK, TRIL>(g, blockIdx.x, gridDim.y - 1 - blockIdx.y, blockIdx.z);
}

template<int E0, int E1>
__global__ void __launch_bounds__(256, 1) gemm_dual(GArgs g0, GArgs g1)
{
    if (blockIdx.z == 0)
        gemm_body<E0, false, false>(g0, blockIdx.x, blockIdx.y, 0);
    else
        gemm_body<E1, false, false>(g1, blockIdx.x, blockIdx.y, 0);
}

// ---------------------------------------------------------------------------
// Merged q/k/v fp32 -> split bf16 [m][2*1024]; 4 float4s per thread (MLP=4)
// ---------------------------------------------------------------------------
__global__ void conv_split_in(const float* __restrict__ q, const float* __restrict__ k,
                              const float* __restrict__ v,
                              __nv_bfloat16* __restrict__ Qc, __nv_bfloat16* __restrict__ Kc,
                              __nv_bfloat16* __restrict__ Vc)
{
    const float* in = (blockIdx.z == 0) ? q : (blockIdx.z == 1) ? k : v;
    __nv_bfloat16* out = (blockIdx.z == 0) ? Qc : (blockIdx.z == 1) ? Kc : Vc;
    const long base = (long)blockIdx.x * 1024 + threadIdx.x;

    float4 v4[4];
#pragma unroll
    for (int j = 0; j < 4; j++)
        v4[j] = reinterpret_cast<const float4*>(in)[base + j * 256];

#pragma unroll
    for (int j = 0; j < 4; j++) {
        const long idx = (base + j * 256) * 4;
        const long m = idx >> 10;
        const int  kk = (int)(idx & 1023);
        const __nv_bfloat16 h0 = __float2bfloat16(v4[j].x);
        const __nv_bfloat16 h1 = __float2bfloat16(v4[j].y);
        const __nv_bfloat16 h2 = __float2bfloat16(v4[j].z);
        const __nv_bfloat16 h3 = __float2bfloat16(v4[j].w);
        uint2 hp, lp;
        hp.x = pack_bf2(v4[j].x, v4[j].y);
        hp.y = pack_bf2(v4[j].z, v4[j].w);
        lp.x = pack_bf2(v4[j].x - __bfloat162float(h0), v4[j].y - __bfloat162float(h1));
        lp.y = pack_bf2(v4[j].z - __bfloat162float(h2), v4[j].w - __bfloat162float(h3));
        __nv_bfloat16* o = out + m * 2048 + kk;
        *reinterpret_cast<uint2*>(o)        = hp;
        *reinterpret_cast<uint2*>(o + 1024) = lp;
    }
}

// ---------------------------------------------------------------------------
// Weight fp32 -> split bf16 (row-major)
// ---------------------------------------------------------------------------
__global__ void conv_split_k1024(const float* __restrict__ in,
                                 __nv_bfloat16* __restrict__ out, long n4)
{
    const long i = (long)blockIdx.x * 256 + threadIdx.x;
    if (i >= n4) return;
    const float4 v = reinterpret_cast<const float4*>(in)[i];
    const long idx = i * 4;
    const long m = idx >> 10;
    const int  k = (int)(idx & 1023);
    const __nv_bfloat16 h0 = __float2bfloat16(v.x);
    const __nv_bfloat16 h1 = __float2bfloat16(v.y);
    const __nv_bfloat16 h2 = __float2bfloat16(v.z);
    const __nv_bfloat16 h3 = __float2bfloat16(v.w);
    uint2 hp, lp;
    hp.x = pack_bf2(v.x, v.y);
    hp.y = pack_bf2(v.z, v.w);
    lp.x = pack_bf2(v.x - __bfloat162float(h0), v.y - __bfloat162float(h1));
    lp.y = pack_bf2(v.z - __bfloat162float(h2), v.w - __bfloat162float(h3));
    __nv_bfloat16* o = out + m * 2048 + k;
    *reinterpret_cast<uint2*>(o)        = hp;
    *reinterpret_cast<uint2*>(o + 1024) = lp;
}

// ---------------------------------------------------------------------------
// 3 weight transposes merged: z picks (Wk->WkT, Wq->WqT, Wv->WvT)
// ---------------------------------------------------------------------------
__global__ void transpose_split_w3(const float* __restrict__ Wk, const float* __restrict__ Wq,
                                   const float* __restrict__ Wv,
                                   __nv_bfloat16* __restrict__ WkT, __nv_bfloat16* __restrict__ WqT,
                                   __nv_bfloat16* __restrict__ WvT)
{
    const float* W = (blockIdx.z == 0) ? Wk : (blockIdx.z == 1) ? Wq : Wv;
    __nv_bfloat16* out = (blockIdx.z == 0) ? WkT : (blockIdx.z == 1) ? WqT : WvT;

    __shared__ float t[32][33];
    const int a0 = blockIdx.x * 32, e0 = blockIdx.y * 32;
    const int tx = threadIdx.x, ty = threadIdx.y;
#pragma unroll
    for (int r = 0; r < 32; r += 8)
        t[r + ty][tx] = W[(long)(e0 + r + ty) * D_ + a0 + tx];
    __syncthreads();
#pragma unroll
    for (int r = 0; r < 32; r += 8) {
        const int a = a0 + r + ty, e = e0 + tx;
        const float v = t[tx][r + ty];
        const __nv_bfloat16 h = __float2bfloat16(v);
        __nv_bfloat16* o = out + (long)a * 2 * D_ + e;
        o[0]  = h;
        o[D_] = __float2bfloat16(v - __bfloat162float(h));
    }
}

// ---------------------------------------------------------------------------
// Z fp32 [s*B+b][d] -> Zt split [b][d][hi(S)|lo(S)], packed uint32 stores.
// ---------------------------------------------------------------------------
__global__ void transpose_split_v(const float* __restrict__ Vf,
                                  __nv_bfloat16* __restrict__ Vt)
{
    __shared__ float t[64][33];
    const int d0 = blockIdx.x * 32, s0 = blockIdx.y * 64, b = blockIdx.z;
    const int tx = threadIdx.x, ty = threadIdx.y;
#pragma unroll
    for (int j = 0; j < 8; j++) {
        const int sl = j * 8 + ty;
        t[sl][tx] = Vf[((size_t)(s0 + sl) * B_ + b) * D_ + d0 + tx];
    }
    __syncthreads();
#pragma unroll
    for (int jj = 0; jj < 4; jj++) {
        const int dl = jj * 8 + ty;
        const float va = t[2 * tx][dl];
        const float vb = t[2 * tx + 1][dl];
        const __nv_bfloat16 ha = __float2bfloat16(va);
        const __nv_bfloat16 hb = __float2bfloat16(vb);
        __nv_bfloat16* o = Vt + ((size_t)b * D_ + d0 + dl) * (2 * S_) + s0 + 2 * tx;
        *reinterpret_cast<uint32_t*>(o) = pack_bf2(va, vb);
        *reinterpret_cast<uint32_t*>(o + S_) =
            pack_bf2(va - __bfloat162float(ha), vb - __bfloat162float(hb));
    }
}

// ---------------------------------------------------------------------------
// w2 = Wk^T * bq, two-phase parallel reduction.
// Phase 1: grid (4, 16); block (a-group, d-slice) sums 64 rows, coalesced.
// Phase 2: combine 16 partials per column.
// ---------------------------------------------------------------------------
__global__ void w2_partial(const float* __restrict__ Wk, const float* __restrict__ bq,
                           float* __restrict__ w2p)
{
    const int a = blockIdx.x * 256 + threadIdx.x;
    const int d0 = blockIdx.y * 64;
    float s = 0.0f;
#pragma unroll 4
    for (int d = d0; d < d0 + 64; d++)
        s += bq[d] * Wk[(long)d * D_ + a];
    w2p[blockIdx.y * D_ + a] = s;
}

__global__ void w2_combine(const float* __restrict__ w2p, float* __restrict__ w2)
{
    const int a = blockIdx.x * 256 + threadIdx.x;
    float s = 0.0f;
#pragma unroll
    for (int i = 0; i < 16; i++) s += w2p[i * D_ + a];
    w2[a] = s;
}

__global__ void cb_kernel(const float* __restrict__ Wo, const float* __restrict__ bv,
                          const float* __restrict__ bo, float* __restrict__ cb)
{
    const int o = blockIdx.x * 8 + (threadIdx.x >> 5);
    const int lane = threadIdx.x & 31;
    float s = 0.0f;
    for (int e = lane * 4; e < D_; e += 128) {
        const float4 w = *reinterpret_cast<const float4*>(Wo + (long)o * D_ + e);
        const float4 b = *reinterpret_cast<const float4*>(bv + e);
        s += w.x * b.x + w.y * b.y + w.z * b.z + w.w * b.w;
    }
#pragma unroll
    for (int off = 16; off > 0; off >>= 1) s += __shfl_xor_sync(0xffffffffu, s, off);
    if (lane == 0) cb[o] = bo[o] + s;
}

__global__ void vb_kernel(const float* __restrict__ key, const float* __restrict__ w2,
                          float* __restrict__ vb)
{
    const int m = blockIdx.x * 8 + (threadIdx.x >> 5);
    const int lane = threadIdx.x & 31;
    const float* row = key + (long)m * D_;
    float s = 0.0f;
    for (int a = lane * 4; a < D_; a += 128) {
        const float4 k = *reinterpret_cast<const float4*>(row + a);
        const float4 w = *reinterpret_cast<const float4*>(w2 + a);
        s += k.x * w.x + k.y * w.y + k.z * w.z + k.w * w.w;
    }
#pragma unroll
    for (int off = 16; off > 0; off >>= 1) s += __shfl_xor_sync(0xffffffffu, s, off);
    if (lane == 0) {
        const int b = m & (B_ - 1);
        const int j = m >> 3;
        vb[(long)b * S_ + j] = s;
    }
}

// ---------------------------------------------------------------------------
// Fused row softmax + split-bf16 emit (fast exp, float4 strides)
// ---------------------------------------------------------------------------
__global__ void __launch_bounds__(256) softmax_split(const float* __restrict__ P,
                                                     __nv_bfloat16* __restrict__ Pb)
{
    const int i = blockIdx.x, b = blockIdx.y;
    const float* p = P + ((size_t)b * S_ + i) * S_;
    __nv_bfloat16* o = Pb + ((size_t)b * S_ + i) * (2 * S_);
    const int jEnd = ((i >> 7) + 1) << 7;
    const int tid = threadIdx.x;
    __shared__ float sm[8];

    float m = neg_inf_f();
    for (int j = tid * 4; j < jEnd; j += 1024) {
        const float4 v = *reinterpret_cast<const float4*>(p + j);
        m = fmaxf(m, fmaxf(fmaxf(v.x, v.y), fmaxf(v.z, v.w)));
    }
#pragma unroll
    for (int off = 16; off > 0; off >>= 1) m = fmaxf(m, __shfl_xor_sync(0xffffffffu, m, off));
    if ((tid & 31) == 0) sm[tid >> 5] = m;
    __syncthreads();
    const float rowmax = fmaxf(fmaxf(fmaxf(sm[0], sm[1]), fmaxf(sm[2], sm[3])),
                               fmaxf(fmaxf(sm[4], sm[5]), fmaxf(sm[6], sm[7])));
    __syncthreads();

    float s = 0.0f;
    for (int j = tid * 4; j < jEnd; j += 1024) {
        const float4 v = *reinterpret_cast<const float4*>(p + j);
        s += __expf(v.x - rowmax) + __expf(v.y - rowmax)
           + __expf(v.z - rowmax) + __expf(v.w - rowmax);
    }
#pragma unroll
    for (int off = 16; off > 0; off >>= 1) s += __shfl_xor_sync(0xffffffffu, s, off);
    if ((tid & 31) == 0) sm[tid >> 5] = s;
    __syncthreads();
    const float inv = 1.0f / ((sm[0] + sm[1]) + (sm[2] + sm[3]) + (sm[4] + sm[5]) + (sm[6] + sm[7]));

    for (int j = tid * 4; j < jEnd; j += 1024) {
        const float4 v = *reinterpret_cast<const float4*>(p + j);
        const float e0 = __expf(v.x - rowmax) * inv;
        const float e1 = __expf(v.y - rowmax) * inv;
        const float e2 = __expf(v.z - rowmax) * inv;
        const float e3 = __expf(v.w - rowmax) * inv;
        const __nv_bfloat16 h0 = __float2bfloat16(e0);
        const __nv_bfloat16 h1 = __float2bfloat16(e1);
        const __nv_bfloat16 h2 = __float2bfloat16(e2);
        const __nv_bfloat16 h3 = __float2bfloat16(e3);
        uint2 hp, lp;
        hp.x = pack_bf2(e0, e1); hp.y = pack_bf2(e2, e3);
        lp.x = pack_bf2(e0 - __bfloat162float(h0), e1 - __bfloat162float(h1));
        lp.y = pack_bf2(e2 - __bfloat162float(h2), e3 - __bfloat162float(h3));
        *reinterpret_cast<uint2*>(o + j)      = hp;
        *reinterpret_cast<uint2*>(o + S_ + j) = lp;
    }
}

// ---------------------------------------------------------------------------
extern "C" void kernel_launch(void* const* d_in, const int* in_sizes, int n_in,
                              void* d_out, int out_size)
{
    const float* query = (const float*)d_in[0];
    const float* key   = (const float*)d_in[1];
    const float* value = (const float*)d_in[2];
    const float* Wq = (const float*)d_in[4];
    const float* bq = (const float*)d_in[5];
    const float* Wk = (const float*)d_in[6];
    // d_in[7] = bk : softmax-invariant, dropped exactly
    const float* Wv = (const float*)d_in[8];
    const float* bv = (const float*)d_in[9];
    const float* Wo = (const float*)d_in[10];
    const float* bo = (const float*)d_in[11];
    float* out = (float*)d_out;

    __nv_bfloat16 *Qc, *Kc, *Vc, *WkT, *WqT, *WvT, *Wos, *H, *WvoB, *T, *Zt, *Pbf;
    float *Zf, *P, *w2p, *w2, *cb, *vb;
    cudaGetSymbolAddress((void**)&Qc,  g_Qc);
    cudaGetSymbolAddress((void**)&Kc,  g_Kc);
    cudaGetSymbolAddress((void**)&Vc,  g_Vc);
    cudaGetSymbolAddress((void**)&WkT, g_WkT);
    cudaGetSymbolAddress((void**)&WqT, g_WqT);
    cudaGetSymbolAddress((void**)&WvT, g_WvT);
    cudaGetSymbolAddress((void**)&Wos, g_Wos);
    cudaGetSymbolAddress((void**)&H,   g_H);
    cudaGetSymbolAddress((void**)&WvoB,g_WvoB);
    cudaGetSymbolAddress((void**)&T,   g_T);
    cudaGetSymbolAddress((void**)&Zf,  g_Zf);
    cudaGetSymbolAddress((void**)&Zt,  g_Zt);
    cudaGetSymbolAddress((void**)&P,   g_P);
    cudaGetSymbolAddress((void**)&Pbf, g_Pbf);
    cudaGetSymbolAddress((void**)&w2p, g_w2p);
    cudaGetSymbolAddress((void**)&w2,  g_w2);
    cudaGetSymbolAddress((void**)&cb,  g_cb);
    cudaGetSymbolAddress((void**)&vb,  g_vb);

    cudaFuncSetAttribute(gemm_dual<1, 1>,
                         cudaFuncAttributeMaxDynamicSharedMemorySize, GEMM_SMEM);
    cudaFuncSetAttribute(gemm_dual<1, 0>,
                         cudaFuncAttributeMaxDynamicSharedMemorySize, GEMM_SMEM);
    cudaFuncSetAttribute(gemm_one<4, false, true>,
                         cudaFuncAttributeMaxDynamicSharedMemorySize, GEMM_SMEM);
    cudaFuncSetAttribute(gemm_one<0, true, false>,
                         cudaFuncAttributeMaxDynamicSharedMemorySize, GEMM_SMEM);

    const long n4w = (long)D_ * D_ / 4;
    const long n4i = (long)M_ * D_ / 4;

    // ---- conversions ----
    conv_split_in<<<dim3((unsigned)(n4i / 1024), 1, 3), 256>>>(query, key, value, Qc, Kc, Vc);
    conv_split_k1024<<<(unsigned)((n4w + 255) / 256), 256>>>(Wo, Wos, n4w);
    transpose_split_w3<<<dim3(D_ / 32, D_ / 32, 3), dim3(32, 8)>>>(Wk, Wq, Wv, WkT, WqT, WvT);

    // ---- exact bias terms (parallel w2) ----
    w2_partial<<<dim3(D_ / 256, 16), 256>>>(Wk, bq, w2p);
    w2_combine<<<D_ / 256, 256>>>(w2p, w2);
    cb_kernel<<<D_ / 8, 256>>>(Wo, bv, bo, cb);
    vb_kernel<<<M_ / 8, 256>>>(key, w2, vb);

    // ---- H = Wk^T Wq  and  WvoB = (Wo Wv)[o][a], one dual launch ----
    GArgs hA{};
    hA.A = WkT; hA.lda = 2 * D_; hA.bsA = 0; hA.oAlo = D_;
    hA.B = WqT; hA.ldb = 2 * D_; hA.bsB = 0; hA.oBlo = D_;
    hA.Kpart = D_; hA.scale = 1.0f; hA.bias = nullptr; hA.cbias = nullptr;
    hA.outH = H; hA.ldo = 2 * D_; hA.bsO = 0; hA.loOff = D_;
    GArgs hB = hA;
    hB.A = Wos; hB.B = WvT; hB.outH = WvoB;
    gemm_dual<1, 1><<<dim3(D_ / 128, D_ / 256, 2), 256, GEMM_SMEM>>>(hA, hB);

    // ---- T = query * G (split out)  and  Z = value * Wvo^T (fp32 out), dual ----
    GArgs tA{};
    tA.A = Qc; tA.lda = 2 * D_; tA.bsA = 0; tA.oAlo = D_;
    tA.B = H;  tA.ldb = 2 * D_; tA.bsB = 0; tA.oBlo = D_;
    tA.Kpart = D_; tA.scale = 1.0f; tA.bias = nullptr; tA.cbias = nullptr;
    tA.outH = T; tA.ldo = 2 * D_; tA.bsO = 0; tA.loOff = D_;
    GArgs tB{};
    tB.A = Vc; tB.lda = 2 * D_; tB.bsA = 0; tB.oAlo = D_;
    tB.B = WvoB; tB.ldb = 2 * D_; tB.bsB = 0; tB.oBlo = D_;
    tB.Kpart = D_; tB.scale = 1.0f; tB.bias = nullptr; tB.cbias = nullptr;
    tB.outF = Zf; tB.ldo = D_; tB.bsO = 0;
    gemm_dual<1, 0><<<dim3(D_ / 128, M_ / 256, 2), 256, GEMM_SMEM>>>(tA, tB);

    // ---- Z^T split for the PV GEMM ----
    transpose_split_v<<<dim3(D_ / 32, S_ / 64, B_), dim3(32, 8)>>>(Zf, Zt);

    // ---- Scores: P = SCALE * (T . key^T + vb), tril tiles, causal mask ----
    GArgs sc{};
    sc.A = T;  sc.lda = (long)B_ * 2 * D_; sc.bsA = 2 * D_; sc.oAlo = D_;
    sc.B = Kc; sc.ldb = (long)B_ * 2 * D_; sc.bsB = 2 * D_; sc.oBlo = D_;
    sc.Kpart = D_; sc.scale = SCALE_; sc.bias = nullptr; sc.cbias = vb;
    sc.outF = P; sc.ldo = S_; sc.bsO = (long)S_ * S_;
    gemm_one<4, false, true><<<dim3(S_ / 128, S_ / 256, B_), 256, GEMM_SMEM>>>(sc);

    // ---- fused softmax + P split ----
    softmax_split<<<dim3(S_, B_), 256>>>(P, Pbf);

    // ---- out = P @ Z + cb (causal K bound), fp32 straight to d_out ----
    GArgs pv{};
    pv.A = Pbf; pv.lda = 2 * S_; pv.bsA = (long)S_ * 2 * S_; pv.oAlo = S_;
    pv.B = Zt;  pv.ldb = 2 * S_; pv.bsB = (long)D_ * 2 * S_; pv.oBlo = S_;
    pv.Kpart = S_; pv.scale = 1.0f; pv.bias = cb; pv.cbias = nullptr;
    pv.outF = out; pv.ldo = (long)B_ * D_; pv.bsO = D_;
    gemm_one<0, true, false><<<dim3(D_ / 128, S_ / 256, B_), 256, GEMM_SMEM>>>(pv);
}

// round 14
// speedup vs baseline: 1.3697x; 1.0136x over previous
#include <cuda_runtime.h>
#include <cuda_bf16.h>
#include <cstdint>
#include <math.h>

// ---------------------------------------------------------------------------
// Problem constants
// ---------------------------------------------------------------------------
static constexpr int S_ = 2048, B_ = 8, D_ = 1024, M_ = S_ * B_;
static constexpr float SCALE_ = 0.03125f;  // 1/sqrt(1024)

// ---------------------------------------------------------------------------
// Static scratch. Split-bf16 layout: row-major [rows][2*K]: hi at [k], lo at [K+k].
// ---------------------------------------------------------------------------
__device__ __nv_bfloat16 g_Qc [(size_t)M_ * 2 * D_];
__device__ __nv_bfloat16 g_Kc [(size_t)M_ * 2 * D_];
__device__ __nv_bfloat16 g_Vc [(size_t)M_ * 2 * D_];
__device__ __nv_bfloat16 g_WkT[(size_t)D_ * 2 * D_];
__device__ __nv_bfloat16 g_WqT[(size_t)D_ * 2 * D_];
__device__ __nv_bfloat16 g_WvT[(size_t)D_ * 2 * D_];
__device__ __nv_bfloat16 g_Wos[(size_t)D_ * 2 * D_];
__device__ __nv_bfloat16 g_H  [(size_t)D_ * 2 * D_];   // (Wk^T Wq) split
__device__ __nv_bfloat16 g_WvoB[(size_t)D_ * 2 * D_];  // (Wo Wv)[o][a] split
__device__ __nv_bfloat16 g_T  [(size_t)M_ * 2 * D_];   // T = query * G
__device__ float         g_Zf [(size_t)M_ * D_];       // Z = value * Wvo^T
__device__ __nv_bfloat16 g_Zt [(size_t)B_ * D_ * 2 * S_]; // Z^T split
__device__ float         g_P  [(size_t)B_ * S_ * S_];
__device__ __nv_bfloat16 g_Pbf[(size_t)B_ * S_ * 2 * S_];
__device__ float         g_w2p[16][D_];                // w2 partials
__device__ float         g_w2 [D_];
__device__ float         g_cb [D_];
__device__ float         g_vb [(size_t)B_ * S_];

// ---------------------------------------------------------------------------
// Portable PTX helpers
// ---------------------------------------------------------------------------
__device__ __forceinline__ uint32_t smem_u32(const void* p) {
    uint32_t a;
    asm("{ .reg .u64 t; cvta.to.shared.u64 t, %1; cvt.u32.u64 %0, t; }" : "=r"(a) : "l"(p));
    return a;
}

__device__ __forceinline__ void ldsm4(uint32_t* r, uint32_t a) {
    asm volatile("ldmatrix.sync.aligned.m8n8.x4.shared.b16 {%0,%1,%2,%3}, [%4];"
                 : "=r"(r[0]), "=r"(r[1]), "=r"(r[2]), "=r"(r[3]) : "r"(a));
}

__device__ __forceinline__ void mma16816(float* d, const uint32_t* a, const uint32_t* b) {
    asm volatile(
        "mma.sync.aligned.m16n8k16.row.col.f32.bf16.bf16.f32 "
        "{%0,%1,%2,%3}, {%4,%5,%6,%7}, {%8,%9}, {%0,%1,%2,%3};"
        : "+f"(d[0]), "+f"(d[1]), "+f"(d[2]), "+f"(d[3])
        : "r"(a[0]), "r"(a[1]), "r"(a[2]), "r"(a[3]), "r"(b[0]), "r"(b[1]));
}

__device__ __forceinline__ void cp16(uint32_t saddr, const void* gaddr) {
    asm volatile("cp.async.cg.shared.global [%0], [%1], 16;" :: "r"(saddr), "l"(gaddr));
}
__device__ __forceinline__ void cp_commit() {
    asm volatile("cp.async.commit_group;" ::: "memory");
}
template<int N>
__device__ __forceinline__ void cp_wait() {
    asm volatile("cp.async.wait_group %0;" :: "n"(N) : "memory");
}

__device__ __forceinline__ float neg_inf_f() { return __int_as_float(0xff800000); }

__device__ __forceinline__ uint32_t pack_bf2(float a, float b) {
    __nv_bfloat162 h = __floats2bfloat162_rn(a, b);
    return *reinterpret_cast<uint32_t*>(&h);
}

// ---------------------------------------------------------------------------
// Fused split GEMM (R10/R13 engine). CTA 256x128, 256 threads, warp tile 64x64.
// acc = Alo*Bhi + Ahi*Bhi + Ahi*Blo. k-chunk 64, 2-stage cp.async.
// EPI: 0 = fp32 out (+bias), 1 = split-bf16 out, 4 = scores (cbias+mask+scale)
// ---------------------------------------------------------------------------
struct GArgs {
    const __nv_bfloat16* A; const __nv_bfloat16* B;
    long lda, ldb, bsA, bsB;
    long oAlo, oBlo;
    int  Kpart;
    float scale;
    const float* bias;
    const float* cbias;
    float* outF;
    __nv_bfloat16* outH;
    long ldo, bsO, loOff;
};

static constexpr int A_TILE = 32768;
static constexpr int B_TILE = 16384;
static constexpr int STAGE  = 2 * A_TILE + 2 * B_TILE;  // 96 KB
static constexpr int GEMM_SMEM = 1024 + 2 * STAGE;      // 193 KB

template<int EPI, bool CAUSALK, bool TRIL>
__device__ __forceinline__ void gemm_body(const GArgs& g, int nt, int mt, int bz)
{
    if (TRIL && nt * 128 > mt * 256 + 255) return;
    const int mBase = mt * 256, nBase = nt * 128;

    extern __shared__ char smem_raw[];
    const uint32_t sbase = smem_u32(smem_raw);
    const uint32_t abase = (sbase + 1023) & ~1023u;

    const int tid  = threadIdx.x;
    const int lane = tid & 31;
    const int warp = tid >> 5;
    const int wm   = warp >> 1;
    const int wn   = warp & 1;

    const __nv_bfloat16* Ab = g.A + (long)bz * g.bsA;
    const __nv_bfloat16* Bb = g.B + (long)bz * g.bsB;

    const int kEff = CAUSALK ? (mBase + 256) : g.Kpart;
    const int nch  = kEff >> 6;

    auto issue_chunk = [&](int c) {
        const long kc = (long)(c << 6);
        const int st = c & 1;
        const uint32_t sAhi = abase + st * STAGE;
        const uint32_t sAlo = sAhi + A_TILE;
        const uint32_t sBhi = sAhi + 2 * A_TILE;
        const uint32_t sBlo = sBhi + B_TILE;
#pragma unroll
        for (int i = 0; i < 8; i++) {
            const int id = tid + i * 256;
            const int row = id >> 3, cc = id & 7;
            const uint32_t so = (uint32_t)(row << 7) + (uint32_t)((cc ^ (row & 7)) << 4);
            const __nv_bfloat16* src = Ab + (long)(mBase + row) * g.lda + kc + cc * 8;
            cp16(sAhi + so, src);
            cp16(sAlo + so, src + g.oAlo);
        }
#pragma unroll
        for (int i = 0; i < 4; i++) {
            const int id = tid + i * 256;
            const int row = id >> 3, cc = id & 7;
            const uint32_t so = (uint32_t)(row << 7) + (uint32_t)((cc ^ (row & 7)) << 4);
            const __nv_bfloat16* src = Bb + (long)(nBase + row) * g.ldb + kc + cc * 8;
            cp16(sBhi + so, src);
            cp16(sBlo + so, src + g.oBlo);
        }
        cp_commit();
    };

    float acc[4][8][4];
#pragma unroll
    for (int i = 0; i < 4; i++)
#pragma unroll
        for (int j = 0; j < 8; j++)
#pragma unroll
            for (int d = 0; d < 4; d++) acc[i][j][d] = 0.0f;

    issue_chunk(0);

    const int arow = (lane & 7) + ((lane >> 3) & 1) * 8;
    const int acol = lane >> 4;
    const int brow = (lane & 7) + ((lane >> 4) & 1) * 8;
    const int bcol = (lane >> 3) & 1;

    for (int c = 0; c < nch; c++) {
        if (c + 1 < nch) issue_chunk(c + 1);
        if (c + 1 < nch) cp_wait<1>(); else cp_wait<0>();
        __syncthreads();

        const int st = c & 1;
        const uint32_t sAhi = abase + st * STAGE;
        const uint32_t sAlo = sAhi + A_TILE;
        const uint32_t sBhi = sAhi + 2 * A_TILE;
        const uint32_t sBlo = sBhi + B_TILE;

#pragma unroll
        for (int ks = 0; ks < 4; ks++) {
            uint32_t af[4][4], bf[4][4];
            // pass 1: Alo x Bhi
#pragma unroll
            for (int mi = 0; mi < 4; mi++) {
                const int row = wm * 64 + mi * 16 + arow;
                const int cc  = ks * 2 + acol;
                ldsm4(af[mi], sAlo + (row << 7) + ((cc ^ (row & 7)) << 4));
            }
#pragma unroll
            for (int nj = 0; nj < 4; nj++) {
                const int row = wn * 64 + nj * 16 + brow;
                const int cc  = ks * 2 + bcol;
                ldsm4(bf[nj], sBhi + (row << 7) + ((cc ^ (row & 7)) << 4));
            }
#pragma unroll
            for (int mi = 0; mi < 4; mi++)
#pragma unroll
                for (int nj = 0; nj < 4; nj++) {
                    mma16816(acc[mi][2 * nj],     af[mi], &bf[nj][0]);
                    mma16816(acc[mi][2 * nj + 1], af[mi], &bf[nj][2]);
                }
            // pass 2: Ahi x Bhi
#pragma unroll
            for (int mi = 0; mi < 4; mi++) {
                const int row = wm * 64 + mi * 16 + arow;
                const int cc  = ks * 2 + acol;
                ldsm4(af[mi], sAhi + (row << 7) + ((cc ^ (row & 7)) << 4));
            }
#pragma unroll
            for (int mi = 0; mi < 4; mi++)
#pragma unroll
                for (int nj = 0; nj < 4; nj++) {
                    mma16816(acc[mi][2 * nj],     af[mi], &bf[nj][0]);
                    mma16816(acc[mi][2 * nj + 1], af[mi], &bf[nj][2]);
                }
            // pass 3: Ahi x Blo
#pragma unroll
            for (int nj = 0; nj < 4; nj++) {
                const int row = wn * 64 + nj * 16 + brow;
                const int cc  = ks * 2 + bcol;
                ldsm4(bf[nj], sBlo + (row << 7) + ((cc ^ (row & 7)) << 4));
            }
#pragma unroll
            for (int mi = 0; mi < 4; mi++)
#pragma unroll
                for (int nj = 0; nj < 4; nj++) {
                    mma16816(acc[mi][2 * nj],     af[mi], &bf[nj][0]);
                    mma16816(acc[mi][2 * nj + 1], af[mi], &bf[nj][2]);
                }
        }
        __syncthreads();
    }

    // ------------------------- epilogue (compile-time EPI) -------------------
    const int gq = lane >> 2, tg = lane & 3;
#pragma unroll
    for (int mi = 0; mi < 4; mi++) {
#pragma unroll
        for (int half = 0; half < 2; half++) {
            const int gm = mBase + wm * 64 + mi * 16 + gq + half * 8;
#pragma unroll
            for (int ni = 0; ni < 8; ni++) {
                const int gn = nBase + wn * 64 + ni * 8 + 2 * tg;
                const float v0 = acc[mi][ni][half * 2 + 0];
                const float v1 = acc[mi][ni][half * 2 + 1];

                if (EPI == 0) {
                    float2 v;
                    v.x = v0; v.y = v1;
                    if (g.bias) { v.x += g.bias[gn + 0]; v.y += g.bias[gn + 1]; }
                    *reinterpret_cast<float2*>(
                        g.outF + (long)bz * g.bsO + (long)gm * g.ldo + gn) = v;
                } else if (EPI == 1) {
                    const __nv_bfloat16 h0 = __float2bfloat16(v0);
                    const __nv_bfloat16 h1 = __float2bfloat16(v1);
                    const __nv_bfloat16 l0 = __float2bfloat16(v0 - __bfloat162float(h0));
                    const __nv_bfloat16 l1 = __float2bfloat16(v1 - __bfloat162float(h1));
                    __nv_bfloat16* o = g.outH + (long)bz * g.bsO + (long)gm * g.ldo + gn;
                    *reinterpret_cast<__nv_bfloat162*>(o) = __nv_bfloat162(h0, h1);
                    *reinterpret_cast<__nv_bfloat162*>(o + g.loOff) = __nv_bfloat162(l0, l1);
                } else {  // EPI == 4 : scores
                    const float cb0 = g.cbias[(long)bz * S_ + gn + 0];
                    const float cb1 = g.cbias[(long)bz * S_ + gn + 1];
                    float2 v;
                    v.x = (gn + 0 > gm) ? neg_inf_f() : (v0 + cb0) * g.scale;
                    v.y = (gn + 1 > gm) ? neg_inf_f() : (v1 + cb1) * g.scale;
                    *reinterpret_cast<float2*>(
                        g.outF + (long)bz * g.bsO + (long)gm * g.ldo + gn) = v;
                }
            }
        }
    }
}

template<int EPI, bool CAUSALK, bool TRIL>
__global__ void __launch_bounds__(256, 1) gemm_one(GArgs g)
{
    gemm_body<EPI, CAUSALK, TRIL>(g, blockIdx.x, gridDim.y - 1 - blockIdx.y, blockIdx.z);
}

template<int E0, int E1>
__global__ void __launch_bounds__(256, 1) gemm_dual(GArgs g0, GArgs g1)
{
    if (blockIdx.z == 0)
        gemm_body<E0, false, false>(g0, blockIdx.x, blockIdx.y, 0);
    else
        gemm_body<E1, false, false>(g1, blockIdx.x, blockIdx.y, 0);
}

// ---------------------------------------------------------------------------
// Merged prep: one launch, grid (4096, 1, 5), 256 threads.
//   z in {0,1,2}: q/k/v fp32 -> split bf16 (MLP=4)
//   z == 3     : Wo fp32 -> split bf16 (x < 1024 active)
//   z == 4     : Wk/Wq/Wv transpose+split (x < 3072 active; x>>10 picks W)
// ---------------------------------------------------------------------------
__global__ void prep_all(const float* __restrict__ q, const float* __restrict__ k,
                         const float* __restrict__ v, const float* __restrict__ Wo,
                         const float* __restrict__ Wk, const float* __restrict__ Wq,
                         const float* __restrict__ Wv,
                         __nv_bfloat16* __restrict__ Qc, __nv_bfloat16* __restrict__ Kc,
                         __nv_bfloat16* __restrict__ Vc, __nv_bfloat16* __restrict__ Wos,
                         __nv_bfloat16* __restrict__ WkT, __nv_bfloat16* __restrict__ WqT,
                         __nv_bfloat16* __restrict__ WvT)
{
    __shared__ float t[32][33];
    const int tid = threadIdx.x;
    const int z = blockIdx.z;

    if (z < 3) {
        const float* in = (z == 0) ? q : (z == 1) ? k : v;
        __nv_bfloat16* out = (z == 0) ? Qc : (z == 1) ? Kc : Vc;
        const long base = (long)blockIdx.x * 1024 + tid;

        float4 v4[4];
#pragma unroll
        for (int j = 0; j < 4; j++)
            v4[j] = reinterpret_cast<const float4*>(in)[base + j * 256];

#pragma unroll
        for (int j = 0; j < 4; j++) {
            const long idx = (base + j * 256) * 4;
            const long m = idx >> 10;
            const int  kk = (int)(idx & 1023);
            const __nv_bfloat16 h0 = __float2bfloat16(v4[j].x);
            const __nv_bfloat16 h1 = __float2bfloat16(v4[j].y);
            const __nv_bfloat16 h2 = __float2bfloat16(v4[j].z);
            const __nv_bfloat16 h3 = __float2bfloat16(v4[j].w);
            uint2 hp, lp;
            hp.x = pack_bf2(v4[j].x, v4[j].y);
            hp.y = pack_bf2(v4[j].z, v4[j].w);
            lp.x = pack_bf2(v4[j].x - __bfloat162float(h0), v4[j].y - __bfloat162float(h1));
            lp.y = pack_bf2(v4[j].z - __bfloat162float(h2), v4[j].w - __bfloat162float(h3));
            __nv_bfloat16* o = out + m * 2048 + kk;
            *reinterpret_cast<uint2*>(o)        = hp;
            *reinterpret_cast<uint2*>(o + 1024) = lp;
        }
    } else if (z == 3) {
        if (blockIdx.x >= 1024) return;
        const long i = (long)blockIdx.x * 256 + tid;
        const float4 vv = reinterpret_cast<const float4*>(Wo)[i];
        const long idx = i * 4;
        const long m = idx >> 10;
        const int  kk = (int)(idx & 1023);
        const __nv_bfloat16 h0 = __float2bfloat16(vv.x);
        const __nv_bfloat16 h1 = __float2bfloat16(vv.y);
        const __nv_bfloat16 h2 = __float2bfloat16(vv.z);
        const __nv_bfloat16 h3 = __float2bfloat16(vv.w);
        uint2 hp, lp;
        hp.x = pack_bf2(vv.x, vv.y);
        hp.y = pack_bf2(vv.z, vv.w);
        lp.x = pack_bf2(vv.x - __bfloat162float(h0), vv.y - __bfloat162float(h1));
        lp.y = pack_bf2(vv.z - __bfloat162float(h2), vv.w - __bfloat162float(h3));
        __nv_bfloat16* o = Wos + m * 2048 + kk;
        *reinterpret_cast<uint2*>(o)        = hp;
        *reinterpret_cast<uint2*>(o + 1024) = lp;
    } else {
        if (blockIdx.x >= 3072) return;
        const int which = blockIdx.x >> 10;
        const int rem = blockIdx.x & 1023;
        const float* W = (which == 0) ? Wk : (which == 1) ? Wq : Wv;
        __nv_bfloat16* out = (which == 0) ? WkT : (which == 1) ? WqT : WvT;
        const int a0 = (rem & 31) * 32, e0 = (rem >> 5) * 32;
        const int tx = tid & 31, ty = tid >> 5;
#pragma unroll
        for (int r = 0; r < 32; r += 8)
            t[r + ty][tx] = W[(long)(e0 + r + ty) * D_ + a0 + tx];
        __syncthreads();
#pragma unroll
        for (int r = 0; r < 32; r += 8) {
            const int a = a0 + r + ty, e = e0 + tx;
            const float vv = t[tx][r + ty];
            const __nv_bfloat16 h = __float2bfloat16(vv);
            __nv_bfloat16* o = out + (long)a * 2 * D_ + e;
            o[0]  = h;
            o[D_] = __float2bfloat16(vv - __bfloat162float(h));
        }
    }
}

// ---------------------------------------------------------------------------
// Z fp32 [s*B+b][d] -> Zt split [b][d][hi(S)|lo(S)], packed uint32 stores.
// ---------------------------------------------------------------------------
__global__ void transpose_split_v(const float* __restrict__ Vf,
                                  __nv_bfloat16* __restrict__ Vt)
{
    __shared__ float t[64][33];
    const int d0 = blockIdx.x * 32, s0 = blockIdx.y * 64, b = blockIdx.z;
    const int tx = threadIdx.x, ty = threadIdx.y;
#pragma unroll
    for (int j = 0; j < 8; j++) {
        const int sl = j * 8 + ty;
        t[sl][tx] = Vf[((size_t)(s0 + sl) * B_ + b) * D_ + d0 + tx];
    }
    __syncthreads();
#pragma unroll
    for (int jj = 0; jj < 4; jj++) {
        const int dl = jj * 8 + ty;
        const float va = t[2 * tx][dl];
        const float vb = t[2 * tx + 1][dl];
        const __nv_bfloat16 ha = __float2bfloat16(va);
        const __nv_bfloat16 hb = __float2bfloat16(vb);
        __nv_bfloat16* o = Vt + ((size_t)b * D_ + d0 + dl) * (2 * S_) + s0 + 2 * tx;
        *reinterpret_cast<uint32_t*>(o) = pack_bf2(va, vb);
        *reinterpret_cast<uint32_t*>(o + S_) =
            pack_bf2(va - __bfloat162float(ha), vb - __bfloat162float(hb));
    }
}

// ---------------------------------------------------------------------------
// Merged bias prep: grid (128, 1, 2).
//   z==0, x<64 : w2 partial (x&3 -> a-group, x>>2 -> d-slice)
//   z==1       : cb = bo + Wo*bv (x<128)
// ---------------------------------------------------------------------------
__global__ void bias_prep(const float* __restrict__ Wk, const float* __restrict__ bq,
                          const float* __restrict__ Wo, const float* __restrict__ bv,
                          const float* __restrict__ bo,
                          float* __restrict__ w2p, float* __restrict__ cb)
{
    if (blockIdx.z == 0) {
        if (blockIdx.x >= 64) return;
        const int a = (blockIdx.x & 3) * 256 + threadIdx.x;
        const int d0 = (blockIdx.x >> 2) * 64;
        float s = 0.0f;
#pragma unroll 4
        for (int d = d0; d < d0 + 64; d++)
            s += bq[d] * Wk[(long)d * D_ + a];
        w2p[(blockIdx.x >> 2) * D_ + a] = s;
    } else {
        const int o = blockIdx.x * 8 + (threadIdx.x >> 5);
        const int lane = threadIdx.x & 31;
        float s = 0.0f;
        for (int e = lane * 4; e < D_; e += 128) {
            const float4 w = *reinterpret_cast<const float4*>(Wo + (long)o * D_ + e);
            const float4 b = *reinterpret_cast<const float4*>(bv + e);
            s += w.x * b.x + w.y * b.y + w.z * b.z + w.w * b.w;
        }
#pragma unroll
        for (int off = 16; off > 0; off >>= 1) s += __shfl_xor_sync(0xffffffffu, s, off);
        if (lane == 0) cb[o] = bo[o] + s;
    }
}

__global__ void w2_combine(const float* __restrict__ w2p, float* __restrict__ w2)
{
    const int a = blockIdx.x * 256 + threadIdx.x;
    float s = 0.0f;
#pragma unroll
    for (int i = 0; i < 16; i++) s += w2p[i * D_ + a];
    w2[a] = s;
}

__global__ void vb_kernel(const float* __restrict__ key, const float* __restrict__ w2,
                          float* __restrict__ vb)
{
    const int m = blockIdx.x * 8 + (threadIdx.x >> 5);
    const int lane = threadIdx.x & 31;
    const float* row = key + (long)m * D_;
    float s = 0.0f;
    for (int a = lane * 4; a < D_; a += 128) {
        const float4 k = *reinterpret_cast<const float4*>(row + a);
        const float4 w = *reinterpret_cast<const float4*>(w2 + a);
        s += k.x * w.x + k.y * w.y + k.z * w.z + k.w * w.w;
    }
#pragma unroll
    for (int off = 16; off > 0; off >>= 1) s += __shfl_xor_sync(0xffffffffu, s, off);
    if (lane == 0) {
        const int b = m & (B_ - 1);
        const int j = m >> 3;
        vb[(long)b * S_ + j] = s;
    }
}

// ---------------------------------------------------------------------------
// Fused row softmax + split-bf16 emit (fast exp, float4 strides)
// ---------------------------------------------------------------------------
__global__ void __launch_bounds__(256) softmax_split(const float* __restrict__ P,
                                                     __nv_bfloat16* __restrict__ Pb)
{
    const int i = blockIdx.x, b = blockIdx.y;
    const float* p = P + ((size_t)b * S_ + i) * S_;
    __nv_bfloat16* o = Pb + ((size_t)b * S_ + i) * (2 * S_);
    const int jEnd = ((i >> 7) + 1) << 7;
    const int tid = threadIdx.x;
    __shared__ float sm[8];

    float m = neg_inf_f();
    for (int j = tid * 4; j < jEnd; j += 1024) {
        const float4 v = *reinterpret_cast<const float4*>(p + j);
        m = fmaxf(m, fmaxf(fmaxf(v.x, v.y), fmaxf(v.z, v.w)));
    }
#pragma unroll
    for (int off = 16; off > 0; off >>= 1) m = fmaxf(m, __shfl_xor_sync(0xffffffffu, m, off));
    if ((tid & 31) == 0) sm[tid >> 5] = m;
    __syncthreads();
    const float rowmax = fmaxf(fmaxf(fmaxf(sm[0], sm[1]), fmaxf(sm[2], sm[3])),
                               fmaxf(fmaxf(sm[4], sm[5]), fmaxf(sm[6], sm[7])));
    __syncthreads();

    float s = 0.0f;
    for (int j = tid * 4; j < jEnd; j += 1024) {
        const float4 v = *reinterpret_cast<const float4*>(p + j);
        s += __expf(v.x - rowmax) + __expf(v.y - rowmax)
           + __expf(v.z - rowmax) + __expf(v.w - rowmax);
    }
#pragma unroll
    for (int off = 16; off > 0; off >>= 1) s += __shfl_xor_sync(0xffffffffu, s, off);
    if ((tid & 31) == 0) sm[tid >> 5] = s;
    __syncthreads();
    const float inv = 1.0f / ((sm[0] + sm[1]) + (sm[2] + sm[3]) + (sm[4] + sm[5]) + (sm[6] + sm[7]));

    for (int j = tid * 4; j < jEnd; j += 1024) {
        const float4 v = *reinterpret_cast<const float4*>(p + j);
        const float e0 = __expf(v.x - rowmax) * inv;
        const float e1 = __expf(v.y - rowmax) * inv;
        const float e2 = __expf(v.z - rowmax) * inv;
        const float e3 = __expf(v.w - rowmax) * inv;
        const __nv_bfloat16 h0 = __float2bfloat16(e0);
        const __nv_bfloat16 h1 = __float2bfloat16(e1);
        const __nv_bfloat16 h2 = __float2bfloat16(e2);
        const __nv_bfloat16 h3 = __float2bfloat16(e3);
        uint2 hp, lp;
        hp.x = pack_bf2(e0, e1); hp.y = pack_bf2(e2, e3);
        lp.x = pack_bf2(e0 - __bfloat162float(h0), e1 - __bfloat162float(h1));
        lp.y = pack_bf2(e2 - __bfloat162float(h2), e3 - __bfloat162float(h3));
        *reinterpret_cast<uint2*>(o + j)      = hp;
        *reinterpret_cast<uint2*>(o + S_ + j) = lp;
    }
}

// ---------------------------------------------------------------------------
extern "C" void kernel_launch(void* const* d_in, const int* in_sizes, int n_in,
                              void* d_out, int out_size)
{
    const float* query = (const float*)d_in[0];
    const float* key   = (const float*)d_in[1];
    const float* value = (const float*)d_in[2];
    const float* Wq = (const float*)d_in[4];
    const float* bq = (const float*)d_in[5];
    const float* Wk = (const float*)d_in[6];
    // d_in[7] = bk : softmax-invariant, dropped exactly
    const float* Wv = (const float*)d_in[8];
    const float* bv = (const float*)d_in[9];
    const float* Wo = (const float*)d_in[10];
    const float* bo = (const float*)d_in[11];
    float* out = (float*)d_out;

    __nv_bfloat16 *Qc, *Kc, *Vc, *WkT, *WqT, *WvT, *Wos, *H, *WvoB, *T, *Zt, *Pbf;
    float *Zf, *P, *w2p, *w2, *cb, *vb;
    cudaGetSymbolAddress((void**)&Qc,  g_Qc);
    cudaGetSymbolAddress((void**)&Kc,  g_Kc);
    cudaGetSymbolAddress((void**)&Vc,  g_Vc);
    cudaGetSymbolAddress((void**)&WkT, g_WkT);
    cudaGetSymbolAddress((void**)&WqT, g_WqT);
    cudaGetSymbolAddress((void**)&WvT, g_WvT);
    cudaGetSymbolAddress((void**)&Wos, g_Wos);
    cudaGetSymbolAddress((void**)&H,   g_H);
    cudaGetSymbolAddress((void**)&WvoB,g_WvoB);
    cudaGetSymbolAddress((void**)&T,   g_T);
    cudaGetSymbolAddress((void**)&Zf,  g_Zf);
    cudaGetSymbolAddress((void**)&Zt,  g_Zt);
    cudaGetSymbolAddress((void**)&P,   g_P);
    cudaGetSymbolAddress((void**)&Pbf, g_Pbf);
    cudaGetSymbolAddress((void**)&w2p, g_w2p);
    cudaGetSymbolAddress((void**)&w2,  g_w2);
    cudaGetSymbolAddress((void**)&cb,  g_cb);
    cudaGetSymbolAddress((void**)&vb,  g_vb);

    cudaFuncSetAttribute(gemm_dual<1, 1>,
                         cudaFuncAttributeMaxDynamicSharedMemorySize, GEMM_SMEM);
    cudaFuncSetAttribute(gemm_dual<1, 0>,
                         cudaFuncAttributeMaxDynamicSharedMemorySize, GEMM_SMEM);
    cudaFuncSetAttribute(gemm_one<4, false, true>,
                         cudaFuncAttributeMaxDynamicSharedMemorySize, GEMM_SMEM);
    cudaFuncSetAttribute(gemm_one<0, true, false>,
                         cudaFuncAttributeMaxDynamicSharedMemorySize, GEMM_SMEM);

    const long n4i = (long)M_ * D_ / 4;

    // ---- merged prep: q/k/v conversions + Wo conversion + 3 weight transposes ----
    prep_all<<<dim3((unsigned)(n4i / 1024), 1, 5), 256>>>(
        query, key, value, Wo, Wk, Wq, Wv, Qc, Kc, Vc, Wos, WkT, WqT, WvT);

    // ---- merged bias prep (w2 partials + cb), then combine, then vb ----
    bias_prep<<<dim3(128, 1, 2), 256>>>(Wk, bq, Wo, bv, bo, w2p, cb);
    w2_combine<<<D_ / 256, 256>>>(w2p, w2);
    vb_kernel<<<M_ / 8, 256>>>(key, w2, vb);

    // ---- H = Wk^T Wq  and  WvoB = (Wo Wv)[o][a], one dual launch ----
    GArgs hA{};
    hA.A = WkT; hA.lda = 2 * D_; hA.bsA = 0; hA.oAlo = D_;
    hA.B = WqT; hA.ldb = 2 * D_; hA.bsB = 0; hA.oBlo = D_;
    hA.Kpart = D_; hA.scale = 1.0f; hA.bias = nullptr; hA.cbias = nullptr;
    hA.outH = H; hA.ldo = 2 * D_; hA.bsO = 0; hA.loOff = D_;
    GArgs hB = hA;
    hB.A = Wos; hB.B = WvT; hB.outH = WvoB;
    gemm_dual<1, 1><<<dim3(D_ / 128, D_ / 256, 2), 256, GEMM_SMEM>>>(hA, hB);

    // ---- T = query * G (split out)  and  Z = value * Wvo^T (fp32 out), dual ----
    GArgs tA{};
    tA.A = Qc; tA.lda = 2 * D_; tA.bsA = 0; tA.oAlo = D_;
    tA.B = H;  tA.ldb = 2 * D_; tA.bsB = 0; tA.oBlo = D_;
    tA.Kpart = D_; tA.scale = 1.0f; tA.bias = nullptr; tA.cbias = nullptr;
    tA.outH = T; tA.ldo = 2 * D_; tA.bsO = 0; tA.loOff = D_;
    GArgs tB{};
    tB.A = Vc; tB.lda = 2 * D_; tB.bsA = 0; tB.oAlo = D_;
    tB.B = WvoB; tB.ldb = 2 * D_; tB.bsB = 0; tB.oBlo = D_;
    tB.Kpart = D_; tB.scale = 1.0f; tB.bias = nullptr; tB.cbias = nullptr;
    tB.outF = Zf; tB.ldo = D_; tB.bsO = 0;
    gemm_dual<1, 0><<<dim3(D_ / 128, M_ / 256, 2), 256, GEMM_SMEM>>>(tA, tB);

    // ---- Z^T split for the PV GEMM ----
    transpose_split_v<<<dim3(D_ / 32, S_ / 64, B_), dim3(32, 8)>>>(Zf, Zt);

    // ---- Scores: P = SCALE * (T . key^T + vb), tril tiles, causal mask ----
    GArgs sc{};
    sc.A = T;  sc.lda = (long)B_ * 2 * D_; sc.bsA = 2 * D_; sc.oAlo = D_;
    sc.B = Kc; sc.ldb = (long)B_ * 2 * D_; sc.bsB = 2 * D_; sc.oBlo = D_;
    sc.Kpart = D_; sc.scale = SCALE_; sc.bias = nullptr; sc.cbias = vb;
    sc.outF = P; sc.ldo = S_; sc.bsO = (long)S_ * S_;
    gemm_one<4, false, true><<<dim3(S_ / 128, S_ / 256, B_), 256, GEMM_SMEM>>>(sc);

    // ---- fused softmax + P split ----
    softmax_split<<<dim3(S_, B_), 256>>>(P, Pbf);

    // ---- out = P @ Z + cb (causal K bound), fp32 straight to d_out ----
    GArgs pv{};
    pv.A = Pbf; pv.lda = 2 * S_; pv.bsA = (long)S_ * 2 * S_; pv.oAlo = S_;
    pv.B = Zt;  pv.ldb = 2 * S_; pv.bsB = (long)D_ * 2 * S_; pv.oBlo = S_;
    pv.Kpart = S_; pv.scale = 1.0f; pv.bias = cb; pv.cbias = nullptr;
    pv.outF = out; pv.ldo = (long)B_ * D_; pv.bsO = D_;
    gemm_one<0, true, false><<<dim3(D_ / 128, S_ / 256, B_), 256, GEMM_SMEM>>>(pv);
}

// round 15
// speedup vs baseline: 1.3846x; 1.0109x over previous
#include <cuda_runtime.h>
#include <cuda_bf16.h>
#include <cstdint>
#include <math.h>

// ---------------------------------------------------------------------------
// Problem constants
// ---------------------------------------------------------------------------
static constexpr int S_ = 2048, B_ = 8, D_ = 1024, M_ = S_ * B_;
static constexpr float SCALE_ = 0.03125f;  // 1/sqrt(1024)

// ---------------------------------------------------------------------------
// Static scratch. Split-bf16 layout: row-major [rows][2*K]: hi at [k], lo at [K+k].
// ---------------------------------------------------------------------------
__device__ __nv_bfloat16 g_Qc [(size_t)M_ * 2 * D_];
__device__ __nv_bfloat16 g_Kc [(size_t)M_ * 2 * D_];
__device__ __nv_bfloat16 g_Vc [(size_t)M_ * 2 * D_];
__device__ __nv_bfloat16 g_WkT[(size_t)D_ * 2 * D_];
__device__ __nv_bfloat16 g_WqT[(size_t)D_ * 2 * D_];
__device__ __nv_bfloat16 g_WvT[(size_t)D_ * 2 * D_];
__device__ __nv_bfloat16 g_Wos[(size_t)D_ * 2 * D_];
__device__ __nv_bfloat16 g_H  [(size_t)D_ * 2 * D_];   // (Wk^T Wq) split
__device__ __nv_bfloat16 g_WvoB[(size_t)D_ * 2 * D_];  // (Wo Wv)[o][a] split
__device__ __nv_bfloat16 g_T  [(size_t)M_ * 2 * D_];   // T = query * G
__device__ __nv_bfloat16 g_Zt [(size_t)B_ * D_ * 2 * S_]; // Z^T split (from EPI2)
__device__ float         g_P  [(size_t)B_ * S_ * S_];
__device__ __nv_bfloat16 g_Pbf[(size_t)B_ * S_ * 2 * S_];
__device__ float         g_w2p[16][D_];                // w2 partials
__device__ float         g_w2 [D_];
__device__ float         g_cb [D_];
__device__ float         g_vb [(size_t)B_ * S_];

// ---------------------------------------------------------------------------
// Portable PTX helpers
// ---------------------------------------------------------------------------
__device__ __forceinline__ uint32_t smem_u32(const void* p) {
    uint32_t a;
    asm("{ .reg .u64 t; cvta.to.shared.u64 t, %1; cvt.u32.u64 %0, t; }" : "=r"(a) : "l"(p));
    return a;
}

__device__ __forceinline__ void ldsm4(uint32_t* r, uint32_t a) {
    asm volatile("ldmatrix.sync.aligned.m8n8.x4.shared.b16 {%0,%1,%2,%3}, [%4];"
                 : "=r"(r[0]), "=r"(r[1]), "=r"(r[2]), "=r"(r[3]) : "r"(a));
}

__device__ __forceinline__ void mma16816(float* d, const uint32_t* a, const uint32_t* b) {
    asm volatile(
        "mma.sync.aligned.m16n8k16.row.col.f32.bf16.bf16.f32 "
        "{%0,%1,%2,%3}, {%4,%5,%6,%7}, {%8,%9}, {%0,%1,%2,%3};"
        : "+f"(d[0]), "+f"(d[1]), "+f"(d[2]), "+f"(d[3])
        : "r"(a[0]), "r"(a[1]), "r"(a[2]), "r"(a[3]), "r"(b[0]), "r"(b[1]));
}

__device__ __forceinline__ void cp16(uint32_t saddr, const void* gaddr) {
    asm volatile("cp.async.cg.shared.global [%0], [%1], 16;" :: "r"(saddr), "l"(gaddr));
}
__device__ __forceinline__ void cp_commit() {
    asm volatile("cp.async.commit_group;" ::: "memory");
}
template<int N>
__device__ __forceinline__ void cp_wait() {
    asm volatile("cp.async.wait_group %0;" :: "n"(N) : "memory");
}

__device__ __forceinline__ float neg_inf_f() { return __int_as_float(0xff800000); }

__device__ __forceinline__ uint32_t pack_bf2(float a, float b) {
    __nv_bfloat162 h = __floats2bfloat162_rn(a, b);
    return *reinterpret_cast<uint32_t*>(&h);
}

__device__ __forceinline__ uint32_t pack_hilo(float v) {
    const __nv_bfloat16 h = __float2bfloat16(v);
    const __nv_bfloat16 l = __float2bfloat16(v - __bfloat162float(h));
    return (uint32_t)*reinterpret_cast<const uint16_t*>(&h)
         | ((uint32_t)*reinterpret_cast<const uint16_t*>(&l) << 16);
}

// ---------------------------------------------------------------------------
// Fused split GEMM (R13/R14 engine, single barrier per chunk).
// CTA 256x128, 256 threads, warp tile 64x64.
// acc = Alo*Bhi + Ahi*Bhi + Ahi*Blo. k-chunk 64, 2-stage cp.async.
// EPI: 0 = fp32 out (+bias), 1 = split-bf16 out,
//      2 = transposed split out to Zt (batch de-interleave, smem staged),
//      4 = scores (cbias+mask+scale)
// ---------------------------------------------------------------------------
struct GArgs {
    const __nv_bfloat16* A; const __nv_bfloat16* B;
    long lda, ldb, bsA, bsB;
    long oAlo, oBlo;
    int  Kpart;
    float scale;
    const float* bias;
    const float* cbias;
    float* outF;
    __nv_bfloat16* outH;
    long ldo, bsO, loOff;
};

static constexpr int A_TILE = 32768;
static constexpr int B_TILE = 16384;
static constexpr int STAGE  = 2 * A_TILE + 2 * B_TILE;  // 96 KB
static constexpr int GEMM_SMEM = 1024 + 2 * STAGE;      // 193 KB
static constexpr int TW = 264;                          // EPI2 stage row width (u32)

template<int EPI, bool CAUSALK, bool TRIL>
__device__ __forceinline__ void gemm_body(const GArgs& g, int nt, int mt, int bz)
{
    if (TRIL && nt * 128 > mt * 256 + 255) return;
    const int mBase = mt * 256, nBase = nt * 128;

    extern __shared__ char smem_raw[];
    const uint32_t sbase = smem_u32(smem_raw);
    const uint32_t abase = (sbase + 1023) & ~1023u;
    char* sal = smem_raw + (abase - sbase);

    const int tid  = threadIdx.x;
    const int lane = tid & 31;
    const int warp = tid >> 5;
    const int wm   = warp >> 1;
    const int wn   = warp & 1;

    const __nv_bfloat16* Ab = g.A + (long)bz * g.bsA;
    const __nv_bfloat16* Bb = g.B + (long)bz * g.bsB;

    const int kEff = CAUSALK ? (mBase + 256) : g.Kpart;
    const int nch  = kEff >> 6;

    auto issue_chunk = [&](int c) {
        const long kc = (long)(c << 6);
        const int st = c & 1;
        const uint32_t sAhi = abase + st * STAGE;
        const uint32_t sAlo = sAhi + A_TILE;
        const uint32_t sBhi = sAhi + 2 * A_TILE;
        const uint32_t sBlo = sBhi + B_TILE;
#pragma unroll
        for (int i = 0; i < 8; i++) {
            const int id = tid + i * 256;
            const int row = id >> 3, cc = id & 7;
            const uint32_t so = (uint32_t)(row << 7) + (uint32_t)((cc ^ (row & 7)) << 4);
            const __nv_bfloat16* src = Ab + (long)(mBase + row) * g.lda + kc + cc * 8;
            cp16(sAhi + so, src);
            cp16(sAlo + so, src + g.oAlo);
        }
#pragma unroll
        for (int i = 0; i < 4; i++) {
            const int id = tid + i * 256;
            const int row = id >> 3, cc = id & 7;
            const uint32_t so = (uint32_t)(row << 7) + (uint32_t)((cc ^ (row & 7)) << 4);
            const __nv_bfloat16* src = Bb + (long)(nBase + row) * g.ldb + kc + cc * 8;
            cp16(sBhi + so, src);
            cp16(sBlo + so, src + g.oBlo);
        }
        cp_commit();
    };

    float acc[4][8][4];
#pragma unroll
    for (int i = 0; i < 4; i++)
#pragma unroll
        for (int j = 0; j < 8; j++)
#pragma unroll
            for (int d = 0; d < 4; d++) acc[i][j][d] = 0.0f;

    issue_chunk(0);

    const int arow = (lane & 7) + ((lane >> 3) & 1) * 8;
    const int acol = lane >> 4;
    const int brow = (lane & 7) + ((lane >> 4) & 1) * 8;
    const int bcol = (lane >> 3) & 1;

    for (int c = 0; c < nch; c++) {
        cp_wait<0>();
        __syncthreads();               // single barrier per chunk
        if (c + 1 < nch) issue_chunk(c + 1);

        const int st = c & 1;
        const uint32_t sAhi = abase + st * STAGE;
        const uint32_t sAlo = sAhi + A_TILE;
        const uint32_t sBhi = sAhi + 2 * A_TILE;
        const uint32_t sBlo = sBhi + B_TILE;

#pragma unroll
        for (int ks = 0; ks < 4; ks++) {
            uint32_t af[4][4], bf[4][4];
            // pass 1: Alo x Bhi
#pragma unroll
            for (int mi = 0; mi < 4; mi++) {
                const int row = wm * 64 + mi * 16 + arow;
                const int cc  = ks * 2 + acol;
                ldsm4(af[mi], sAlo + (row << 7) + ((cc ^ (row & 7)) << 4));
            }
#pragma unroll
            for (int nj = 0; nj < 4; nj++) {
                const int row = wn * 64 + nj * 16 + brow;
                const int cc  = ks * 2 + bcol;
                ldsm4(bf[nj], sBhi + (row << 7) + ((cc ^ (row & 7)) << 4));
            }
#pragma unroll
            for (int mi = 0; mi < 4; mi++)
#pragma unroll
                for (int nj = 0; nj < 4; nj++) {
                    mma16816(acc[mi][2 * nj],     af[mi], &bf[nj][0]);
                    mma16816(acc[mi][2 * nj + 1], af[mi], &bf[nj][2]);
                }
            // pass 2: Ahi x Bhi
#pragma unroll
            for (int mi = 0; mi < 4; mi++) {
                const int row = wm * 64 + mi * 16 + arow;
                const int cc  = ks * 2 + acol;
                ldsm4(af[mi], sAhi + (row << 7) + ((cc ^ (row & 7)) << 4));
            }
#pragma unroll
            for (int mi = 0; mi < 4; mi++)
#pragma unroll
                for (int nj = 0; nj < 4; nj++) {
                    mma16816(acc[mi][2 * nj],     af[mi], &bf[nj][0]);
                    mma16816(acc[mi][2 * nj + 1], af[mi], &bf[nj][2]);
                }
            // pass 3: Ahi x Blo
#pragma unroll
            for (int nj = 0; nj < 4; nj++) {
                const int row = wn * 64 + nj * 16 + brow;
                const int cc  = ks * 2 + bcol;
                ldsm4(bf[nj], sBlo + (row << 7) + ((cc ^ (row & 7)) << 4));
            }
#pragma unroll
            for (int mi = 0; mi < 4; mi++)
#pragma unroll
                for (int nj = 0; nj < 4; nj++) {
                    mma16816(acc[mi][2 * nj],     af[mi], &bf[nj][0]);
                    mma16816(acc[mi][2 * nj + 1], af[mi], &bf[nj][2]);
                }
        }
    }

    // ------------------------- epilogue (compile-time EPI) -------------------
    const int gq = lane >> 2, tg = lane & 3;

    if (EPI == 2) {
        // Transposed split write to Zt via smem staging.
        // m = s*8 + b (global row); output Zt[b][d][hi(S)|lo(S)].
        uint32_t* sm32 = reinterpret_cast<uint32_t*>(sal);
        __syncthreads();   // all warps done with pipeline smem
#pragma unroll
        for (int mi = 0; mi < 4; mi++) {
#pragma unroll
            for (int half = 0; half < 2; half++) {
                const int gmL = wm * 64 + mi * 16 + gq + half * 8;   // 0..255
                const int col = (gmL >> 3) + 33 * (gmL & 7);
#pragma unroll
                for (int ni = 0; ni < 8; ni++) {
                    const int gnL = wn * 64 + ni * 8 + 2 * tg;       // 0..127
                    sm32[(gnL + 0) * TW + col] = pack_hilo(acc[mi][ni][half * 2 + 0]);
                    sm32[(gnL + 1) * TW + col] = pack_hilo(acc[mi][ni][half * 2 + 1]);
                }
            }
        }
        __syncthreads();
        const int sBase = mBase >> 3;          // tile s start (32-aligned)
        const int bb = (tid >> 4) & 7;
        const int sq = tid & 15;
        const int nHalf = tid >> 7;            // 0/1
#pragma unroll 4
        for (int it = 0; it < 64; it++) {
            const int n = it * 2 + nHalf;
            const uint32_t u0 = sm32[n * TW + 2 * sq     + 33 * bb];
            const uint32_t u1 = sm32[n * TW + 2 * sq + 1 + 33 * bb];
            const uint32_t hi01 = (u0 & 0xFFFFu) | (u1 << 16);
            const uint32_t lo01 = (u0 >> 16) | (u1 & 0xFFFF0000u);
            __nv_bfloat16* orow = g.outH
                + ((size_t)bb * D_ + nBase + n) * (2 * S_) + sBase + 2 * sq;
            *reinterpret_cast<uint32_t*>(orow)      = hi01;
            *reinterpret_cast<uint32_t*>(orow + S_) = lo01;
        }
        return;
    }

#pragma unroll
    for (int mi = 0; mi < 4; mi++) {
#pragma unroll
        for (int half = 0; half < 2; half++) {
            const int gm = mBase + wm * 64 + mi * 16 + gq + half * 8;
#pragma unroll
            for (int ni = 0; ni < 8; ni++) {
                const int gn = nBase + wn * 64 + ni * 8 + 2 * tg;
                const float v0 = acc[mi][ni][half * 2 + 0];
                const float v1 = acc[mi][ni][half * 2 + 1];

                if (EPI == 0) {
                    float2 v;
                    v.x = v0; v.y = v1;
                    if (g.bias) { v.x += g.bias[gn + 0]; v.y += g.bias[gn + 1]; }
                    *reinterpret_cast<float2*>(
                        g.outF + (long)bz * g.bsO + (long)gm * g.ldo + gn) = v;
                } else if (EPI == 1) {
                    const __nv_bfloat16 h0 = __float2bfloat16(v0);
                    const __nv_bfloat16 h1 = __float2bfloat16(v1);
                    const __nv_bfloat16 l0 = __float2bfloat16(v0 - __bfloat162float(h0));
                    const __nv_bfloat16 l1 = __float2bfloat16(v1 - __bfloat162float(h1));
                    __nv_bfloat16* o = g.outH + (long)bz * g.bsO + (long)gm * g.ldo + gn;
                    *reinterpret_cast<__nv_bfloat162*>(o) = __nv_bfloat162(h0, h1);
                    *reinterpret_cast<__nv_bfloat162*>(o + g.loOff) = __nv_bfloat162(l0, l1);
                } else {  // EPI == 4 : scores
                    const float cb0 = g.cbias[(long)bz * S_ + gn + 0];
                    const float cb1 = g.cbias[(long)bz * S_ + gn + 1];
                    float2 v;
                    v.x = (gn + 0 > gm) ? neg_inf_f() : (v0 + cb0) * g.scale;
                    v.y = (gn + 1 > gm) ? neg_inf_f() : (v1 + cb1) * g.scale;
                    *reinterpret_cast<float2*>(
                        g.outF + (long)bz * g.bsO + (long)gm * g.ldo + gn) = v;
                }
            }
        }
    }
}

template<int EPI, bool CAUSALK, bool TRIL>
__global__ void __launch_bounds__(256, 1) gemm_one(GArgs g)
{
    gemm_body<EPI, CAUSALK, TRIL>(g, blockIdx.x, gridDim.y - 1 - blockIdx.y, blockIdx.z);
}

template<int E0, int E1>
__global__ void __launch_bounds__(256, 1) gemm_dual(GArgs g0, GArgs g1)
{
    if (blockIdx.z == 0)
        gemm_body<E0, false, false>(g0, blockIdx.x, blockIdx.y, 0);
    else
        gemm_body<E1, false, false>(g1, blockIdx.x, blockIdx.y, 0);
}

// ---------------------------------------------------------------------------
// Merged prep: one launch, grid (4096, 1, 5), 256 threads.
//   z in {0,1,2}: q/k/v fp32 -> split bf16 (MLP=4)
//   z == 3     : Wo fp32 -> split bf16 (x < 1024 active)
//   z == 4     : Wk/Wq/Wv transpose+split (x < 3072 active; x>>10 picks W)
// ---------------------------------------------------------------------------
__global__ void prep_all(const float* __restrict__ q, const float* __restrict__ k,
                         const float* __restrict__ v, const float* __restrict__ Wo,
                         const float* __restrict__ Wk, const float* __restrict__ Wq,
                         const float* __restrict__ Wv,
                         __nv_bfloat16* __restrict__ Qc, __nv_bfloat16* __restrict__ Kc,
                         __nv_bfloat16* __restrict__ Vc, __nv_bfloat16* __restrict__ Wos,
                         __nv_bfloat16* __restrict__ WkT, __nv_bfloat16* __restrict__ WqT,
                         __nv_bfloat16* __restrict__ WvT)
{
    __shared__ float t[32][33];
    const int tid = threadIdx.x;
    const int z = blockIdx.z;

    if (z < 3) {
        const float* in = (z == 0) ? q : (z == 1) ? k : v;
        __nv_bfloat16* out = (z == 0) ? Qc : (z == 1) ? Kc : Vc;
        const long base = (long)blockIdx.x * 1024 + tid;

        float4 v4[4];
#pragma unroll
        for (int j = 0; j < 4; j++)
            v4[j] = reinterpret_cast<const float4*>(in)[base + j * 256];

#pragma unroll
        for (int j = 0; j < 4; j++) {
            const long idx = (base + j * 256) * 4;
            const long m = idx >> 10;
            const int  kk = (int)(idx & 1023);
            const __nv_bfloat16 h0 = __float2bfloat16(v4[j].x);
            const __nv_bfloat16 h1 = __float2bfloat16(v4[j].y);
            const __nv_bfloat16 h2 = __float2bfloat16(v4[j].z);
            const __nv_bfloat16 h3 = __float2bfloat16(v4[j].w);
            uint2 hp, lp;
            hp.x = pack_bf2(v4[j].x, v4[j].y);
            hp.y = pack_bf2(v4[j].z, v4[j].w);
            lp.x = pack_bf2(v4[j].x - __bfloat162float(h0), v4[j].y - __bfloat162float(h1));
            lp.y = pack_bf2(v4[j].z - __bfloat162float(h2), v4[j].w - __bfloat162float(h3));
            __nv_bfloat16* o = out + m * 2048 + kk;
            *reinterpret_cast<uint2*>(o)        = hp;
            *reinterpret_cast<uint2*>(o + 1024) = lp;
        }
    } else if (z == 3) {
        if (blockIdx.x >= 1024) return;
        const long i = (long)blockIdx.x * 256 + tid;
        const float4 vv = reinterpret_cast<const float4*>(Wo)[i];
        const long idx = i * 4;
        const long m = idx >> 10;
        const int  kk = (int)(idx & 1023);
        const __nv_bfloat16 h0 = __float2bfloat16(vv.x);
        const __nv_bfloat16 h1 = __float2bfloat16(vv.y);
        const __nv_bfloat16 h2 = __float2bfloat16(vv.z);
        const __nv_bfloat16 h3 = __float2bfloat16(vv.w);
        uint2 hp, lp;
        hp.x = pack_bf2(vv.x, vv.y);
        hp.y = pack_bf2(vv.z, vv.w);
        lp.x = pack_bf2(vv.x - __bfloat162float(h0), vv.y - __bfloat162float(h1));
        lp.y = pack_bf2(vv.z - __bfloat162float(h2), vv.w - __bfloat162float(h3));
        __nv_bfloat16* o = Wos + m * 2048 + kk;
        *reinterpret_cast<uint2*>(o)        = hp;
        *reinterpret_cast<uint2*>(o + 1024) = lp;
    } else {
        if (blockIdx.x >= 3072) return;
        const int which = blockIdx.x >> 10;
        const int rem = blockIdx.x & 1023;
        const float* W = (which == 0) ? Wk : (which == 1) ? Wq : Wv;
        __nv_bfloat16* out = (which == 0) ? WkT : (which == 1) ? WqT : WvT;
        const int a0 = (rem & 31) * 32, e0 = (rem >> 5) * 32;
        const int tx = tid & 31, ty = tid >> 5;
#pragma unroll
        for (int r = 0; r < 32; r += 8)
            t[r + ty][tx] = W[(long)(e0 + r + ty) * D_ + a0 + tx];
        __syncthreads();
#pragma unroll
        for (int r = 0; r < 32; r += 8) {
            const int a = a0 + r + ty, e = e0 + tx;
            const float vv = t[tx][r + ty];
            const __nv_bfloat16 h = __float2bfloat16(vv);
            __nv_bfloat16* o = out + (long)a * 2 * D_ + e;
            o[0]  = h;
            o[D_] = __float2bfloat16(vv - __bfloat162float(h));
        }
    }
}

// ---------------------------------------------------------------------------
// Merged bias prep: grid (128, 1, 2).
//   z==0, x<64 : w2 partial (x&3 -> a-group, x>>2 -> d-slice)
//   z==1       : cb = bo + Wo*bv (x<128)
// ---------------------------------------------------------------------------
__global__ void bias_prep(const float* __restrict__ Wk, const float* __restrict__ bq,
                          const float* __restrict__ Wo, const float* __restrict__ bv,
                          const float* __restrict__ bo,
                          float* __restrict__ w2p, float* __restrict__ cb)
{
    if (blockIdx.z == 0) {
        if (blockIdx.x >= 64) return;
        const int a = (blockIdx.x & 3) * 256 + threadIdx.x;
        const int d0 = (blockIdx.x >> 2) * 64;
        float s = 0.0f;
#pragma unroll 4
        for (int d = d0; d < d0 + 64; d++)
            s += bq[d] * Wk[(long)d * D_ + a];
        w2p[(blockIdx.x >> 2) * D_ + a] = s;
    } else {
        const int o = blockIdx.x * 8 + (threadIdx.x >> 5);
        const int lane = threadIdx.x & 31;
        float s = 0.0f;
        for (int e = lane * 4; e < D_; e += 128) {
            const float4 w = *reinterpret_cast<const float4*>(Wo + (long)o * D_ + e);
            const float4 b = *reinterpret_cast<const float4*>(bv + e);
            s += w.x * b.x + w.y * b.y + w.z * b.z + w.w * b.w;
        }
#pragma unroll
        for (int off = 16; off > 0; off >>= 1) s += __shfl_xor_sync(0xffffffffu, s, off);
        if (lane == 0) cb[o] = bo[o] + s;
    }
}

__global__ void w2_combine(const float* __restrict__ w2p, float* __restrict__ w2)
{
    const int a = blockIdx.x * 256 + threadIdx.x;
    float s = 0.0f;
#pragma unroll
    for (int i = 0; i < 16; i++) s += w2p[i * D_ + a];
    w2[a] = s;
}

__global__ void vb_kernel(const float* __restrict__ key, const float* __restrict__ w2,
                          float* __restrict__ vb)
{
    const int m = blockIdx.x * 8 + (threadIdx.x >> 5);
    const int lane = threadIdx.x & 31;
    const float* row = key + (long)m * D_;
    float s = 0.0f;
    for (int a = lane * 4; a < D_; a += 128) {
        const float4 k = *reinterpret_cast<const float4*>(row + a);
        const float4 w = *reinterpret_cast<const float4*>(w2 + a);
        s += k.x * w.x + k.y * w.y + k.z * w.z + k.w * w.w;
    }
#pragma unroll
    for (int off = 16; off > 0; off >>= 1) s += __shfl_xor_sync(0xffffffffu, s, off);
    if (lane == 0) {
        const int b = m & (B_ - 1);
        const int j = m >> 3;
        vb[(long)b * S_ + j] = s;
    }
}

// ---------------------------------------------------------------------------
// Fused row softmax + split-bf16 emit (fast exp, float4 strides)
// ---------------------------------------------------------------------------
__global__ void __launch_bounds__(256) softmax_split(const float* __restrict__ P,
                                                     __nv_bfloat16* __restrict__ Pb)
{
    const int i = blockIdx.x, b = blockIdx.y;
    const float* p = P + ((size_t)b * S_ + i) * S_;
    __nv_bfloat16* o = Pb + ((size_t)b * S_ + i) * (2 * S_);
    const int jEnd = ((i >> 7) + 1) << 7;
    const int tid = threadIdx.x;
    __shared__ float sm[8];

    float m = neg_inf_f();
    for (int j = tid * 4; j < jEnd; j += 1024) {
        const float4 v = *reinterpret_cast<const float4*>(p + j);
        m = fmaxf(m, fmaxf(fmaxf(v.x, v.y), fmaxf(v.z, v.w)));
    }
#pragma unroll
    for (int off = 16; off > 0; off >>= 1) m = fmaxf(m, __shfl_xor_sync(0xffffffffu, m, off));
    if ((tid & 31) == 0) sm[tid >> 5] = m;
    __syncthreads();
    const float rowmax = fmaxf(fmaxf(fmaxf(sm[0], sm[1]), fmaxf(sm[2], sm[3])),
                               fmaxf(fmaxf(sm[4], sm[5]), fmaxf(sm[6], sm[7])));
    __syncthreads();

    float s = 0.0f;
    for (int j = tid * 4; j < jEnd; j += 1024) {
        const float4 v = *reinterpret_cast<const float4*>(p + j);
        s += __expf(v.x - rowmax) + __expf(v.y - rowmax)
           + __expf(v.z - rowmax) + __expf(v.w - rowmax);
    }
#pragma unroll
    for (int off = 16; off > 0; off >>= 1) s += __shfl_xor_sync(0xffffffffu, s, off);
    if ((tid & 31) == 0) sm[tid >> 5] = s;
    __syncthreads();
    const float inv = 1.0f / ((sm[0] + sm[1]) + (sm[2] + sm[3]) + (sm[4] + sm[5]) + (sm[6] + sm[7]));

    for (int j = tid * 4; j < jEnd; j += 1024) {
        const float4 v = *reinterpret_cast<const float4*>(p + j);
        const float e0 = __expf(v.x - rowmax) * inv;
        const float e1 = __expf(v.y - rowmax) * inv;
        const float e2 = __expf(v.z - rowmax) * inv;
        const float e3 = __expf(v.w - rowmax) * inv;
        const __nv_bfloat16 h0 = __float2bfloat16(e0);
        const __nv_bfloat16 h1 = __float2bfloat16(e1);
        const __nv_bfloat16 h2 = __float2bfloat16(e2);
        const __nv_bfloat16 h3 = __float2bfloat16(e3);
        uint2 hp, lp;
        hp.x = pack_bf2(e0, e1); hp.y = pack_bf2(e2, e3);
        lp.x = pack_bf2(e0 - __bfloat162float(h0), e1 - __bfloat162float(h1));
        lp.y = pack_bf2(e2 - __bfloat162float(h2), e3 - __bfloat162float(h3));
        *reinterpret_cast<uint2*>(o + j)      = hp;
        *reinterpret_cast<uint2*>(o + S_ + j) = lp;
    }
}

// ---------------------------------------------------------------------------
extern "C" void kernel_launch(void* const* d_in, const int* in_sizes, int n_in,
                              void* d_out, int out_size)
{
    const float* query = (const float*)d_in[0];
    const float* key   = (const float*)d_in[1];
    const float* value = (const float*)d_in[2];
    const float* Wq = (const float*)d_in[4];
    const float* bq = (const float*)d_in[5];
    const float* Wk = (const float*)d_in[6];
    // d_in[7] = bk : softmax-invariant, dropped exactly
    const float* Wv = (const float*)d_in[8];
    const float* bv = (const float*)d_in[9];
    const float* Wo = (const float*)d_in[10];
    const float* bo = (const float*)d_in[11];
    float* out = (float*)d_out;

    __nv_bfloat16 *Qc, *Kc, *Vc, *WkT, *WqT, *WvT, *Wos, *H, *WvoB, *T, *Zt, *Pbf;
    float *P, *w2p, *w2, *cb, *vb;
    cudaGetSymbolAddress((void**)&Qc,  g_Qc);
    cudaGetSymbolAddress((void**)&Kc,  g_Kc);
    cudaGetSymbolAddress((void**)&Vc,  g_Vc);
    cudaGetSymbolAddress((void**)&WkT, g_WkT);
    cudaGetSymbolAddress((void**)&WqT, g_WqT);
    cudaGetSymbolAddress((void**)&WvT, g_WvT);
    cudaGetSymbolAddress((void**)&Wos, g_Wos);
    cudaGetSymbolAddress((void**)&H,   g_H);
    cudaGetSymbolAddress((void**)&WvoB,g_WvoB);
    cudaGetSymbolAddress((void**)&T,   g_T);
    cudaGetSymbolAddress((void**)&Zt,  g_Zt);
    cudaGetSymbolAddress((void**)&P,   g_P);
    cudaGetSymbolAddress((void**)&Pbf, g_Pbf);
    cudaGetSymbolAddress((void**)&w2p, g_w2p);
    cudaGetSymbolAddress((void**)&w2,  g_w2);
    cudaGetSymbolAddress((void**)&cb,  g_cb);
    cudaGetSymbolAddress((void**)&vb,  g_vb);

    cudaFuncSetAttribute(gemm_dual<1, 1>,
                         cudaFuncAttributeMaxDynamicSharedMemorySize, GEMM_SMEM);
    cudaFuncSetAttribute(gemm_dual<1, 2>,
                         cudaFuncAttributeMaxDynamicSharedMemorySize, GEMM_SMEM);
    cudaFuncSetAttribute(gemm_one<4, false, true>,
                         cudaFuncAttributeMaxDynamicSharedMemorySize, GEMM_SMEM);
    cudaFuncSetAttribute(gemm_one<0, true, false>,
                         cudaFuncAttributeMaxDynamicSharedMemorySize, GEMM_SMEM);

    const long n4i = (long)M_ * D_ / 4;

    // ---- merged prep: q/k/v conversions + Wo conversion + 3 weight transposes ----
    prep_all<<<dim3((unsigned)(n4i / 1024), 1, 5), 256>>>(
        query, key, value, Wo, Wk, Wq, Wv, Qc, Kc, Vc, Wos, WkT, WqT, WvT);

    // ---- merged bias prep (w2 partials + cb), then combine, then vb ----
    bias_prep<<<dim3(128, 1, 2), 256>>>(Wk, bq, Wo, bv, bo, w2p, cb);
    w2_combine<<<D_ / 256, 256>>>(w2p, w2);
    vb_kernel<<<M_ / 8, 256>>>(key, w2, vb);

    // ---- H = Wk^T Wq  and  WvoB = (Wo Wv)[o][a], one dual launch ----
    GArgs hA{};
    hA.A = WkT; hA.lda = 2 * D_; hA.bsA = 0; hA.oAlo = D_;
    hA.B = WqT; hA.ldb = 2 * D_; hA.bsB = 0; hA.oBlo = D_;
    hA.Kpart = D_; hA.scale = 1.0f; hA.bias = nullptr; hA.cbias = nullptr;
    hA.outH = H; hA.ldo = 2 * D_; hA.bsO = 0; hA.loOff = D_;
    GArgs hB = hA;
    hB.A = Wos; hB.B = WvT; hB.outH = WvoB;
    gemm_dual<1, 1><<<dim3(D_ / 128, D_ / 256, 2), 256, GEMM_SMEM>>>(hA, hB);

    // ---- T = query * G (split out)  and  Z -> Zt directly (EPI2), dual ----
    GArgs tA{};
    tA.A = Qc; tA.lda = 2 * D_; tA.bsA = 0; tA.oAlo = D_;
    tA.B = H;  tA.ldb = 2 * D_; tA.bsB = 0; tA.oBlo = D_;
    tA.Kpart = D_; tA.scale = 1.0f; tA.bias = nullptr; tA.cbias = nullptr;
    tA.outH = T; tA.ldo = 2 * D_; tA.bsO = 0; tA.loOff = D_;
    GArgs tB{};
    tB.A = Vc; tB.lda = 2 * D_; tB.bsA = 0; tB.oAlo = D_;
    tB.B = WvoB; tB.ldb = 2 * D_; tB.bsB = 0; tB.oBlo = D_;
    tB.Kpart = D_; tB.scale = 1.0f; tB.bias = nullptr; tB.cbias = nullptr;
    tB.outH = Zt;   // EPI2: transposed split write
    gemm_dual<1, 2><<<dim3(D_ / 128, M_ / 256, 2), 256, GEMM_SMEM>>>(tA, tB);

    // ---- Scores: P = SCALE * (T . key^T + vb), tril tiles, causal mask ----
    GArgs sc{};
    sc.A = T;  sc.lda = (long)B_ * 2 * D_; sc.bsA = 2 * D_; sc.oAlo = D_;
    sc.B = Kc; sc.ldb = (long)B_ * 2 * D_; sc.bsB = 2 * D_; sc.oBlo = D_;
    sc.Kpart = D_; sc.scale = SCALE_; sc.bias = nullptr; sc.cbias = vb;
    sc.outF = P; sc.ldo = S_; sc.bsO = (long)S_ * S_;
    gemm_one<4, false, true><<<dim3(S_ / 128, S_ / 256, B_), 256, GEMM_SMEM>>>(sc);

    // ---- fused softmax + P split ----
    softmax_split<<<dim3(S_, B_), 256>>>(P, Pbf);

    // ---- out = P @ Z + cb (causal K bound), fp32 straight to d_out ----
    GArgs pv{};
    pv.A = Pbf; pv.lda = 2 * S_; pv.bsA = (long)S_ * 2 * S_; pv.oAlo = S_;
    pv.B = Zt;  pv.ldb = 2 * S_; pv.bsB = (long)D_ * 2 * S_; pv.oBlo = S_;
    pv.Kpart = S_; pv.scale = 1.0f; pv.bias = cb; pv.cbias = nullptr;
    pv.outF = out; pv.ldo = (long)B_ * D_; pv.bsO = D_;
    gemm_one<0, true, false><<<dim3(D_ / 128, S_ / 256, B_), 256, GEMM_SMEM>>>(pv);
}

// round 17
// speedup vs baseline: 1.4077x; 1.0167x over previous
#include <cuda_runtime.h>
#include <cuda_bf16.h>
#include <cstdint>
#include <math.h>

// ---------------------------------------------------------------------------
// Problem constants
// ---------------------------------------------------------------------------
static constexpr int S_ = 2048, B_ = 8, D_ = 1024, M_ = S_ * B_;
static constexpr float SCALE_ = 0.03125f;  // 1/sqrt(1024)

// ---------------------------------------------------------------------------
// Static scratch. Split-bf16 layout: row-major [rows][2*K]: hi at [k], lo at [K+k].
// ---------------------------------------------------------------------------
__device__ __nv_bfloat16 g_Qc [(size_t)M_ * 2 * D_];
__device__ __nv_bfloat16 g_Kc [(size_t)M_ * 2 * D_];
__device__ __nv_bfloat16 g_Vc [(size_t)M_ * 2 * D_];
__device__ __nv_bfloat16 g_WkT[(size_t)D_ * 2 * D_];
__device__ __nv_bfloat16 g_WqT[(size_t)D_ * 2 * D_];
__device__ __nv_bfloat16 g_WvT[(size_t)D_ * 2 * D_];
__device__ __nv_bfloat16 g_Wos[(size_t)D_ * 2 * D_];
__device__ __nv_bfloat16 g_H  [(size_t)D_ * 2 * D_];   // (Wk^T Wq) split
__device__ __nv_bfloat16 g_WvoB[(size_t)D_ * 2 * D_];  // (Wo Wv)[o][a] split
__device__ __nv_bfloat16 g_T  [(size_t)M_ * 2 * D_];   // T = query * G
__device__ __nv_bfloat16 g_Zt [(size_t)B_ * D_ * 2 * S_]; // Z^T split (from EPI2)
__device__ float         g_P  [(size_t)B_ * S_ * S_];
__device__ __nv_bfloat16 g_Pbf[(size_t)B_ * S_ * 2 * S_];
__device__ float         g_w2p[16][D_];                // w2 partials
__device__ float         g_w2 [D_];
__device__ float         g_cb [D_];
__device__ float         g_vb [(size_t)B_ * S_];

// ---------------------------------------------------------------------------
// Portable PTX helpers
// ---------------------------------------------------------------------------
__device__ __forceinline__ uint32_t smem_u32(const void* p) {
    uint32_t a;
    asm("{ .reg .u64 t; cvta.to.shared.u64 t, %1; cvt.u32.u64 %0, t; }" : "=r"(a) : "l"(p));
    return a;
}

__device__ __forceinline__ void ldsm4(uint32_t* r, uint32_t a) {
    asm volatile("ldmatrix.sync.aligned.m8n8.x4.shared.b16 {%0,%1,%2,%3}, [%4];"
                 : "=r"(r[0]), "=r"(r[1]), "=r"(r[2]), "=r"(r[3]) : "r"(a));
}

__device__ __forceinline__ void mma16816(float* d, const uint32_t* a, const uint32_t* b) {
    asm volatile(
        "mma.sync.aligned.m16n8k16.row.col.f32.bf16.bf16.f32 "
        "{%0,%1,%2,%3}, {%4,%5,%6,%7}, {%8,%9}, {%0,%1,%2,%3};"
        : "+f"(d[0]), "+f"(d[1]), "+f"(d[2]), "+f"(d[3])
        : "r"(a[0]), "r"(a[1]), "r"(a[2]), "r"(a[3]), "r"(b[0]), "r"(b[1]));
}

__device__ __forceinline__ void cp16(uint32_t saddr, const void* gaddr) {
    asm volatile("cp.async.cg.shared.global [%0], [%1], 16;" :: "r"(saddr), "l"(gaddr));
}
__device__ __forceinline__ void cp_commit() {
    asm volatile("cp.async.commit_group;" ::: "memory");
}
template<int N>
__device__ __forceinline__ void cp_wait() {
    asm volatile("cp.async.wait_group %0;" :: "n"(N) : "memory");
}

__device__ __forceinline__ float neg_inf_f() { return __int_as_float(0xff800000); }

__device__ __forceinline__ uint32_t pack_bf2(float a, float b) {
    __nv_bfloat162 h = __floats2bfloat162_rn(a, b);
    return *reinterpret_cast<uint32_t*>(&h);
}

__device__ __forceinline__ uint32_t pack_hilo(float v) {
    const __nv_bfloat16 h = __float2bfloat16(v);
    const __nv_bfloat16 l = __float2bfloat16(v - __bfloat162float(h));
    return (uint32_t)*reinterpret_cast<const uint16_t*>(&h)
         | ((uint32_t)*reinterpret_cast<const uint16_t*>(&l) << 16);
}

// ---------------------------------------------------------------------------
// Fused split GEMM (single barrier per chunk). CTA 256x128, 256 threads.
// acc = Alo*Bhi + Ahi*Bhi + Ahi*Blo. k-chunk 64, 2-stage cp.async.
// EPI: 0 = fp32 out (+bias), 1 = split-bf16 out,
//      2 = transposed split out to Zt, 4 = scores (cbias+mask+scale)
// ---------------------------------------------------------------------------
struct GArgs {
    const __nv_bfloat16* A; const __nv_bfloat16* B;
    long lda, ldb, bsA, bsB;
    long oAlo, oBlo;
    int  Kpart;
    float scale;
    const float* bias;
    const float* cbias;
    float* outF;
    __nv_bfloat16* outH;
    long ldo, bsO, loOff;
};

static constexpr int A_TILE = 32768;
static constexpr int B_TILE = 16384;
static constexpr int STAGE  = 2 * A_TILE + 2 * B_TILE;  // 96 KB
static constexpr int GEMM_SMEM = 1024 + 2 * STAGE;      // 193 KB
static constexpr int TW = 264;                          // EPI2 stage row width (u32)

template<int EPI, bool CAUSALK, bool TRIL>
__device__ __forceinline__ void gemm_body(const GArgs& g, int nt, int mt, int bz)
{
    if (TRIL && nt * 128 > mt * 256 + 255) return;
    const int mBase = mt * 256, nBase = nt * 128;

    extern __shared__ char smem_raw[];
    const uint32_t sbase = smem_u32(smem_raw);
    const uint32_t abase = (sbase + 1023) & ~1023u;
    char* sal = smem_raw + (abase - sbase);

    const int tid  = threadIdx.x;
    const int lane = tid & 31;
    const int warp = tid >> 5;
    const int wm   = warp >> 1;
    const int wn   = warp & 1;

    const __nv_bfloat16* Ab = g.A + (long)bz * g.bsA;
    const __nv_bfloat16* Bb = g.B + (long)bz * g.bsB;

    const int kEff = CAUSALK ? (mBase + 256) : g.Kpart;
    const int nch  = kEff >> 6;

    auto issue_chunk = [&](int c) {
        const long kc = (long)(c << 6);
        const int st = c & 1;
        const uint32_t sAhi = abase + st * STAGE;
        const uint32_t sAlo = sAhi + A_TILE;
        const uint32_t sBhi = sAhi + 2 * A_TILE;
        const uint32_t sBlo = sBhi + B_TILE;
#pragma unroll
        for (int i = 0; i < 8; i++) {
            const int id = tid + i * 256;
            const int row = id >> 3, cc = id & 7;
            const uint32_t so = (uint32_t)(row << 7) + (uint32_t)((cc ^ (row & 7)) << 4);
            const __nv_bfloat16* src = Ab + (long)(mBase + row) * g.lda + kc + cc * 8;
            cp16(sAhi + so, src);
            cp16(sAlo + so, src + g.oAlo);
        }
#pragma unroll
        for (int i = 0; i < 4; i++) {
            const int id = tid + i * 256;
            const int row = id >> 3, cc = id & 7;
            const uint32_t so = (uint32_t)(row << 7) + (uint32_t)((cc ^ (row & 7)) << 4);
            const __nv_bfloat16* src = Bb + (long)(nBase + row) * g.ldb + kc + cc * 8;
            cp16(sBhi + so, src);
            cp16(sBlo + so, src + g.oBlo);
        }
        cp_commit();
    };

    float acc[4][8][4];
#pragma unroll
    for (int i = 0; i < 4; i++)
#pragma unroll
        for (int j = 0; j < 8; j++)
#pragma unroll
            for (int d = 0; d < 4; d++) acc[i][j][d] = 0.0f;

    issue_chunk(0);

    const int arow = (lane & 7) + ((lane >> 3) & 1) * 8;
    const int acol = lane >> 4;
    const int brow = (lane & 7) + ((lane >> 4) & 1) * 8;
    const int bcol = (lane >> 3) & 1;

    for (int c = 0; c < nch; c++) {
        cp_wait<0>();
        __syncthreads();               // single barrier per chunk
        if (c + 1 < nch) issue_chunk(c + 1);

        const int st = c & 1;
        const uint32_t sAhi = abase + st * STAGE;
        const uint32_t sAlo = sAhi + A_TILE;
        const uint32_t sBhi = sAhi + 2 * A_TILE;
        const uint32_t sBlo = sBhi + B_TILE;

#pragma unroll
        for (int ks = 0; ks < 4; ks++) {
            uint32_t af[4][4], bf[4][4];
            // pass 1: Alo x Bhi
#pragma unroll
            for (int mi = 0; mi < 4; mi++) {
                const int row = wm * 64 + mi * 16 + arow;
                const int cc  = ks * 2 + acol;
                ldsm4(af[mi], sAlo + (row << 7) + ((cc ^ (row & 7)) << 4));
            }
#pragma unroll
            for (int nj = 0; nj < 4; nj++) {
                const int row = wn * 64 + nj * 16 + brow;
                const int cc  = ks * 2 + bcol;
                ldsm4(bf[nj], sBhi + (row << 7) + ((cc ^ (row & 7)) << 4));
            }
#pragma unroll
            for (int mi = 0; mi < 4; mi++)
#pragma unroll
                for (int nj = 0; nj < 4; nj++) {
                    mma16816(acc[mi][2 * nj],     af[mi], &bf[nj][0]);
                    mma16816(acc[mi][2 * nj + 1], af[mi], &bf[nj][2]);
                }
            // pass 2: Ahi x Bhi
#pragma unroll
            for (int mi = 0; mi < 4; mi++) {
                const int row = wm * 64 + mi * 16 + arow;
                const int cc  = ks * 2 + acol;
                ldsm4(af[mi], sAhi + (row << 7) + ((cc ^ (row & 7)) << 4));
            }
#pragma unroll
            for (int mi = 0; mi < 4; mi++)
#pragma unroll
                for (int nj = 0; nj < 4; nj++) {
                    mma16816(acc[mi][2 * nj],     af[mi], &bf[nj][0]);
                    mma16816(acc[mi][2 * nj + 1], af[mi], &bf[nj][2]);
                }
            // pass 3: Ahi x Blo
#pragma unroll
            for (int nj = 0; nj < 4; nj++) {
                const int row = wn * 64 + nj * 16 + brow;
                const int cc  = ks * 2 + bcol;
                ldsm4(bf[nj], sBlo + (row << 7) + ((cc ^ (row & 7)) << 4));
            }
#pragma unroll
            for (int mi = 0; mi < 4; mi++)
#pragma unroll
                for (int nj = 0; nj < 4; nj++) {
                    mma16816(acc[mi][2 * nj],     af[mi], &bf[nj][0]);
                    mma16816(acc[mi][2 * nj + 1], af[mi], &bf[nj][2]);
                }
        }
    }

    // ------------------------- epilogue (compile-time EPI) -------------------
    const int gq = lane >> 2, tg = lane & 3;

    if (EPI == 2) {
        uint32_t* sm32 = reinterpret_cast<uint32_t*>(sal);
        __syncthreads();
#pragma unroll
        for (int mi = 0; mi < 4; mi++) {
#pragma unroll
            for (int half = 0; half < 2; half++) {
                const int gmL = wm * 64 + mi * 16 + gq + half * 8;   // 0..255
                const int col = (gmL >> 3) + 33 * (gmL & 7);
#pragma unroll
                for (int ni = 0; ni < 8; ni++) {
                    const int gnL = wn * 64 + ni * 8 + 2 * tg;       // 0..127
                    sm32[(gnL + 0) * TW + col] = pack_hilo(acc[mi][ni][half * 2 + 0]);
                    sm32[(gnL + 1) * TW + col] = pack_hilo(acc[mi][ni][half * 2 + 1]);
                }
            }
        }
        __syncthreads();
        const int sBase = mBase >> 3;
        const int bb = (tid >> 4) & 7;
        const int sq = tid & 15;
        const int nHalf = tid >> 7;
#pragma unroll 4
        for (int it = 0; it < 64; it++) {
            const int n = it * 2 + nHalf;
            const uint32_t u0 = sm32[n * TW + 2 * sq     + 33 * bb];
            const uint32_t u1 = sm32[n * TW + 2 * sq + 1 + 33 * bb];
            const uint32_t hi01 = (u0 & 0xFFFFu) | (u1 << 16);
            const uint32_t lo01 = (u0 >> 16) | (u1 & 0xFFFF0000u);
            __nv_bfloat16* orow = g.outH
                + ((size_t)bb * D_ + nBase + n) * (2 * S_) + sBase + 2 * sq;
            *reinterpret_cast<uint32_t*>(orow)      = hi01;
            *reinterpret_cast<uint32_t*>(orow + S_) = lo01;
        }
        return;
    }

#pragma unroll
    for (int mi = 0; mi < 4; mi++) {
#pragma unroll
        for (int half = 0; half < 2; half++) {
            const int gm = mBase + wm * 64 + mi * 16 + gq + half * 8;
#pragma unroll
            for (int ni = 0; ni < 8; ni++) {
                const int gn = nBase + wn * 64 + ni * 8 + 2 * tg;
                const float v0 = acc[mi][ni][half * 2 + 0];
                const float v1 = acc[mi][ni][half * 2 + 1];

                if (EPI == 0) {
                    float2 v;
                    v.x = v0; v.y = v1;
                    if (g.bias) { v.x += g.bias[gn + 0]; v.y += g.bias[gn + 1]; }
                    *reinterpret_cast<float2*>(
                        g.outF + (long)bz * g.bsO + (long)gm * g.ldo + gn) = v;
                } else if (EPI == 1) {
                    const __nv_bfloat16 h0 = __float2bfloat16(v0);
                    const __nv_bfloat16 h1 = __float2bfloat16(v1);
                    const __nv_bfloat16 l0 = __float2bfloat16(v0 - __bfloat162float(h0));
                    const __nv_bfloat16 l1 = __float2bfloat16(v1 - __bfloat162float(h1));
                    __nv_bfloat16* o = g.outH + (long)bz * g.bsO + (long)gm * g.ldo + gn;
                    *reinterpret_cast<__nv_bfloat162*>(o) = __nv_bfloat162(h0, h1);
                    *reinterpret_cast<__nv_bfloat162*>(o + g.loOff) = __nv_bfloat162(l0, l1);
                } else {  // EPI == 4 : scores
                    const float cb0 = g.cbias[(long)bz * S_ + gn + 0];
                    const float cb1 = g.cbias[(long)bz * S_ + gn + 1];
                    float2 v;
                    v.x = (gn + 0 > gm) ? neg_inf_f() : (v0 + cb0) * g.scale;
                    v.y = (gn + 1 > gm) ? neg_inf_f() : (v1 + cb1) * g.scale;
                    *reinterpret_cast<float2*>(
                        g.outF + (long)bz * g.bsO + (long)gm * g.ldo + gn) = v;
                }
            }
        }
    }
}

template<int EPI, bool CAUSALK, bool TRIL>
__global__ void __launch_bounds__(256, 1) gemm_one(GArgs g)
{
    gemm_body<EPI, CAUSALK, TRIL>(g, blockIdx.x, gridDim.y - 1 - blockIdx.y, blockIdx.z);
}

template<int E0, int E1>
__global__ void __launch_bounds__(256, 1) gemm_dual(GArgs g0, GArgs g1)
{
    if (blockIdx.z == 0)
        gemm_body<E0, false, false>(g0, blockIdx.x, blockIdx.y, 0);
    else
        gemm_body<E1, false, false>(g1, blockIdx.x, blockIdx.y, 0);
}

// ---------------------------------------------------------------------------
// Merged prep: grid (4096, 1, 5), 256 threads.
//   z in {0,1,2}: q/k/v fp32 -> split bf16 (MLP=4); z==1 also computes vb
//                 (vb[m] = key_m . w2; block covers exactly 4 rows)
//   z == 3     : Wo fp32 -> split bf16 (x < 1024 active)
//   z == 4     : Wk/Wq/Wv transpose+split (x < 3072 active)
// ---------------------------------------------------------------------------
__global__ void prep_all(const float* __restrict__ q, const float* __restrict__ k,
                         const float* __restrict__ v, const float* __restrict__ Wo,
                         const float* __restrict__ Wk, const float* __restrict__ Wq,
                         const float* __restrict__ Wv, const float* __restrict__ w2,
                         __nv_bfloat16* __restrict__ Qc, __nv_bfloat16* __restrict__ Kc,
                         __nv_bfloat16* __restrict__ Vc, __nv_bfloat16* __restrict__ Wos,
                         __nv_bfloat16* __restrict__ WkT, __nv_bfloat16* __restrict__ WqT,
                         __nv_bfloat16* __restrict__ WvT, float* __restrict__ vb)
{
    __shared__ float t[32][33];
    __shared__ float shv[4];
    const int tid = threadIdx.x;
    const int z = blockIdx.z;

    if (z < 3) {
        const float* in = (z == 0) ? q : (z == 1) ? k : v;
        __nv_bfloat16* out = (z == 0) ? Qc : (z == 1) ? Kc : Vc;
        const long base = (long)blockIdx.x * 1024 + tid;

        if (z == 1 && tid < 4) shv[tid] = 0.0f;
        if (z == 1) __syncthreads();

        float4 v4[4];
#pragma unroll
        for (int j = 0; j < 4; j++)
            v4[j] = reinterpret_cast<const float4*>(in)[base + j * 256];

#pragma unroll
        for (int j = 0; j < 4; j++) {
            const long idx = (base + j * 256) * 4;
            const long m = idx >> 10;
            const int  kk = (int)(idx & 1023);
            const __nv_bfloat16 h0 = __float2bfloat16(v4[j].x);
            const __nv_bfloat16 h1 = __float2bfloat16(v4[j].y);
            const __nv_bfloat16 h2 = __float2bfloat16(v4[j].z);
            const __nv_bfloat16 h3 = __float2bfloat16(v4[j].w);
            uint2 hp, lp;
            hp.x = pack_bf2(v4[j].x, v4[j].y);
            hp.y = pack_bf2(v4[j].z, v4[j].w);
            lp.x = pack_bf2(v4[j].x - __bfloat162float(h0), v4[j].y - __bfloat162float(h1));
            lp.y = pack_bf2(v4[j].z - __bfloat162float(h2), v4[j].w - __bfloat162float(h3));
            __nv_bfloat16* o = out + m * 2048 + kk;
            *reinterpret_cast<uint2*>(o)        = hp;
            *reinterpret_cast<uint2*>(o + 1024) = lp;

            if (z == 1) {
                // vb partial: whole warp's j-th float4s lie in ONE row
                const float4 w = *reinterpret_cast<const float4*>(w2 + kk);
                float s = v4[j].x * w.x + v4[j].y * w.y + v4[j].z * w.z + v4[j].w * w.w;
#pragma unroll
                for (int off = 16; off > 0; off >>= 1)
                    s += __shfl_xor_sync(0xffffffffu, s, off);
                if ((tid & 31) == 0) atomicAdd(&shv[(int)(m & 3)], s);
            }
        }

        if (z == 1) {
            __syncthreads();
            if (tid < 4) {
                const long m = (long)blockIdx.x * 4 + tid;
                const int b = (int)(m & (B_ - 1));
                const int jj = (int)(m >> 3);
                vb[(long)b * S_ + jj] = shv[tid];
            }
        }
    } else if (z == 3) {
        if (blockIdx.x >= 1024) return;
        const long i = (long)blockIdx.x * 256 + tid;
        const float4 vv = reinterpret_cast<const float4*>(Wo)[i];
        const long idx = i * 4;
        const long m = idx >> 10;
        const int  kk = (int)(idx & 1023);
        const __nv_bfloat16 h0 = __float2bfloat16(vv.x);
        const __nv_bfloat16 h1 = __float2bfloat16(vv.y);
        const __nv_bfloat16 h2 = __float2bfloat16(vv.z);
        const __nv_bfloat16 h3 = __float2bfloat16(vv.w);
        uint2 hp, lp;
        hp.x = pack_bf2(vv.x, vv.y);
        hp.y = pack_bf2(vv.z, vv.w);
        lp.x = pack_bf2(vv.x - __bfloat162float(h0), vv.y - __bfloat162float(h1));
        lp.y = pack_bf2(vv.z - __bfloat162float(h2), vv.w - __bfloat162float(h3));
        __nv_bfloat16* o = Wos + m * 2048 + kk;
        *reinterpret_cast<uint2*>(o)        = hp;
        *reinterpret_cast<uint2*>(o + 1024) = lp;
    } else {
        if (blockIdx.x >= 3072) return;
        const int which = blockIdx.x >> 10;
        const int rem = blockIdx.x & 1023;
        const float* W = (which == 0) ? Wk : (which == 1) ? Wq : Wv;
        __nv_bfloat16* out = (which == 0) ? WkT : (which == 1) ? WqT : WvT;
        const int a0 = (rem & 31) * 32, e0 = (rem >> 5) * 32;
        const int tx = tid & 31, ty = tid >> 5;
#pragma unroll
        for (int r = 0; r < 32; r += 8)
            t[r + ty][tx] = W[(long)(e0 + r + ty) * D_ + a0 + tx];
        __syncthreads();
#pragma unroll
        for (int r = 0; r < 32; r += 8) {
            const int a = a0 + r + ty, e = e0 + tx;
            const float vv = t[tx][r + ty];
            const __nv_bfloat16 h = __float2bfloat16(vv);
            __nv_bfloat16* o = out + (long)a * 2 * D_ + e;
            o[0]  = h;
            o[D_] = __float2bfloat16(vv - __bfloat162float(h));
        }
    }
}

// ---------------------------------------------------------------------------
// Merged bias prep: grid (128, 1, 2).
// ---------------------------------------------------------------------------
__global__ void bias_prep(const float* __restrict__ Wk, const float* __restrict__ bq,
                          const float* __restrict__ Wo, const float* __restrict__ bv,
                          const float* __restrict__ bo,
                          float* __restrict__ w2p, float* __restrict__ cb)
{
    if (blockIdx.z == 0) {
        if (blockIdx.x >= 64) return;
        const int a = (blockIdx.x & 3) * 256 + threadIdx.x;
        const int d0 = (blockIdx.x >> 2) * 64;
        float s = 0.0f;
#pragma unroll 4
        for (int d = d0; d < d0 + 64; d++)
            s += bq[d] * Wk[(long)d * D_ + a];
        w2p[(blockIdx.x >> 2) * D_ + a] = s;
    } else {
        const int o = blockIdx.x * 8 + (threadIdx.x >> 5);
        const int lane = threadIdx.x & 31;
        float s = 0.0f;
        for (int e = lane * 4; e < D_; e += 128) {
            const float4 w = *reinterpret_cast<const float4*>(Wo + (long)o * D_ + e);
            const float4 b = *reinterpret_cast<const float4*>(bv + e);
            s += w.x * b.x + w.y * b.y + w.z * b.z + w.w * b.w;
        }
#pragma unroll
        for (int off = 16; off > 0; off >>= 1) s += __shfl_xor_sync(0xffffffffu, s, off);
        if (lane == 0) cb[o] = bo[o] + s;
    }
}

__global__ void w2_combine(const float* __restrict__ w2p, float* __restrict__ w2)
{
    const int a = blockIdx.x * 256 + threadIdx.x;
    float s = 0.0f;
#pragma unroll
    for (int i = 0; i < 16; i++) s += w2p[i * D_ + a];
    w2[a] = s;
}

// ---------------------------------------------------------------------------
// Fused row softmax + split-bf16 emit; single global read via smem row cache.
// ---------------------------------------------------------------------------
__global__ void __launch_bounds__(256) softmax_split(const float* __restrict__ P,
                                                     __nv_bfloat16* __restrict__ Pb)
{
    __shared__ float sP[2048];
    __shared__ float sm[8];
    const int i = blockIdx.x, b = blockIdx.y;
    const float* p = P + ((size_t)b * S_ + i) * S_;
    __nv_bfloat16* o = Pb + ((size_t)b * S_ + i) * (2 * S_);
    const int jEnd = ((i >> 7) + 1) << 7;
    const int tid = threadIdx.x;

    // pass 1: load -> smem, rowmax
    float m = neg_inf_f();
    for (int j = tid * 4; j < jEnd; j += 1024) {
        const float4 v = *reinterpret_cast<const float4*>(p + j);
        *reinterpret_cast<float4*>(sP + j) = v;
        m = fmaxf(m, fmaxf(fmaxf(v.x, v.y), fmaxf(v.z, v.w)));
    }
#pragma unroll
    for (int off = 16; off > 0; off >>= 1) m = fmaxf(m, __shfl_xor_sync(0xffffffffu, m, off));
    if ((tid & 31) == 0) sm[tid >> 5] = m;
    __syncthreads();
    const float rowmax = fmaxf(fmaxf(fmaxf(sm[0], sm[1]), fmaxf(sm[2], sm[3])),
                               fmaxf(fmaxf(sm[4], sm[5]), fmaxf(sm[6], sm[7])));
    __syncthreads();

    // pass 2: exp in place, sum
    float s = 0.0f;
    for (int j = tid * 4; j < jEnd; j += 1024) {
        float4 v = *reinterpret_cast<float4*>(sP + j);
        v.x = __expf(v.x - rowmax);
        v.y = __expf(v.y - rowmax);
        v.z = __expf(v.z - rowmax);
        v.w = __expf(v.w - rowmax);
        *reinterpret_cast<float4*>(sP + j) = v;
        s += v.x + v.y + v.z + v.w;
    }
#pragma unroll
    for (int off = 16; off > 0; off >>= 1) s += __shfl_xor_sync(0xffffffffu, s, off);
    if ((tid & 31) == 0) sm[tid >> 5] = s;
    __syncthreads();
    const float inv = 1.0f / ((sm[0] + sm[1]) + (sm[2] + sm[3]) + (sm[4] + sm[5]) + (sm[6] + sm[7]));

    // pass 3: scale + split emit
    for (int j = tid * 4; j < jEnd; j += 1024) {
        const float4 v = *reinterpret_cast<const float4*>(sP + j);
        const float e0 = v.x * inv, e1 = v.y * inv, e2 = v.z * inv, e3 = v.w * inv;
        const __nv_bfloat16 h0 = __float2bfloat16(e0);
        const __nv_bfloat16 h1 = __float2bfloat16(e1);
        const __nv_bfloat16 h2 = __float2bfloat16(e2);
        const __nv_bfloat16 h3 = __float2bfloat16(e3);
        uint2 hp, lp;
        hp.x = pack_bf2(e0, e1); hp.y = pack_bf2(e2, e3);
        lp.x = pack_bf2(e0 - __bfloat162float(h0), e1 - __bfloat162float(h1));
        lp.y = pack_bf2(e2 - __bfloat162float(h2), e3 - __bfloat162float(h3));
        *reinterpret_cast<uint2*>(o + j)      = hp;
        *reinterpret_cast<uint2*>(o + S_ + j) = lp;
    }
}

// ---------------------------------------------------------------------------
extern "C" void kernel_launch(void* const* d_in, const int* in_sizes, int n_in,
                              void* d_out, int out_size)
{
    const float* query = (const float*)d_in[0];
    const float* key   = (const float*)d_in[1];
    const float* value = (const float*)d_in[2];
    const float* Wq = (const float*)d_in[4];
    const float* bq = (const float*)d_in[5];
    const float* Wk = (const float*)d_in[6];
    // d_in[7] = bk : softmax-invariant, dropped exactly
    const float* Wv = (const float*)d_in[8];
    const float* bv = (const float*)d_in[9];
    const float* Wo = (const float*)d_in[10];
    const float* bo = (const float*)d_in[11];
    float* out = (float*)d_out;

    __nv_bfloat16 *Qc, *Kc, *Vc, *WkT, *WqT, *WvT, *Wos, *H, *WvoB, *T, *Zt, *Pbf;
    float *P, *w2p, *w2, *cb, *vb;
    cudaGetSymbolAddress((void**)&Qc,  g_Qc);
    cudaGetSymbolAddress((void**)&Kc,  g_Kc);
    cudaGetSymbolAddress((void**)&Vc,  g_Vc);
    cudaGetSymbolAddress((void**)&WkT, g_WkT);
    cudaGetSymbolAddress((void**)&WqT, g_WqT);
    cudaGetSymbolAddress((void**)&WvT, g_WvT);
    cudaGetSymbolAddress((void**)&Wos, g_Wos);
    cudaGetSymbolAddress((void**)&H,   g_H);
    cudaGetSymbolAddress((void**)&WvoB,g_WvoB);
    cudaGetSymbolAddress((void**)&T,   g_T);
    cudaGetSymbolAddress((void**)&Zt,  g_Zt);
    cudaGetSymbolAddress((void**)&P,   g_P);
    cudaGetSymbolAddress((void**)&Pbf, g_Pbf);
    cudaGetSymbolAddress((void**)&w2p, g_w2p);
    cudaGetSymbolAddress((void**)&w2,  g_w2);
    cudaGetSymbolAddress((void**)&cb,  g_cb);
    cudaGetSymbolAddress((void**)&vb,  g_vb);

    cudaFuncSetAttribute(gemm_dual<1, 1>,
                         cudaFuncAttributeMaxDynamicSharedMemorySize, GEMM_SMEM);
    cudaFuncSetAttribute(gemm_dual<1, 2>,
                         cudaFuncAttributeMaxDynamicSharedMemorySize, GEMM_SMEM);
    cudaFuncSetAttribute(gemm_one<4, false, true>,
                         cudaFuncAttributeMaxDynamicSharedMemorySize, GEMM_SMEM);
    cudaFuncSetAttribute(gemm_one<0, true, false>,
                         cudaFuncAttributeMaxDynamicSharedMemorySize, GEMM_SMEM);

    const long n4i = (long)M_ * D_ / 4;

    // ---- bias prep first (w2 must be ready before prep_all computes vb) ----
    bias_prep<<<dim3(128, 1, 2), 256>>>(Wk, bq, Wo, bv, bo, w2p, cb);
    w2_combine<<<D_ / 256, 256>>>(w2p, w2);

    // ---- merged prep: q/k/v conversions (+vb) + Wo conversion + transposes ----
    prep_all<<<dim3((unsigned)(n4i / 1024), 1, 5), 256>>>(
        query, key, value, Wo, Wk, Wq, Wv, w2, Qc, Kc, Vc, Wos, WkT, WqT, WvT, vb);

    // ---- H = Wk^T Wq  and  WvoB = (Wo Wv)[o][a], one dual launch ----
    GArgs hA{};
    hA.A = WkT; hA.lda = 2 * D_; hA.bsA = 0; hA.oAlo = D_;
    hA.B = WqT; hA.ldb = 2 * D_; hA.bsB = 0; hA.oBlo = D_;
    hA.Kpart = D_; hA.scale = 1.0f; hA.bias = nullptr; hA.cbias = nullptr;
    hA.outH = H; hA.ldo = 2 * D_; hA.bsO = 0; hA.loOff = D_;
    GArgs hB = hA;
    hB.A = Wos; hB.B = WvT; hB.outH = WvoB;
    gemm_dual<1, 1><<<dim3(D_ / 128, D_ / 256, 2), 256, GEMM_SMEM>>>(hA, hB);

    // ---- T = query * G (split out)  and  Z -> Zt directly (EPI2), dual ----
    GArgs tA{};
    tA.A = Qc; tA.lda = 2 * D_; tA.bsA = 0; tA.oAlo = D_;
    tA.B = H;  tA.ldb = 2 * D_; tA.bsB = 0; tA.oBlo = D_;
    tA.Kpart = D_; tA.scale = 1.0f; tA.bias = nullptr; tA.cbias = nullptr;
    tA.outH = T; tA.ldo = 2 * D_; tA.bsO = 0; tA.loOff = D_;
    GArgs tB{};
    tB.A = Vc; tB.lda = 2 * D_; tB.bsA = 0; tB.oAlo = D_;
    tB.B = WvoB; tB.ldb = 2 * D_; tB.bsB = 0; tB.oBlo = D_;
    tB.Kpart = D_; tB.scale = 1.0f; tB.bias = nullptr; tB.cbias = nullptr;
    tB.outH = Zt;   // EPI2: transposed split write
    gemm_dual<1, 2><<<dim3(D_ / 128, M_ / 256, 2), 256, GEMM_SMEM>>>(tA, tB);

    // ---- Scores: P = SCALE * (T . key^T + vb), tril tiles, causal mask ----
    GArgs sc{};
    sc.A = T;  sc.lda = (long)B_ * 2 * D_; sc.bsA = 2 * D_; sc.oAlo = D_;
    sc.B = Kc; sc.ldb = (long)B_ * 2 * D_; sc.bsB = 2 * D_; sc.oBlo = D_;
    sc.Kpart = D_; sc.scale = SCALE_; sc.bias = nullptr; sc.cbias = vb;
    sc.outF = P; sc.ldo = S_; sc.bsO = (long)S_ * S_;
    gemm_one<4, false, true><<<dim3(S_ / 128, S_ / 256, B_), 256, GEMM_SMEM>>>(sc);

    // ---- fused softmax + P split (single global read) ----
    softmax_split<<<dim3(S_, B_), 256>>>(P, Pbf);

    // ---- out = P @ Z + cb (causal K bound), fp32 straight to d_out ----
    GArgs pv{};
    pv.A = Pbf; pv.lda = 2 * S_; pv.bsA = (long)S_ * 2 * S_; pv.oAlo = S_;
    pv.B = Zt;  pv.ldb = 2 * S_; pv.bsB = (long)D_ * 2 * S_; pv.oBlo = S_;
    pv.Kpart = S_; pv.scale = 1.0f; pv.bias = cb; pv.cbias = nullptr;
    pv.outF = out; pv.ldo = (long)B_ * D_; pv.bsO = D_;
    gemm_one<0, true, false><<<dim3(D_ / 128, S_ / 256, B_), 256, GEMM_SMEM>>>(pv);
}